// round 1
// baseline (speedup 1.0000x reference)
#include <cuda_runtime.h>
#include <math.h>

// ---------------------------------------------------------------------------
// CrossModalFusionModel: two projections + two sliding-window cross-attentions.
// Algebraic restructuring: K/V projections done ONCE on the context (window-
// independent); zero-pad window slots collapse to a single (kb, vb) pad slot
// whose softmax weight is scaled by n_zero. Masked slots underflow to 0.
//
// Shapes: B=1, N=512, D=1024, HEADS=8, dh=128, WINDOW=64, L=66.
// ---------------------------------------------------------------------------

#define NTOK   512
#define DM     1024
#define HEADS  8
#define DH     128
#define WIN    64
#define HALF   32      // WIN/2

// Scratch: txt, img, q1,k1,v1, q2,k2,v2, o1,o2  (10 x 512x1024 fp32)
__device__ float g_scratch[10 * NTOK * DM];

// ---------------------------------------------------------------------------
// Batched SGEMM:  C[M,N] = A[M,K] @ W[N,K]^T + bias[N] (+ resid[M,N])
// 64x64 tile, BK=16, 256 threads, 4x4 per thread.
// ---------------------------------------------------------------------------
struct GDesc {
    const float* A;
    const float* W;
    const float* bias;
    const float* resid;   // nullptr if none
    float*       C;
    int          K;
};
struct GBatch { GDesc d[6]; };

#define BM 64
#define BN 64
#define BK 16

__global__ __launch_bounds__(256)
void gemm_kernel(GBatch batch, int M, int N) {
    const GDesc g = batch.d[blockIdx.z];

    __shared__ float As[BK][BM + 4];
    __shared__ float Bs[BK][BN + 4];

    const int tid = threadIdx.x;
    const int tx  = tid & 15;       // 0..15  (N direction)
    const int ty  = tid >> 4;       // 0..15  (M direction)
    const int m0  = blockIdx.y * BM;
    const int n0  = blockIdx.x * BN;

    const int lrow = tid >> 2;          // 0..63
    const int lcg  = (tid & 3) << 2;    // 0,4,8,12

    const float* Aptr = g.A + (size_t)(m0 + lrow) * g.K + lcg;
    const float* Wptr = g.W + (size_t)(n0 + lrow) * g.K + lcg;

    float acc[4][4];
#pragma unroll
    for (int i = 0; i < 4; i++)
#pragma unroll
        for (int j = 0; j < 4; j++) acc[i][j] = 0.f;

    for (int k0 = 0; k0 < g.K; k0 += BK) {
        float4 a = *(const float4*)(Aptr + k0);
        float4 b = *(const float4*)(Wptr + k0);
        As[lcg + 0][lrow] = a.x;
        As[lcg + 1][lrow] = a.y;
        As[lcg + 2][lrow] = a.z;
        As[lcg + 3][lrow] = a.w;
        Bs[lcg + 0][lrow] = b.x;
        Bs[lcg + 1][lrow] = b.y;
        Bs[lcg + 2][lrow] = b.z;
        Bs[lcg + 3][lrow] = b.w;
        __syncthreads();

#pragma unroll
        for (int kk = 0; kk < BK; kk++) {
            float4 av = *(const float4*)&As[kk][ty << 2];
            float4 bv = *(const float4*)&Bs[kk][tx << 2];
            acc[0][0] += av.x * bv.x; acc[0][1] += av.x * bv.y;
            acc[0][2] += av.x * bv.z; acc[0][3] += av.x * bv.w;
            acc[1][0] += av.y * bv.x; acc[1][1] += av.y * bv.y;
            acc[1][2] += av.y * bv.z; acc[1][3] += av.y * bv.w;
            acc[2][0] += av.z * bv.x; acc[2][1] += av.z * bv.y;
            acc[2][2] += av.z * bv.z; acc[2][3] += av.z * bv.w;
            acc[3][0] += av.w * bv.x; acc[3][1] += av.w * bv.y;
            acc[3][2] += av.w * bv.z; acc[3][3] += av.w * bv.w;
        }
        __syncthreads();
    }

    const int col = n0 + (tx << 2);
    const float4 bv = *(const float4*)(g.bias + col);
#pragma unroll
    for (int i = 0; i < 4; i++) {
        const int row = m0 + (ty << 2) + i;
        float4 out;
        out.x = acc[i][0] + bv.x;
        out.y = acc[i][1] + bv.y;
        out.z = acc[i][2] + bv.z;
        out.w = acc[i][3] + bv.w;
        if (g.resid) {
            float4 r = *(const float4*)(g.resid + (size_t)row * N + col);
            out.x += r.x; out.y += r.y; out.z += r.z; out.w += r.w;
        }
        *(float4*)(g.C + (size_t)row * N + col) = out;
    }
}

// ---------------------------------------------------------------------------
// Sliding-window attention. grid = (512, 2); block = 256 (warp per head).
// Window for query n: real keys [max(0,n-32), min(511,n+33)], plus
// n_zero = max(0, 64 - cnt) pad slots with k = kb, v = vb.
// ---------------------------------------------------------------------------
__global__ __launch_bounds__(256)
void attn_kernel(const float* __restrict__ Q1, const float* __restrict__ K1,
                 const float* __restrict__ V1, const float* __restrict__ kb1,
                 const float* __restrict__ vb1, float* __restrict__ O1,
                 const float* __restrict__ Q2, const float* __restrict__ K2,
                 const float* __restrict__ V2, const float* __restrict__ kb2,
                 const float* __restrict__ vb2, float* __restrict__ O2) {
    const int n = blockIdx.x;
    const float *Q, *K, *V, *kb, *vb;
    float* O;
    if (blockIdx.y == 0) { Q = Q1; K = K1; V = V1; kb = kb1; vb = vb1; O = O1; }
    else                 { Q = Q2; K = K2; V = V2; kb = kb2; vb = vb2; O = O2; }

    const int h    = threadIdx.x >> 5;
    const int lane = threadIdx.x & 31;

    __shared__ float sc[HEADS][WIN + 2];

    const int lo  = max(0, n - HALF);
    const int hi  = min(NTOK - 1, n + HALF + 1);
    const int cnt = hi - lo + 1;
    const int nz  = max(0, WIN - cnt);

    const float scale = 0.088388347648318447f;   // 1/sqrt(128)
    const int   off   = h * DH + (lane << 2);

    const float4 q = *(const float4*)(Q + (size_t)n * DM + off);

    // pad-slot score (k = kb)
    const float4 kbv = *(const float4*)(kb + off);
    float sp = q.x * kbv.x + q.y * kbv.y + q.z * kbv.z + q.w * kbv.w;
#pragma unroll
    for (int o = 16; o; o >>= 1) sp += __shfl_xor_sync(0xffffffffu, sp, o);
    sp *= scale;

    // real key scores
    for (int j = 0; j < cnt; j++) {
        const float4 kv = *(const float4*)(K + (size_t)(lo + j) * DM + off);
        float s = q.x * kv.x + q.y * kv.y + q.z * kv.z + q.w * kv.w;
#pragma unroll
        for (int o = 16; o; o >>= 1) s += __shfl_xor_sync(0xffffffffu, s, o);
        if (lane == 0) sc[h][j] = s * scale;
    }
    __syncwarp();

    // max
    float m = (nz > 0) ? sp : -INFINITY;
    for (int j = lane; j < cnt; j += 32) m = fmaxf(m, sc[h][j]);
#pragma unroll
    for (int o = 16; o; o >>= 1) m = fmaxf(m, __shfl_xor_sync(0xffffffffu, m, o));

    // exp + denom (overwrite scores with weights)
    float dsum = 0.f;
    for (int j = lane; j < cnt; j += 32) {
        float e = expf(sc[h][j] - m);
        sc[h][j] = e;
        dsum += e;
    }
    __syncwarp();
#pragma unroll
    for (int o = 16; o; o >>= 1) dsum += __shfl_xor_sync(0xffffffffu, dsum, o);
    const float ep = (nz > 0) ? expf(sp - m) : 0.f;
    dsum += (float)nz * ep;

    // weighted value sum
    float4 acc = make_float4(0.f, 0.f, 0.f, 0.f);
    for (int j = 0; j < cnt; j++) {
        const float w = sc[h][j];
        const float4 vv = *(const float4*)(V + (size_t)(lo + j) * DM + off);
        acc.x += w * vv.x; acc.y += w * vv.y;
        acc.z += w * vv.z; acc.w += w * vv.w;
    }
    const float wpad = (float)nz * ep;
    const float4 vbv = *(const float4*)(vb + off);
    acc.x += wpad * vbv.x; acc.y += wpad * vbv.y;
    acc.z += wpad * vbv.z; acc.w += wpad * vbv.w;

    const float inv = 1.f / dsum;
    float4 out = make_float4(acc.x * inv, acc.y * inv, acc.z * inv, acc.w * inv);
    *(float4*)(O + (size_t)n * DM + off) = out;
}

// ---------------------------------------------------------------------------
// Launch
// ---------------------------------------------------------------------------
extern "C" void kernel_launch(void* const* d_in, const int* in_sizes, int n_in,
                              void* d_out, int out_size) {
    const float* images    = (const float*)d_in[0];
    const float* capitions = (const float*)d_in[1];
    // d_in[2] = text_input_ids (unused by reference)
    const float* tp_w  = (const float*)d_in[3];
    const float* tp_b  = (const float*)d_in[4];
    const float* ip_w  = (const float*)d_in[5];
    const float* ip_b  = (const float*)d_in[6];
    const float* ia_qw = (const float*)d_in[7];
    const float* ia_qb = (const float*)d_in[8];
    const float* ia_kw = (const float*)d_in[9];
    const float* ia_kb = (const float*)d_in[10];
    const float* ia_vw = (const float*)d_in[11];
    const float* ia_vb = (const float*)d_in[12];
    const float* ia_ow = (const float*)d_in[13];
    const float* ia_ob = (const float*)d_in[14];
    const float* ta_qw = (const float*)d_in[15];
    const float* ta_qb = (const float*)d_in[16];
    const float* ta_kw = (const float*)d_in[17];
    const float* ta_kb = (const float*)d_in[18];
    const float* ta_vw = (const float*)d_in[19];
    const float* ta_vb = (const float*)d_in[20];
    const float* ta_ow = (const float*)d_in[21];
    const float* ta_ob = (const float*)d_in[22];

    void* sp = nullptr;
    cudaGetSymbolAddress(&sp, g_scratch);
    float* base  = (float*)sp;
    const size_t SZ = (size_t)NTOK * DM;
    float* g_txt = base + 0 * SZ;
    float* g_img = base + 1 * SZ;
    float* g_q1  = base + 2 * SZ;
    float* g_k1  = base + 3 * SZ;
    float* g_v1  = base + 4 * SZ;
    float* g_q2  = base + 5 * SZ;
    float* g_k2  = base + 6 * SZ;
    float* g_v2  = base + 7 * SZ;
    float* g_o1  = base + 8 * SZ;
    float* g_o2  = base + 9 * SZ;

    float* out_img = (float*)d_out;
    float* out_txt = out_img + SZ;

    // Stage 1: modality projections
    GBatch b1 = {};
    b1.d[0] = { capitions, tp_w, tp_b, nullptr, g_txt, 768 };
    b1.d[1] = { images,    ip_w, ip_b, nullptr, g_img, 1024 };
    gemm_kernel<<<dim3(DM / BN, NTOK / BM, 2), 256>>>(b1, NTOK, DM);

    // Stage 2: Q/K/V for both attentions (6 GEMMs)
    GBatch b2 = {};
    b2.d[0] = { g_img, ia_qw, ia_qb, nullptr, g_q1, 1024 };
    b2.d[1] = { g_txt, ia_kw, ia_kb, nullptr, g_k1, 1024 };
    b2.d[2] = { g_txt, ia_vw, ia_vb, nullptr, g_v1, 1024 };
    b2.d[3] = { g_txt, ta_qw, ta_qb, nullptr, g_q2, 1024 };
    b2.d[4] = { g_img, ta_kw, ta_kb, nullptr, g_k2, 1024 };
    b2.d[5] = { g_img, ta_vw, ta_vb, nullptr, g_v2, 1024 };
    gemm_kernel<<<dim3(DM / BN, NTOK / BM, 6), 256>>>(b2, NTOK, DM);

    // Stage 3: windowed attention (both directions)
    attn_kernel<<<dim3(NTOK, 2), 256>>>(g_q1, g_k1, g_v1, ia_kb, ia_vb, g_o1,
                                        g_q2, g_k2, g_v2, ta_kb, ta_vb, g_o2);

    // Stage 4: output projections + residual, written straight to d_out
    GBatch b4 = {};
    b4.d[0] = { g_o1, ia_ow, ia_ob, g_img, out_img, 1024 };
    b4.d[1] = { g_o2, ta_ow, ta_ob, g_txt, out_txt, 1024 };
    gemm_kernel<<<dim3(DM / BN, NTOK / BM, 2), 256>>>(b4, NTOK, DM);
}

// round 3
// speedup vs baseline: 1.1707x; 1.1707x over previous
#include <cuda_runtime.h>
#include <cuda_bf16.h>
#include <math.h>
#include <stdint.h>

// ===========================================================================
// CrossModalFusionModel via mma.sync (HMMA) on sm_103 base target.
// All GEMMs: bf16 hi/lo split (3 passes: AhiWhi + AhiWlo + AloWhi, fp32 acc).
// Attention: smem-tiled sliding window (fp32 SIMT, tiny).
// ===========================================================================

#define NTOK  512
#define DM    1024
#define HEADS 8
#define DH    128
#define WIN   64
#define HALF  32

// ---------------------------------------------------------------------------
// Low-level helpers (base-target ISA only: cp.async, ldmatrix, mma.sync)
// ---------------------------------------------------------------------------
__device__ __forceinline__ uint32_t s2u(const void* p) {
    uint32_t a;
    asm("{ .reg .u64 t; cvta.to.shared.u64 t, %1; cvt.u32.u64 %0, t; }" : "=r"(a) : "l"(p));
    return a;
}
__device__ __forceinline__ void cp16(uint32_t smem, const void* g) {
    asm volatile("cp.async.cg.shared.global [%0], [%1], 16;" :: "r"(smem), "l"(g));
}
#define CP_COMMIT() asm volatile("cp.async.commit_group;" ::: "memory")
#define CP_WAIT0()  asm volatile("cp.async.wait_group 0;" ::: "memory")
#define CP_WAIT1()  asm volatile("cp.async.wait_group 1;" ::: "memory")

__device__ __forceinline__ void ldx4(uint32_t r[4], uint32_t addr) {
    asm volatile("ldmatrix.sync.aligned.m8n8.x4.shared.b16 {%0,%1,%2,%3}, [%4];"
        : "=r"(r[0]), "=r"(r[1]), "=r"(r[2]), "=r"(r[3]) : "r"(addr));
}
__device__ __forceinline__ void mma16816(float d[4], const uint32_t a[4],
                                         uint32_t b0, uint32_t b1) {
    asm volatile(
        "mma.sync.aligned.m16n8k16.row.col.f32.bf16.bf16.f32 "
        "{%0,%1,%2,%3}, {%4,%5,%6,%7}, {%8,%9}, {%0,%1,%2,%3};"
        : "+f"(d[0]), "+f"(d[1]), "+f"(d[2]), "+f"(d[3])
        : "r"(a[0]), "r"(a[1]), "r"(a[2]), "r"(a[3]), "r"(b0), "r"(b1));
}

// ---------------------------------------------------------------------------
// Scratch (static __device__ — no allocation)
// ---------------------------------------------------------------------------
#define SZ (NTOK * DM)                 // 524288
__device__ float          g_f[8 * SZ]; // txt,img,q1,k1,v1,q2,k2,v2 (fp32)
__device__ __nv_bfloat16  g_bf[26476544];

// ---------------------------------------------------------------------------
// Conversion: fp32 -> (hi, lo) bf16, batched segments
// ---------------------------------------------------------------------------
struct CSeg { const float* src; __nv_bfloat16 *hi, *lo; int n4; };
struct CBatch { CSeg s[12]; };

__global__ __launch_bounds__(256)
void convert_kernel(CBatch cb) {
    CSeg s = cb.s[blockIdx.y];
    int i = blockIdx.x * 256 + threadIdx.x;
    if (i >= s.n4) return;
    float4 x = ((const float4*)s.src)[i];
    __nv_bfloat16 h0 = __float2bfloat16(x.x);
    __nv_bfloat16 h1 = __float2bfloat16(x.y);
    __nv_bfloat16 h2 = __float2bfloat16(x.z);
    __nv_bfloat16 h3 = __float2bfloat16(x.w);
    __nv_bfloat16 l0 = __float2bfloat16(x.x - __bfloat162float(h0));
    __nv_bfloat16 l1 = __float2bfloat16(x.y - __bfloat162float(h1));
    __nv_bfloat16 l2 = __float2bfloat16(x.z - __bfloat162float(h2));
    __nv_bfloat16 l3 = __float2bfloat16(x.w - __bfloat162float(h3));
    __nv_bfloat162* ph = (__nv_bfloat162*)(s.hi) + 2 * i;
    __nv_bfloat162* pl = (__nv_bfloat162*)(s.lo) + 2 * i;
    ph[0] = __halves2bfloat162(h0, h1); ph[1] = __halves2bfloat162(h2, h3);
    pl[0] = __halves2bfloat162(l0, l1); pl[1] = __halves2bfloat162(l2, l3);
}

// ---------------------------------------------------------------------------
// mma.sync GEMM: C[M,N] = A[M,K] @ W[N,K]^T (+bias)(+resid), split-bf16.
// CTA tile 128x128, 8 warps (warp tile 32x64), K-chunks of 64,
// cp.async double buffer, XOR-swizzled smem, fused 3-pass split.
// ---------------------------------------------------------------------------
struct GD {
    const __nv_bfloat16 *Ahi, *Alo, *Whi, *Wlo;
    const float *bias, *resid;
    float* C;
    __nv_bfloat16 *Chi, *Clo;   // optional split output
    int K;
};
struct GB { GD d[6]; };

#define TILE_B    16384                  // 128 rows x 128 bytes
#define BUF_B     (4 * TILE_B)           // Ahi,Alo,Whi,Wlo
#define GEMM_SMEM (2 * BUF_B)            // 131072

// smem layout: tile row r holds 64 bf16 (128B); 16B chunk c swizzled by
// (c*16) ^ ((r&7)<<4) -> ldmatrix conflict-free.
__device__ __forceinline__ void load_tile(uint32_t sdst, const __nv_bfloat16* src,
                                          int row0, int k0, int K, int tid) {
    const char* g = (const char*)(src + (size_t)row0 * K + k0);
    const size_t rstride = (size_t)K * 2;
#pragma unroll
    for (int it = 0; it < 4; it++) {
        int idx = tid + it * 256;            // 0..1023
        int r = idx >> 3, f4 = idx & 7;
        cp16(sdst + (uint32_t)(r * 128 + ((f4 * 16) ^ ((r & 7) << 4))),
             g + (size_t)r * rstride + f4 * 16);
    }
}
__device__ __forceinline__ void load4(uint32_t bo, const GD& g,
                                      int m0, int n0, int k0, int tid) {
    load_tile(bo,              g.Ahi, m0, k0, g.K, tid);
    load_tile(bo + TILE_B,     g.Alo, m0, k0, g.K, tid);
    load_tile(bo + 2 * TILE_B, g.Whi, n0, k0, g.K, tid);
    load_tile(bo + 3 * TILE_B, g.Wlo, n0, k0, g.K, tid);
}

__global__ __launch_bounds__(256, 1)
void gemm_mma(GB batch, int N) {
    extern __shared__ char smem[];
    const GD g = batch.d[blockIdx.z];
    const uint32_t sb = s2u(smem);
    const int tid = threadIdx.x, wid = tid >> 5, lane = tid & 31;
    const int m0 = blockIdx.y * 128, n0 = blockIdx.x * 128;
    const int wm = (wid & 3) * 32;        // warp M offset in tile
    const int wn = (wid >> 2) * 64;       // warp N offset in tile

    float acc[2][8][4];
#pragma unroll
    for (int a = 0; a < 2; a++)
#pragma unroll
        for (int b = 0; b < 8; b++)
#pragma unroll
            for (int c = 0; c < 4; c++) acc[a][b][c] = 0.f;

    const int nch = g.K >> 6;

    // lane-constant ldmatrix addressing
    const int      lrow = lane & 15;
    const uint32_t cgb  = (uint32_t)((lane >> 4) * 16);
    const uint32_t xm   = (uint32_t)((lrow & 7) << 4);

    load4(sb, g, m0, n0, 0, tid);
    CP_COMMIT();

    for (int i = 0; i < nch; i++) {
        if (i + 1 < nch) {
            load4(sb + (uint32_t)(((i + 1) & 1) * BUF_B), g, m0, n0, (i + 1) << 6, tid);
            CP_COMMIT();
            CP_WAIT1();
        } else {
            CP_WAIT0();
        }
        __syncthreads();

        const uint32_t bo = sb + (uint32_t)((i & 1) * BUF_B);
        const uint32_t aHi = bo + (uint32_t)((wm + lrow) * 128);
        const uint32_t aLo = aHi + TILE_B;
        const uint32_t bHi = bo + 2 * TILE_B + (uint32_t)((wn + lrow) * 128);
        const uint32_t bLo = bHi + TILE_B;

#pragma unroll
        for (int ks = 0; ks < 4; ks++) {
            const uint32_t co = ((uint32_t)(ks * 32) + cgb) ^ xm;
            uint32_t ah[2][4], al[2][4], bh[4][4], bl[4][4];
#pragma unroll
            for (int mf = 0; mf < 2; mf++) {
                ldx4(ah[mf], aHi + (uint32_t)(mf * 16 * 128) + co);
                ldx4(al[mf], aLo + (uint32_t)(mf * 16 * 128) + co);
            }
#pragma unroll
            for (int p = 0; p < 4; p++) {
                ldx4(bh[p], bHi + (uint32_t)(p * 16 * 128) + co);
                ldx4(bl[p], bLo + (uint32_t)(p * 16 * 128) + co);
            }
#pragma unroll
            for (int mf = 0; mf < 2; mf++)
#pragma unroll
                for (int nf = 0; nf < 8; nf++) {
                    const int p = nf >> 1, o = nf & 1;
                    mma16816(acc[mf][nf], ah[mf], bh[p][o], bh[p][o + 2]);
                    mma16816(acc[mf][nf], ah[mf], bl[p][o], bl[p][o + 2]);
                    mma16816(acc[mf][nf], al[mf], bh[p][o], bh[p][o + 2]);
                }
        }
        __syncthreads();
    }

    // Epilogue: d0,d1 = (row, col..col+1); d2,d3 = (row+8, col..col+1)
    const int qr = lane >> 2, qc = (lane & 3) * 2;
#pragma unroll
    for (int mf = 0; mf < 2; mf++) {
        const int r0 = m0 + wm + mf * 16 + qr;
#pragma unroll
        for (int nf = 0; nf < 8; nf++) {
            const int c = n0 + wn + nf * 8 + qc;
            const float2 bv = *(const float2*)(g.bias + c);
            float o00 = acc[mf][nf][0] + bv.x, o01 = acc[mf][nf][1] + bv.y;
            float o10 = acc[mf][nf][2] + bv.x, o11 = acc[mf][nf][3] + bv.y;
            const size_t off0 = (size_t)r0 * N + c;
            const size_t off1 = off0 + (size_t)8 * N;
            if (g.resid) {
                float2 ra = *(const float2*)(g.resid + off0);
                float2 rb = *(const float2*)(g.resid + off1);
                o00 += ra.x; o01 += ra.y; o10 += rb.x; o11 += rb.y;
            }
            *(float2*)(g.C + off0) = make_float2(o00, o01);
            *(float2*)(g.C + off1) = make_float2(o10, o11);
            if (g.Chi) {
                __nv_bfloat16 h00 = __float2bfloat16(o00), h01 = __float2bfloat16(o01);
                __nv_bfloat16 h10 = __float2bfloat16(o10), h11 = __float2bfloat16(o11);
                *(__nv_bfloat162*)(g.Chi + off0) = __halves2bfloat162(h00, h01);
                *(__nv_bfloat162*)(g.Chi + off1) = __halves2bfloat162(h10, h11);
                *(__nv_bfloat162*)(g.Clo + off0) = __halves2bfloat162(
                    __float2bfloat16(o00 - __bfloat162float(h00)),
                    __float2bfloat16(o01 - __bfloat162float(h01)));
                *(__nv_bfloat162*)(g.Clo + off1) = __halves2bfloat162(
                    __float2bfloat16(o10 - __bfloat162float(h10)),
                    __float2bfloat16(o11 - __bfloat162float(h11)));
            }
        }
    }
}

// ---------------------------------------------------------------------------
// Sliding-window attention, smem-tiled: 16 queries/block share 81-row K/V window.
// grid (32, 2), 256 threads. Output written as split bf16 (feeds stage-4 GEMM).
// ---------------------------------------------------------------------------
#define AQ 16
#define WROWS 81
#define ATTN_SMEM ((2 * WROWS * 128 + 8 * 68) * 4)   // 85120 B

__global__ __launch_bounds__(256)
void attn_kernel(const float* __restrict__ Q1, const float* __restrict__ K1,
                 const float* __restrict__ V1, const float* __restrict__ kb1,
                 const float* __restrict__ vb1,
                 __nv_bfloat16* __restrict__ O1h, __nv_bfloat16* __restrict__ O1l,
                 const float* __restrict__ Q2, const float* __restrict__ K2,
                 const float* __restrict__ V2, const float* __restrict__ kb2,
                 const float* __restrict__ vb2,
                 __nv_bfloat16* __restrict__ O2h, __nv_bfloat16* __restrict__ O2l) {
    extern __shared__ float sm[];
    float* Ks = sm;
    float* Vs = sm + WROWS * 128;
    float* sw = sm + 2 * WROWS * 128;   // [8][68]

    const float *Q, *K, *V, *kb, *vb;
    __nv_bfloat16 *Oh, *Ol;
    if (blockIdx.y == 0) { Q=Q1; K=K1; V=V1; kb=kb1; vb=vb1; Oh=O1h; Ol=O1l; }
    else                 { Q=Q2; K=K2; V=V2; kb=kb2; vb=vb2; Oh=O2h; Ol=O2l; }

    const int tid = threadIdx.x, wid = tid >> 5, lane = tid & 31;
    const int q0 = blockIdx.x * AQ;
    const int base = q0 - HALF;                       // global row of smem j=0
    const int jmin = max(0, -base);
    const int jmax = min(NTOK - 1, q0 + AQ - 1 + HALF + 1) - base;
    const float scale = 0.088388347648318447f;        // 1/sqrt(128)

    for (int h = 0; h < HEADS; h++) {
        if (h) __syncthreads();
        for (int idx = tid; idx < WROWS * 32; idx += 256) {
            int j = idx >> 5, c4 = (idx & 31) << 2;
            if (j >= jmin && j <= jmax) {
                size_t go = (size_t)(base + j) * DM + h * DH + c4;
                *(float4*)&Ks[j * 128 + c4] = *(const float4*)(K + go);
                *(float4*)&Vs[j * 128 + c4] = *(const float4*)(V + go);
            }
        }
        __syncthreads();

        const float4 kb4 = *(const float4*)(kb + h * DH + (lane << 2));
        const float4 vb4 = *(const float4*)(vb + h * DH + (lane << 2));
        float* swp = sw + wid * 68;

#pragma unroll
        for (int qq = 0; qq < 2; qq++) {
            const int n  = q0 + wid * 2 + qq;
            const int lo = max(0, n - HALF);
            const int hi = min(NTOK - 1, n + HALF + 1);
            const int cnt = hi - lo + 1;
            const int nz  = max(0, WIN - cnt);
            const int jb  = lo - base;

            const float4 q4 = *(const float4*)(Q + (size_t)n * DM + h * DH + (lane << 2));

            float sp = q4.x * kb4.x + q4.y * kb4.y + q4.z * kb4.z + q4.w * kb4.w;
#pragma unroll
            for (int o = 16; o; o >>= 1) sp += __shfl_xor_sync(0xffffffffu, sp, o);
            sp *= scale;

            for (int j = 0; j < cnt; j++) {
                const float4 k4 = *(const float4*)&Ks[(jb + j) * 128 + (lane << 2)];
                float s = q4.x * k4.x + q4.y * k4.y + q4.z * k4.z + q4.w * k4.w;
#pragma unroll
                for (int o = 16; o; o >>= 1) s += __shfl_xor_sync(0xffffffffu, s, o);
                if (lane == 0) swp[j] = s * scale;
            }
            __syncwarp();

            float mx = (nz > 0) ? sp : -INFINITY;
            for (int j = lane; j < cnt; j += 32) mx = fmaxf(mx, swp[j]);
#pragma unroll
            for (int o = 16; o; o >>= 1) mx = fmaxf(mx, __shfl_xor_sync(0xffffffffu, mx, o));

            float dsum = 0.f;
            for (int j = lane; j < cnt; j += 32) {
                float e = expf(swp[j] - mx);
                swp[j] = e;
                dsum += e;
            }
            __syncwarp();
#pragma unroll
            for (int o = 16; o; o >>= 1) dsum += __shfl_xor_sync(0xffffffffu, dsum, o);
            const float ep = (nz > 0) ? expf(sp - mx) : 0.f;
            dsum += (float)nz * ep;

            float4 acc = make_float4(0.f, 0.f, 0.f, 0.f);
            for (int j = 0; j < cnt; j++) {
                const float w = swp[j];
                const float4 v4 = *(const float4*)&Vs[(jb + j) * 128 + (lane << 2)];
                acc.x += w * v4.x; acc.y += w * v4.y;
                acc.z += w * v4.z; acc.w += w * v4.w;
            }
            const float wp = (float)nz * ep;
            acc.x += wp * vb4.x; acc.y += wp * vb4.y;
            acc.z += wp * vb4.z; acc.w += wp * vb4.w;

            const float inv = 1.f / dsum;
            const float o0 = acc.x * inv, o1 = acc.y * inv, o2 = acc.z * inv, o3 = acc.w * inv;

            const size_t oo = (size_t)n * DM + h * DH + (lane << 2);
            __nv_bfloat16 h0 = __float2bfloat16(o0), h1 = __float2bfloat16(o1);
            __nv_bfloat16 h2 = __float2bfloat16(o2), h3 = __float2bfloat16(o3);
            __nv_bfloat162* ph = (__nv_bfloat162*)(Oh + oo);
            ph[0] = __halves2bfloat162(h0, h1); ph[1] = __halves2bfloat162(h2, h3);
            __nv_bfloat162* pl = (__nv_bfloat162*)(Ol + oo);
            pl[0] = __halves2bfloat162(__float2bfloat16(o0 - __bfloat162float(h0)),
                                       __float2bfloat16(o1 - __bfloat162float(h1)));
            pl[1] = __halves2bfloat162(__float2bfloat16(o2 - __bfloat162float(h2)),
                                       __float2bfloat16(o3 - __bfloat162float(h3)));
        }
    }
}

// ---------------------------------------------------------------------------
// Launch
// ---------------------------------------------------------------------------
extern "C" void kernel_launch(void* const* d_in, const int* in_sizes, int n_in,
                              void* d_out, int out_size) {
    const float* images    = (const float*)d_in[0];
    const float* capitions = (const float*)d_in[1];
    const float* tp_w  = (const float*)d_in[3];
    const float* tp_b  = (const float*)d_in[4];
    const float* ip_w  = (const float*)d_in[5];
    const float* ip_b  = (const float*)d_in[6];
    const float* ia_qw = (const float*)d_in[7];
    const float* ia_qb = (const float*)d_in[8];
    const float* ia_kw = (const float*)d_in[9];
    const float* ia_kb = (const float*)d_in[10];
    const float* ia_vw = (const float*)d_in[11];
    const float* ia_vb = (const float*)d_in[12];
    const float* ia_ow = (const float*)d_in[13];
    const float* ia_ob = (const float*)d_in[14];
    const float* ta_qw = (const float*)d_in[15];
    const float* ta_qb = (const float*)d_in[16];
    const float* ta_kw = (const float*)d_in[17];
    const float* ta_kb = (const float*)d_in[18];
    const float* ta_vw = (const float*)d_in[19];
    const float* ta_vb = (const float*)d_in[20];
    const float* ta_ow = (const float*)d_in[21];
    const float* ta_ob = (const float*)d_in[22];

    void* fp = nullptr; cudaGetSymbolAddress(&fp, g_f);
    void* bp = nullptr; cudaGetSymbolAddress(&bp, g_bf);
    float* F = (float*)fp;
    __nv_bfloat16* B = (__nv_bfloat16*)bp;

    float* g_txt = F + 0 * SZ;  float* g_img = F + 1 * SZ;
    float* g_q1  = F + 2 * SZ;  float* g_k1  = F + 3 * SZ;  float* g_v1 = F + 4 * SZ;
    float* g_q2  = F + 5 * SZ;  float* g_k2  = F + 6 * SZ;  float* g_v2 = F + 7 * SZ;

    size_t cur = 0;
    auto take = [&](size_t n) { __nv_bfloat16* p = B + cur; cur += n; return p; };
    const size_t WTP = 1024 * 768, W1 = 1024 * 1024;
    __nv_bfloat16 *tpw_h = take(WTP), *tpw_l = take(WTP);
    __nv_bfloat16 *ipw_h = take(W1),  *ipw_l = take(W1);
    __nv_bfloat16 *iaq_h = take(W1), *iaq_l = take(W1);
    __nv_bfloat16 *iak_h = take(W1), *iak_l = take(W1);
    __nv_bfloat16 *iav_h = take(W1), *iav_l = take(W1);
    __nv_bfloat16 *iao_h = take(W1), *iao_l = take(W1);
    __nv_bfloat16 *taq_h = take(W1), *taq_l = take(W1);
    __nv_bfloat16 *tak_h = take(W1), *tak_l = take(W1);
    __nv_bfloat16 *tav_h = take(W1), *tav_l = take(W1);
    __nv_bfloat16 *tao_h = take(W1), *tao_l = take(W1);
    __nv_bfloat16 *img_h = take(SZ), *img_l = take(SZ);
    __nv_bfloat16 *cap_h = take(NTOK * 768), *cap_l = take(NTOK * 768);
    __nv_bfloat16 *txt_h = take(SZ), *txt_l = take(SZ);
    __nv_bfloat16 *gim_h = take(SZ), *gim_l = take(SZ);
    __nv_bfloat16 *o1_h  = take(SZ), *o1_l  = take(SZ);
    __nv_bfloat16 *o2_h  = take(SZ), *o2_l  = take(SZ);

    float* out_img = (float*)d_out;
    float* out_txt = out_img + SZ;

    cudaFuncSetAttribute(gemm_mma, cudaFuncAttributeMaxDynamicSharedMemorySize, GEMM_SMEM);
    cudaFuncSetAttribute(attn_kernel, cudaFuncAttributeMaxDynamicSharedMemorySize, ATTN_SMEM);

    // 0: convert weights + inputs to split bf16
    CBatch cb = {};
    cb.s[0]  = { tp_w,      tpw_h, tpw_l, (int)(WTP / 4) };
    cb.s[1]  = { ip_w,      ipw_h, ipw_l, (int)(W1 / 4) };
    cb.s[2]  = { ia_qw,     iaq_h, iaq_l, (int)(W1 / 4) };
    cb.s[3]  = { ia_kw,     iak_h, iak_l, (int)(W1 / 4) };
    cb.s[4]  = { ia_vw,     iav_h, iav_l, (int)(W1 / 4) };
    cb.s[5]  = { ia_ow,     iao_h, iao_l, (int)(W1 / 4) };
    cb.s[6]  = { ta_qw,     taq_h, taq_l, (int)(W1 / 4) };
    cb.s[7]  = { ta_kw,     tak_h, tak_l, (int)(W1 / 4) };
    cb.s[8]  = { ta_vw,     tav_h, tav_l, (int)(W1 / 4) };
    cb.s[9]  = { ta_ow,     tao_h, tao_l, (int)(W1 / 4) };
    cb.s[10] = { images,    img_h, img_l, (int)(SZ / 4) };
    cb.s[11] = { capitions, cap_h, cap_l, (int)(NTOK * 768 / 4) };
    convert_kernel<<<dim3(1024, 12), 256>>>(cb);

    // 1: modality projections (fp32 out + split bf16 out)
    GB b1 = {};
    b1.d[0] = { cap_h, cap_l, tpw_h, tpw_l, tp_b, nullptr, g_txt, txt_h, txt_l, 768 };
    b1.d[1] = { img_h, img_l, ipw_h, ipw_l, ip_b, nullptr, g_img, gim_h, gim_l, 1024 };
    gemm_mma<<<dim3(8, 4, 2), 256, GEMM_SMEM>>>(b1, DM);

    // 2: Q/K/V for both attentions (fp32 out only)
    GB b2 = {};
    b2.d[0] = { gim_h, gim_l, iaq_h, iaq_l, ia_qb, nullptr, g_q1, nullptr, nullptr, 1024 };
    b2.d[1] = { txt_h, txt_l, iak_h, iak_l, ia_kb, nullptr, g_k1, nullptr, nullptr, 1024 };
    b2.d[2] = { txt_h, txt_l, iav_h, iav_l, ia_vb, nullptr, g_v1, nullptr, nullptr, 1024 };
    b2.d[3] = { txt_h, txt_l, taq_h, taq_l, ta_qb, nullptr, g_q2, nullptr, nullptr, 1024 };
    b2.d[4] = { gim_h, gim_l, tak_h, tak_l, ta_kb, nullptr, g_k2, nullptr, nullptr, 1024 };
    b2.d[5] = { gim_h, gim_l, tav_h, tav_l, ta_vb, nullptr, g_v2, nullptr, nullptr, 1024 };
    gemm_mma<<<dim3(8, 4, 6), 256, GEMM_SMEM>>>(b2, DM);

    // 3: windowed attention -> split bf16 outputs
    attn_kernel<<<dim3(NTOK / AQ, 2), 256, ATTN_SMEM>>>(
        g_q1, g_k1, g_v1, ia_kb, ia_vb, o1_h, o1_l,
        g_q2, g_k2, g_v2, ta_kb, ta_vb, o2_h, o2_l);

    // 4: output projections + residual -> d_out
    GB b4 = {};
    b4.d[0] = { o1_h, o1_l, iao_h, iao_l, ia_ob, g_img, out_img, nullptr, nullptr, 1024 };
    b4.d[1] = { o2_h, o2_l, tao_h, tao_l, ta_ob, g_txt, out_txt, nullptr, nullptr, 1024 };
    gemm_mma<<<dim3(8, 4, 2), 256, GEMM_SMEM>>>(b4, DM);
}

// round 4
// speedup vs baseline: 1.8057x; 1.5423x over previous
#include <cuda_runtime.h>
#include <cuda_bf16.h>
#include <math.h>
#include <stdint.h>

// ===========================================================================
// CrossModalFusionModel via mma.sync (HMMA) on sm_103 base target.
// GEMMs: bf16 hi/lo split (3 passes: AhiWhi + AhiWlo + AloWhi, fp32 acc).
// Attention: transposed-K smem, shfl-free scores, one block per (qtile,head).
// ===========================================================================

#define NTOK  512
#define DM    1024
#define HEADS 8
#define DH    128
#define WIN   64
#define HALF  32

// ---------------------------------------------------------------------------
// Low-level helpers (base-target ISA only: cp.async, ldmatrix, mma.sync)
// ---------------------------------------------------------------------------
__device__ __forceinline__ uint32_t s2u(const void* p) {
    uint32_t a;
    asm("{ .reg .u64 t; cvta.to.shared.u64 t, %1; cvt.u32.u64 %0, t; }" : "=r"(a) : "l"(p));
    return a;
}
__device__ __forceinline__ void cp16(uint32_t smem, const void* g) {
    asm volatile("cp.async.cg.shared.global [%0], [%1], 16;" :: "r"(smem), "l"(g));
}
#define CP_COMMIT() asm volatile("cp.async.commit_group;" ::: "memory")
#define CP_WAIT0()  asm volatile("cp.async.wait_group 0;" ::: "memory")
#define CP_WAIT1()  asm volatile("cp.async.wait_group 1;" ::: "memory")

__device__ __forceinline__ void ldx4(uint32_t r[4], uint32_t addr) {
    asm volatile("ldmatrix.sync.aligned.m8n8.x4.shared.b16 {%0,%1,%2,%3}, [%4];"
        : "=r"(r[0]), "=r"(r[1]), "=r"(r[2]), "=r"(r[3]) : "r"(addr));
}
__device__ __forceinline__ void mma16816(float d[4], const uint32_t a[4],
                                         uint32_t b0, uint32_t b1) {
    asm volatile(
        "mma.sync.aligned.m16n8k16.row.col.f32.bf16.bf16.f32 "
        "{%0,%1,%2,%3}, {%4,%5,%6,%7}, {%8,%9}, {%0,%1,%2,%3};"
        : "+f"(d[0]), "+f"(d[1]), "+f"(d[2]), "+f"(d[3])
        : "r"(a[0]), "r"(a[1]), "r"(a[2]), "r"(a[3]), "r"(b0), "r"(b1));
}

// ---------------------------------------------------------------------------
// Scratch (static __device__ — no allocation)
// ---------------------------------------------------------------------------
#define SZ (NTOK * DM)                 // 524288
__device__ float          g_f[8 * SZ]; // txt,img,q1,k1,v1,q2,k2,v2 (fp32)
__device__ __nv_bfloat16  g_bf[26476544];

// ---------------------------------------------------------------------------
// Conversion: fp32 -> (hi, lo) bf16, batched segments
// ---------------------------------------------------------------------------
struct CSeg { const float* src; __nv_bfloat16 *hi, *lo; int n4; };
struct CBatch { CSeg s[12]; };

__global__ __launch_bounds__(256)
void convert_kernel(CBatch cb) {
    CSeg s = cb.s[blockIdx.y];
    int i = blockIdx.x * 256 + threadIdx.x;
    if (i >= s.n4) return;
    float4 x = ((const float4*)s.src)[i];
    __nv_bfloat16 h0 = __float2bfloat16(x.x);
    __nv_bfloat16 h1 = __float2bfloat16(x.y);
    __nv_bfloat16 h2 = __float2bfloat16(x.z);
    __nv_bfloat16 h3 = __float2bfloat16(x.w);
    __nv_bfloat16 l0 = __float2bfloat16(x.x - __bfloat162float(h0));
    __nv_bfloat16 l1 = __float2bfloat16(x.y - __bfloat162float(h1));
    __nv_bfloat16 l2 = __float2bfloat16(x.z - __bfloat162float(h2));
    __nv_bfloat16 l3 = __float2bfloat16(x.w - __bfloat162float(h3));
    __nv_bfloat162* ph = (__nv_bfloat162*)(s.hi) + 2 * i;
    __nv_bfloat162* pl = (__nv_bfloat162*)(s.lo) + 2 * i;
    ph[0] = __halves2bfloat162(h0, h1); ph[1] = __halves2bfloat162(h2, h3);
    pl[0] = __halves2bfloat162(l0, l1); pl[1] = __halves2bfloat162(l2, l3);
}

// ---------------------------------------------------------------------------
// mma.sync GEMM: C[M,N] = A[M,K] @ W[N,K]^T (+bias)(+resid), split-bf16.
// CTA tile 128x128, 8 warps (warp tile 32x64), K-chunks of 64,
// cp.async double buffer, XOR-swizzled smem, fused 3-pass split.
// ---------------------------------------------------------------------------
struct GD {
    const __nv_bfloat16 *Ahi, *Alo, *Whi, *Wlo;
    const float *bias, *resid;
    float* C;
    __nv_bfloat16 *Chi, *Clo;   // optional split output
    int K;
};
struct GB { GD d[6]; };

#define TILE_B    16384                  // 128 rows x 128 bytes
#define BUF_B     (4 * TILE_B)           // Ahi,Alo,Whi,Wlo
#define GEMM_SMEM (2 * BUF_B)            // 131072

__device__ __forceinline__ void load_tile(uint32_t sdst, const __nv_bfloat16* src,
                                          int row0, int k0, int K, int tid) {
    const char* g = (const char*)(src + (size_t)row0 * K + k0);
    const size_t rstride = (size_t)K * 2;
#pragma unroll
    for (int it = 0; it < 4; it++) {
        int idx = tid + it * 256;            // 0..1023
        int r = idx >> 3, f4 = idx & 7;
        cp16(sdst + (uint32_t)(r * 128 + ((f4 * 16) ^ ((r & 7) << 4))),
             g + (size_t)r * rstride + f4 * 16);
    }
}
__device__ __forceinline__ void load4(uint32_t bo, const GD& g,
                                      int m0, int n0, int k0, int tid) {
    load_tile(bo,              g.Ahi, m0, k0, g.K, tid);
    load_tile(bo + TILE_B,     g.Alo, m0, k0, g.K, tid);
    load_tile(bo + 2 * TILE_B, g.Whi, n0, k0, g.K, tid);
    load_tile(bo + 3 * TILE_B, g.Wlo, n0, k0, g.K, tid);
}

__global__ __launch_bounds__(256, 1)
void gemm_mma(GB batch, int N) {
    extern __shared__ char smem[];
    const GD g = batch.d[blockIdx.z];
    const uint32_t sb = s2u(smem);
    const int tid = threadIdx.x, wid = tid >> 5, lane = tid & 31;
    const int m0 = blockIdx.y * 128, n0 = blockIdx.x * 128;
    const int wm = (wid & 3) * 32;
    const int wn = (wid >> 2) * 64;

    float acc[2][8][4];
#pragma unroll
    for (int a = 0; a < 2; a++)
#pragma unroll
        for (int b = 0; b < 8; b++)
#pragma unroll
            for (int c = 0; c < 4; c++) acc[a][b][c] = 0.f;

    const int nch = g.K >> 6;
    const int      lrow = lane & 15;
    const uint32_t cgb  = (uint32_t)((lane >> 4) * 16);
    const uint32_t xm   = (uint32_t)((lrow & 7) << 4);

    load4(sb, g, m0, n0, 0, tid);
    CP_COMMIT();

    for (int i = 0; i < nch; i++) {
        if (i + 1 < nch) {
            load4(sb + (uint32_t)(((i + 1) & 1) * BUF_B), g, m0, n0, (i + 1) << 6, tid);
            CP_COMMIT();
            CP_WAIT1();
        } else {
            CP_WAIT0();
        }
        __syncthreads();

        const uint32_t bo = sb + (uint32_t)((i & 1) * BUF_B);
        const uint32_t aHi = bo + (uint32_t)((wm + lrow) * 128);
        const uint32_t aLo = aHi + TILE_B;
        const uint32_t bHi = bo + 2 * TILE_B + (uint32_t)((wn + lrow) * 128);
        const uint32_t bLo = bHi + TILE_B;

#pragma unroll
        for (int ks = 0; ks < 4; ks++) {
            const uint32_t co = ((uint32_t)(ks * 32) + cgb) ^ xm;
            uint32_t ah[2][4], al[2][4], bh[4][4], bl[4][4];
#pragma unroll
            for (int mf = 0; mf < 2; mf++) {
                ldx4(ah[mf], aHi + (uint32_t)(mf * 16 * 128) + co);
                ldx4(al[mf], aLo + (uint32_t)(mf * 16 * 128) + co);
            }
#pragma unroll
            for (int p = 0; p < 4; p++) {
                ldx4(bh[p], bHi + (uint32_t)(p * 16 * 128) + co);
                ldx4(bl[p], bLo + (uint32_t)(p * 16 * 128) + co);
            }
#pragma unroll
            for (int mf = 0; mf < 2; mf++)
#pragma unroll
                for (int nf = 0; nf < 8; nf++) {
                    const int p = nf >> 1, o = nf & 1;
                    mma16816(acc[mf][nf], ah[mf], bh[p][o], bh[p][o + 2]);
                    mma16816(acc[mf][nf], ah[mf], bl[p][o], bl[p][o + 2]);
                    mma16816(acc[mf][nf], al[mf], bh[p][o], bh[p][o + 2]);
                }
        }
        __syncthreads();
    }

    const int qr = lane >> 2, qc = (lane & 3) * 2;
#pragma unroll
    for (int mf = 0; mf < 2; mf++) {
        const int r0 = m0 + wm + mf * 16 + qr;
#pragma unroll
        for (int nf = 0; nf < 8; nf++) {
            const int c = n0 + wn + nf * 8 + qc;
            const float2 bv = *(const float2*)(g.bias + c);
            float o00 = acc[mf][nf][0] + bv.x, o01 = acc[mf][nf][1] + bv.y;
            float o10 = acc[mf][nf][2] + bv.x, o11 = acc[mf][nf][3] + bv.y;
            const size_t off0 = (size_t)r0 * N + c;
            const size_t off1 = off0 + (size_t)8 * N;
            if (g.resid) {
                float2 ra = *(const float2*)(g.resid + off0);
                float2 rb = *(const float2*)(g.resid + off1);
                o00 += ra.x; o01 += ra.y; o10 += rb.x; o11 += rb.y;
            }
            *(float2*)(g.C + off0) = make_float2(o00, o01);
            *(float2*)(g.C + off1) = make_float2(o10, o11);
            if (g.Chi) {
                __nv_bfloat16 h00 = __float2bfloat16(o00), h01 = __float2bfloat16(o01);
                __nv_bfloat16 h10 = __float2bfloat16(o10), h11 = __float2bfloat16(o11);
                *(__nv_bfloat162*)(g.Chi + off0) = __halves2bfloat162(h00, h01);
                *(__nv_bfloat162*)(g.Chi + off1) = __halves2bfloat162(h10, h11);
                *(__nv_bfloat162*)(g.Clo + off0) = __halves2bfloat162(
                    __float2bfloat16(o00 - __bfloat162float(h00)),
                    __float2bfloat16(o01 - __bfloat162float(h01)));
                *(__nv_bfloat162*)(g.Clo + off1) = __halves2bfloat162(
                    __float2bfloat16(o10 - __bfloat162float(h10)),
                    __float2bfloat16(o11 - __bfloat162float(h11)));
            }
        }
    }
}

// ---------------------------------------------------------------------------
// Sliding-window attention, v2: grid (NTOK/QB, HEADS, 2), block 256.
// Smem: Kt[128][82] transposed (+pad col 81 = kb), V[82][128] (+pad row = vb),
// Q[16][128], weights [8][68]. Lanes own window POSITIONS for scores (no
// shfl in the hot loop), own DIMS for the AV pass.
// ---------------------------------------------------------------------------
#define QB    16
#define WR    81                     // real window rows
#define WC    82                     // + pad column
#define PADC  81
#define ATTN_SMEM ((128 * WC + WC * 128 + QB * 128 + 8 * 68) * 4)  // 94336

__global__ __launch_bounds__(256)
void attn_kernel(const float* __restrict__ Q1, const float* __restrict__ K1,
                 const float* __restrict__ V1, const float* __restrict__ kb1,
                 const float* __restrict__ vb1,
                 __nv_bfloat16* __restrict__ O1h, __nv_bfloat16* __restrict__ O1l,
                 const float* __restrict__ Q2, const float* __restrict__ K2,
                 const float* __restrict__ V2, const float* __restrict__ kb2,
                 const float* __restrict__ vb2,
                 __nv_bfloat16* __restrict__ O2h, __nv_bfloat16* __restrict__ O2l) {
    extern __shared__ float sm[];
    float* Kt = sm;                      // [128][WC]
    float* Vs = Kt + 128 * WC;           // [WC][128]
    float* Qs = Vs + WC * 128;           // [QB][128]
    float* Ws = Qs + QB * 128;           // [8][68]

    const float *Q, *K, *V, *kb, *vb;
    __nv_bfloat16 *Oh, *Ol;
    if (blockIdx.z == 0) { Q=Q1; K=K1; V=V1; kb=kb1; vb=vb1; Oh=O1h; Ol=O1l; }
    else                 { Q=Q2; K=K2; V=V2; kb=kb2; vb=vb2; Oh=O2h; Ol=O2l; }

    const int h   = blockIdx.y;
    const int tid = threadIdx.x, wid = tid >> 5, lane = tid & 31;
    const int q0  = blockIdx.x * QB;
    const int base = q0 - HALF;
    const int jmin = max(0, -base);
    const int jmax = min(NTOK - 1, q0 + QB - 1 + HALF + 1) - base;
    const float scale = 0.088388347648318447f;   // 1/sqrt(128)

    // ---- load K (transposed), V, pad col/row, Q tile ----
    for (int idx = tid; idx < WR * 32; idx += 256) {
        const int j = idx >> 5, dg = idx & 31;
        if (j >= jmin && j <= jmax) {
            const size_t go = (size_t)(base + j) * DM + h * DH + dg * 4;
            const float4 kv = *(const float4*)(K + go);
            Kt[(dg * 4 + 0) * WC + j] = kv.x;
            Kt[(dg * 4 + 1) * WC + j] = kv.y;
            Kt[(dg * 4 + 2) * WC + j] = kv.z;
            Kt[(dg * 4 + 3) * WC + j] = kv.w;
            *(float4*)&Vs[j * 128 + dg * 4] = *(const float4*)(V + go);
        }
    }
    if (tid < 32) {                                   // pad slot (kb, vb)
        const float4 kv = *(const float4*)(kb + h * DH + tid * 4);
        Kt[(tid * 4 + 0) * WC + PADC] = kv.x;
        Kt[(tid * 4 + 1) * WC + PADC] = kv.y;
        Kt[(tid * 4 + 2) * WC + PADC] = kv.z;
        Kt[(tid * 4 + 3) * WC + PADC] = kv.w;
        *(float4*)&Vs[PADC * 128 + tid * 4] = *(const float4*)(vb + h * DH + tid * 4);
    }
    for (int idx = tid; idx < QB * 32; idx += 256) {
        const int q = idx >> 5, dg = idx & 31;
        *(float4*)&Qs[q * 128 + dg * 4] =
            *(const float4*)(Q + (size_t)(q0 + q) * DM + h * DH + dg * 4);
    }
    __syncthreads();

    float* wq = Ws + wid * 68;

#pragma unroll
    for (int qq = 0; qq < 2; qq++) {
        const int n   = q0 + wid * 2 + qq;
        const int lo  = max(0, n - HALF);
        const int hi  = min(NTOK - 1, n + HALF + 1);
        const int cnt = hi - lo + 1;
        const int nz  = max(0, WIN - cnt);
        const int jb  = lo - base;
        const int npos = cnt + (nz > 0 ? 1 : 0);

        const float* qp = Qs + (wid * 2 + qq) * 128;

        // lane owns positions lane, lane+32, lane+64
        int colx[3]; bool act[3];
        float s0 = 0.f, s1 = 0.f, s2 = 0.f;
#pragma unroll
        for (int t = 0; t < 3; t++) {
            const int p = lane + 32 * t;
            act[t] = (p < npos);
            colx[t] = !act[t] ? 0 : (p < cnt ? jb + p : PADC);
        }
        const int c0 = colx[0], c1 = colx[1], c2 = colx[2];

#pragma unroll 4
        for (int d4 = 0; d4 < 32; d4++) {
            const float4 q4 = *(const float4*)&qp[d4 * 4];
            const float* kr0 = &Kt[(d4 * 4) * WC];
            s0 += q4.x * kr0[c0]          + q4.y * kr0[WC + c0]
                + q4.z * kr0[2 * WC + c0] + q4.w * kr0[3 * WC + c0];
            s1 += q4.x * kr0[c1]          + q4.y * kr0[WC + c1]
                + q4.z * kr0[2 * WC + c1] + q4.w * kr0[3 * WC + c1];
            s2 += q4.x * kr0[c2]          + q4.y * kr0[WC + c2]
                + q4.z * kr0[2 * WC + c2] + q4.w * kr0[3 * WC + c2];
        }
        s0 = act[0] ? s0 * scale : -INFINITY;
        s1 = act[1] ? s1 * scale : -INFINITY;
        s2 = act[2] ? s2 * scale : -INFINITY;

        float mx = fmaxf(s0, fmaxf(s1, s2));
#pragma unroll
        for (int o = 16; o; o >>= 1) mx = fmaxf(mx, __shfl_xor_sync(0xffffffffu, mx, o));

        float dsum = 0.f;
#pragma unroll
        for (int t = 0; t < 3; t++) {
            const int p = lane + 32 * t;
            const float sv = (t == 0) ? s0 : (t == 1) ? s1 : s2;
            float wv = 0.f;
            if (act[t]) {
                float e = expf(sv - mx);
                wv = (p == cnt) ? (float)nz * e : e;   // pad weight scaled by nz
                wq[p] = wv;
            }
            dsum += wv;
        }
#pragma unroll
        for (int o = 16; o; o >>= 1) dsum += __shfl_xor_sync(0xffffffffu, dsum, o);
        __syncwarp();

        // AV: lane owns dims lane*4..lane*4+3
        float4 acc = make_float4(0.f, 0.f, 0.f, 0.f);
        for (int p = 0; p < npos; p++) {
            const float w = wq[p];
            const int c = (p < cnt) ? jb + p : PADC;
            const float4 v4 = *(const float4*)&Vs[c * 128 + lane * 4];
            acc.x += w * v4.x; acc.y += w * v4.y;
            acc.z += w * v4.z; acc.w += w * v4.w;
        }
        __syncwarp();

        const float inv = 1.f / dsum;
        const float o0 = acc.x * inv, o1 = acc.y * inv, o2 = acc.z * inv, o3 = acc.w * inv;

        const size_t oo = (size_t)n * DM + h * DH + lane * 4;
        __nv_bfloat16 h0 = __float2bfloat16(o0), h1 = __float2bfloat16(o1);
        __nv_bfloat16 h2 = __float2bfloat16(o2), h3 = __float2bfloat16(o3);
        __nv_bfloat162* ph = (__nv_bfloat162*)(Oh + oo);
        ph[0] = __halves2bfloat162(h0, h1); ph[1] = __halves2bfloat162(h2, h3);
        __nv_bfloat162* pl = (__nv_bfloat162*)(Ol + oo);
        pl[0] = __halves2bfloat162(__float2bfloat16(o0 - __bfloat162float(h0)),
                                   __float2bfloat16(o1 - __bfloat162float(h1)));
        pl[1] = __halves2bfloat162(__float2bfloat16(o2 - __bfloat162float(h2)),
                                   __float2bfloat16(o3 - __bfloat162float(h3)));
    }
}

// ---------------------------------------------------------------------------
// Launch
// ---------------------------------------------------------------------------
extern "C" void kernel_launch(void* const* d_in, const int* in_sizes, int n_in,
                              void* d_out, int out_size) {
    const float* images    = (const float*)d_in[0];
    const float* capitions = (const float*)d_in[1];
    const float* tp_w  = (const float*)d_in[3];
    const float* tp_b  = (const float*)d_in[4];
    const float* ip_w  = (const float*)d_in[5];
    const float* ip_b  = (const float*)d_in[6];
    const float* ia_qw = (const float*)d_in[7];
    const float* ia_qb = (const float*)d_in[8];
    const float* ia_kw = (const float*)d_in[9];
    const float* ia_kb = (const float*)d_in[10];
    const float* ia_vw = (const float*)d_in[11];
    const float* ia_vb = (const float*)d_in[12];
    const float* ia_ow = (const float*)d_in[13];
    const float* ia_ob = (const float*)d_in[14];
    const float* ta_qw = (const float*)d_in[15];
    const float* ta_qb = (const float*)d_in[16];
    const float* ta_kw = (const float*)d_in[17];
    const float* ta_kb = (const float*)d_in[18];
    const float* ta_vw = (const float*)d_in[19];
    const float* ta_vb = (const float*)d_in[20];
    const float* ta_ow = (const float*)d_in[21];
    const float* ta_ob = (const float*)d_in[22];

    void* fp = nullptr; cudaGetSymbolAddress(&fp, g_f);
    void* bp = nullptr; cudaGetSymbolAddress(&bp, g_bf);
    float* F = (float*)fp;
    __nv_bfloat16* B = (__nv_bfloat16*)bp;

    float* g_txt = F + 0 * SZ;  float* g_img = F + 1 * SZ;
    float* g_q1  = F + 2 * SZ;  float* g_k1  = F + 3 * SZ;  float* g_v1 = F + 4 * SZ;
    float* g_q2  = F + 5 * SZ;  float* g_k2  = F + 6 * SZ;  float* g_v2 = F + 7 * SZ;

    size_t cur = 0;
    auto take = [&](size_t n) { __nv_bfloat16* p = B + cur; cur += n; return p; };
    const size_t WTP = 1024 * 768, W1 = 1024 * 1024;
    __nv_bfloat16 *tpw_h = take(WTP), *tpw_l = take(WTP);
    __nv_bfloat16 *ipw_h = take(W1),  *ipw_l = take(W1);
    __nv_bfloat16 *iaq_h = take(W1), *iaq_l = take(W1);
    __nv_bfloat16 *iak_h = take(W1), *iak_l = take(W1);
    __nv_bfloat16 *iav_h = take(W1), *iav_l = take(W1);
    __nv_bfloat16 *iao_h = take(W1), *iao_l = take(W1);
    __nv_bfloat16 *taq_h = take(W1), *taq_l = take(W1);
    __nv_bfloat16 *tak_h = take(W1), *tak_l = take(W1);
    __nv_bfloat16 *tav_h = take(W1), *tav_l = take(W1);
    __nv_bfloat16 *tao_h = take(W1), *tao_l = take(W1);
    __nv_bfloat16 *img_h = take(SZ), *img_l = take(SZ);
    __nv_bfloat16 *cap_h = take(NTOK * 768), *cap_l = take(NTOK * 768);
    __nv_bfloat16 *txt_h = take(SZ), *txt_l = take(SZ);
    __nv_bfloat16 *gim_h = take(SZ), *gim_l = take(SZ);
    __nv_bfloat16 *o1_h  = take(SZ), *o1_l  = take(SZ);
    __nv_bfloat16 *o2_h  = take(SZ), *o2_l  = take(SZ);

    float* out_img = (float*)d_out;
    float* out_txt = out_img + SZ;

    cudaFuncSetAttribute(gemm_mma, cudaFuncAttributeMaxDynamicSharedMemorySize, GEMM_SMEM);
    cudaFuncSetAttribute(attn_kernel, cudaFuncAttributeMaxDynamicSharedMemorySize, ATTN_SMEM);

    // 0: convert weights + inputs to split bf16
    CBatch cb = {};
    cb.s[0]  = { tp_w,      tpw_h, tpw_l, (int)(WTP / 4) };
    cb.s[1]  = { ip_w,      ipw_h, ipw_l, (int)(W1 / 4) };
    cb.s[2]  = { ia_qw,     iaq_h, iaq_l, (int)(W1 / 4) };
    cb.s[3]  = { ia_kw,     iak_h, iak_l, (int)(W1 / 4) };
    cb.s[4]  = { ia_vw,     iav_h, iav_l, (int)(W1 / 4) };
    cb.s[5]  = { ia_ow,     iao_h, iao_l, (int)(W1 / 4) };
    cb.s[6]  = { ta_qw,     taq_h, taq_l, (int)(W1 / 4) };
    cb.s[7]  = { ta_kw,     tak_h, tak_l, (int)(W1 / 4) };
    cb.s[8]  = { ta_vw,     tav_h, tav_l, (int)(W1 / 4) };
    cb.s[9]  = { ta_ow,     tao_h, tao_l, (int)(W1 / 4) };
    cb.s[10] = { images,    img_h, img_l, (int)(SZ / 4) };
    cb.s[11] = { capitions, cap_h, cap_l, (int)(NTOK * 768 / 4) };
    convert_kernel<<<dim3(1024, 12), 256>>>(cb);

    // 1: modality projections (fp32 out + split bf16 out)
    GB b1 = {};
    b1.d[0] = { cap_h, cap_l, tpw_h, tpw_l, tp_b, nullptr, g_txt, txt_h, txt_l, 768 };
    b1.d[1] = { img_h, img_l, ipw_h, ipw_l, ip_b, nullptr, g_img, gim_h, gim_l, 1024 };
    gemm_mma<<<dim3(8, 4, 2), 256, GEMM_SMEM>>>(b1, DM);

    // 2: Q/K/V for both attentions (fp32 out only)
    GB b2 = {};
    b2.d[0] = { gim_h, gim_l, iaq_h, iaq_l, ia_qb, nullptr, g_q1, nullptr, nullptr, 1024 };
    b2.d[1] = { txt_h, txt_l, iak_h, iak_l, ia_kb, nullptr, g_k1, nullptr, nullptr, 1024 };
    b2.d[2] = { txt_h, txt_l, iav_h, iav_l, ia_vb, nullptr, g_v1, nullptr, nullptr, 1024 };
    b2.d[3] = { txt_h, txt_l, taq_h, taq_l, ta_qb, nullptr, g_q2, nullptr, nullptr, 1024 };
    b2.d[4] = { gim_h, gim_l, tak_h, tak_l, ta_kb, nullptr, g_k2, nullptr, nullptr, 1024 };
    b2.d[5] = { gim_h, gim_l, tav_h, tav_l, ta_vb, nullptr, g_v2, nullptr, nullptr, 1024 };
    gemm_mma<<<dim3(8, 4, 6), 256, GEMM_SMEM>>>(b2, DM);

    // 3: windowed attention -> split bf16 outputs
    attn_kernel<<<dim3(NTOK / QB, HEADS, 2), 256, ATTN_SMEM>>>(
        g_q1, g_k1, g_v1, ia_kb, ia_vb, o1_h, o1_l,
        g_q2, g_k2, g_v2, ta_kb, ta_vb, o2_h, o2_l);

    // 4: output projections + residual -> d_out
    GB b4 = {};
    b4.d[0] = { o1_h, o1_l, iao_h, iao_l, ia_ob, g_img, out_img, nullptr, nullptr, 1024 };
    b4.d[1] = { o2_h, o2_l, tao_h, tao_l, ta_ob, g_txt, out_txt, nullptr, nullptr, 1024 };
    gemm_mma<<<dim3(8, 4, 2), 256, GEMM_SMEM>>>(b4, DM);
}

// round 5
// speedup vs baseline: 2.4043x; 1.3315x over previous
#include <cuda_runtime.h>
#include <cuda_fp16.h>
#include <math.h>
#include <stdint.h>

// ===========================================================================
// CrossModalFusionModel via mma.sync (HMMA fp16) on sm_103 base target.
// GEMMs: fp16 activation hi/lo split, single-fp16 weights, 2 passes:
//   C = Ahi@Whi + Alo@Whi   (residual A@Wlo ~ 2^-12 -> rel err ~1e-4)
// Attention: transposed-K smem, shfl-free scores (unchanged from R4).
// ===========================================================================

#define NTOK  512
#define DM    1024
#define HEADS 8
#define DH    128
#define WIN   64
#define HALF  32

// ---------------------------------------------------------------------------
// Low-level helpers (base-target ISA only: cp.async, ldmatrix, mma.sync)
// ---------------------------------------------------------------------------
__device__ __forceinline__ uint32_t s2u(const void* p) {
    uint32_t a;
    asm("{ .reg .u64 t; cvta.to.shared.u64 t, %1; cvt.u32.u64 %0, t; }" : "=r"(a) : "l"(p));
    return a;
}
__device__ __forceinline__ void cp16(uint32_t smem, const void* g) {
    asm volatile("cp.async.cg.shared.global [%0], [%1], 16;" :: "r"(smem), "l"(g));
}
#define CP_COMMIT() asm volatile("cp.async.commit_group;" ::: "memory")
#define CP_WAIT0()  asm volatile("cp.async.wait_group 0;" ::: "memory")
#define CP_WAIT1()  asm volatile("cp.async.wait_group 1;" ::: "memory")

__device__ __forceinline__ void ldx4(uint32_t r[4], uint32_t addr) {
    asm volatile("ldmatrix.sync.aligned.m8n8.x4.shared.b16 {%0,%1,%2,%3}, [%4];"
        : "=r"(r[0]), "=r"(r[1]), "=r"(r[2]), "=r"(r[3]) : "r"(addr));
}
__device__ __forceinline__ void mma16816(float d[4], const uint32_t a[4],
                                         uint32_t b0, uint32_t b1) {
    asm volatile(
        "mma.sync.aligned.m16n8k16.row.col.f32.f16.f16.f32 "
        "{%0,%1,%2,%3}, {%4,%5,%6,%7}, {%8,%9}, {%0,%1,%2,%3};"
        : "+f"(d[0]), "+f"(d[1]), "+f"(d[2]), "+f"(d[3])
        : "r"(a[0]), "r"(a[1]), "r"(a[2]), "r"(a[3]), "r"(b0), "r"(b1));
}

// ---------------------------------------------------------------------------
// Scratch (static __device__ — no allocation)
// ---------------------------------------------------------------------------
#define SZ (NTOK * DM)                 // 524288
__device__ float   g_f[8 * SZ];        // txt,img,q1,k1,v1,q2,k2,v2 (fp32)
__device__ __half  g_hf[26476544];

// ---------------------------------------------------------------------------
// Conversion: fp32 -> fp16 (hi[,lo]), batched segments. lo==nullptr => single.
// ---------------------------------------------------------------------------
struct CSeg { const float* src; __half *hi, *lo; int n4; };
struct CBatch { CSeg s[12]; };

__global__ __launch_bounds__(256)
void convert_kernel(CBatch cb) {
    CSeg s = cb.s[blockIdx.y];
    int i = blockIdx.x * 256 + threadIdx.x;
    if (i >= s.n4) return;
    float4 x = ((const float4*)s.src)[i];
    __half h0 = __float2half(x.x), h1 = __float2half(x.y);
    __half h2 = __float2half(x.z), h3 = __float2half(x.w);
    __half2* ph = (__half2*)(s.hi) + 2 * i;
    ph[0] = __halves2half2(h0, h1); ph[1] = __halves2half2(h2, h3);
    if (s.lo) {
        __half2* pl = (__half2*)(s.lo) + 2 * i;
        pl[0] = __halves2half2(__float2half(x.x - __half2float(h0)),
                               __float2half(x.y - __half2float(h1)));
        pl[1] = __halves2half2(__float2half(x.z - __half2float(h2)),
                               __float2half(x.w - __half2float(h3)));
    }
}

// ---------------------------------------------------------------------------
// mma.sync GEMM: C[M,N] = A[M,K] @ W[N,K]^T (+bias)(+resid), split-fp16 A.
// CTA tile 128x128, 8 warps (warp tile 32x64), K-chunks of 64,
// cp.async double buffer (3 tiles = 48KB each), XOR-swizzled smem, 2 passes.
// ---------------------------------------------------------------------------
struct GD {
    const __half *Ahi, *Alo, *Whi;
    const float *bias, *resid;
    float* C;
    __half *Chi, *Clo;   // optional split output
    int K;
};
struct GB { GD d[6]; };

#define TILE_B    16384                  // 128 rows x 128 bytes
#define BUF_B     (3 * TILE_B)           // Ahi, Alo, Whi
#define GEMM_SMEM (2 * BUF_B)            // 98304 -> 2 CTAs/SM

__device__ __forceinline__ void load_tile(uint32_t sdst, const __half* src,
                                          int row0, int k0, int K, int tid) {
    const char* g = (const char*)(src + (size_t)row0 * K + k0);
    const size_t rstride = (size_t)K * 2;
#pragma unroll
    for (int it = 0; it < 4; it++) {
        int idx = tid + it * 256;            // 0..1023
        int r = idx >> 3, f4 = idx & 7;
        cp16(sdst + (uint32_t)(r * 128 + ((f4 * 16) ^ ((r & 7) << 4))),
             g + (size_t)r * rstride + f4 * 16);
    }
}
__device__ __forceinline__ void load3(uint32_t bo, const GD& g,
                                      int m0, int n0, int k0, int tid) {
    load_tile(bo,              g.Ahi, m0, k0, g.K, tid);
    load_tile(bo + TILE_B,     g.Alo, m0, k0, g.K, tid);
    load_tile(bo + 2 * TILE_B, g.Whi, n0, k0, g.K, tid);
}

__global__ __launch_bounds__(256, 2)
void gemm_mma(GB batch, int N) {
    extern __shared__ char smem[];
    const GD g = batch.d[blockIdx.z];
    const uint32_t sb = s2u(smem);
    const int tid = threadIdx.x, wid = tid >> 5, lane = tid & 31;
    const int m0 = blockIdx.y * 128, n0 = blockIdx.x * 128;
    const int wm = (wid & 3) * 32;
    const int wn = (wid >> 2) * 64;

    float acc[2][8][4];
#pragma unroll
    for (int a = 0; a < 2; a++)
#pragma unroll
        for (int b = 0; b < 8; b++)
#pragma unroll
            for (int c = 0; c < 4; c++) acc[a][b][c] = 0.f;

    const int nch = g.K >> 6;
    const int      lrow = lane & 15;
    const uint32_t cgb  = (uint32_t)((lane >> 4) * 16);
    const uint32_t xm   = (uint32_t)((lrow & 7) << 4);

    load3(sb, g, m0, n0, 0, tid);
    CP_COMMIT();

    for (int i = 0; i < nch; i++) {
        if (i + 1 < nch) {
            load3(sb + (uint32_t)(((i + 1) & 1) * BUF_B), g, m0, n0, (i + 1) << 6, tid);
            CP_COMMIT();
            CP_WAIT1();
        } else {
            CP_WAIT0();
        }
        __syncthreads();

        const uint32_t bo = sb + (uint32_t)((i & 1) * BUF_B);
        const uint32_t aHi = bo + (uint32_t)((wm + lrow) * 128);
        const uint32_t aLo = aHi + TILE_B;
        const uint32_t bHi = bo + 2 * TILE_B + (uint32_t)((wn + lrow) * 128);

#pragma unroll
        for (int ks = 0; ks < 4; ks++) {
            const uint32_t co = ((uint32_t)(ks * 32) + cgb) ^ xm;
            uint32_t ah[2][4], al[2][4], bh[4][4];
#pragma unroll
            for (int mf = 0; mf < 2; mf++) {
                ldx4(ah[mf], aHi + (uint32_t)(mf * 16 * 128) + co);
                ldx4(al[mf], aLo + (uint32_t)(mf * 16 * 128) + co);
            }
#pragma unroll
            for (int p = 0; p < 4; p++)
                ldx4(bh[p], bHi + (uint32_t)(p * 16 * 128) + co);
#pragma unroll
            for (int mf = 0; mf < 2; mf++)
#pragma unroll
                for (int nf = 0; nf < 8; nf++) {
                    const int p = nf >> 1, o = nf & 1;
                    mma16816(acc[mf][nf], ah[mf], bh[p][o], bh[p][o + 2]);
                    mma16816(acc[mf][nf], al[mf], bh[p][o], bh[p][o + 2]);
                }
        }
        __syncthreads();
    }

    const int qr = lane >> 2, qc = (lane & 3) * 2;
#pragma unroll
    for (int mf = 0; mf < 2; mf++) {
        const int r0 = m0 + wm + mf * 16 + qr;
#pragma unroll
        for (int nf = 0; nf < 8; nf++) {
            const int c = n0 + wn + nf * 8 + qc;
            const float2 bv = *(const float2*)(g.bias + c);
            float o00 = acc[mf][nf][0] + bv.x, o01 = acc[mf][nf][1] + bv.y;
            float o10 = acc[mf][nf][2] + bv.x, o11 = acc[mf][nf][3] + bv.y;
            const size_t off0 = (size_t)r0 * N + c;
            const size_t off1 = off0 + (size_t)8 * N;
            if (g.resid) {
                float2 ra = *(const float2*)(g.resid + off0);
                float2 rb = *(const float2*)(g.resid + off1);
                o00 += ra.x; o01 += ra.y; o10 += rb.x; o11 += rb.y;
            }
            *(float2*)(g.C + off0) = make_float2(o00, o01);
            *(float2*)(g.C + off1) = make_float2(o10, o11);
            if (g.Chi) {
                __half h00 = __float2half(o00), h01 = __float2half(o01);
                __half h10 = __float2half(o10), h11 = __float2half(o11);
                *(__half2*)(g.Chi + off0) = __halves2half2(h00, h01);
                *(__half2*)(g.Chi + off1) = __halves2half2(h10, h11);
                *(__half2*)(g.Clo + off0) = __halves2half2(
                    __float2half(o00 - __half2float(h00)),
                    __float2half(o01 - __half2float(h01)));
                *(__half2*)(g.Clo + off1) = __halves2half2(
                    __float2half(o10 - __half2float(h10)),
                    __float2half(o11 - __half2float(h11)));
            }
        }
    }
}

// ---------------------------------------------------------------------------
// Sliding-window attention: grid (NTOK/QB, HEADS, 2), block 256.
// Smem: Kt[128][82] transposed (+pad col 81 = kb), V[82][128] (+pad row = vb),
// Q[16][128], weights [8][68]. Lanes own window POSITIONS for scores.
// ---------------------------------------------------------------------------
#define QB    16
#define WR    81
#define WC    82
#define PADC  81
#define ATTN_SMEM ((128 * WC + WC * 128 + QB * 128 + 8 * 68) * 4)  // 94336

__global__ __launch_bounds__(256)
void attn_kernel(const float* __restrict__ Q1, const float* __restrict__ K1,
                 const float* __restrict__ V1, const float* __restrict__ kb1,
                 const float* __restrict__ vb1,
                 __half* __restrict__ O1h, __half* __restrict__ O1l,
                 const float* __restrict__ Q2, const float* __restrict__ K2,
                 const float* __restrict__ V2, const float* __restrict__ kb2,
                 const float* __restrict__ vb2,
                 __half* __restrict__ O2h, __half* __restrict__ O2l) {
    extern __shared__ float sm[];
    float* Kt = sm;                      // [128][WC]
    float* Vs = Kt + 128 * WC;           // [WC][128]
    float* Qs = Vs + WC * 128;           // [QB][128]
    float* Ws = Qs + QB * 128;           // [8][68]

    const float *Q, *K, *V, *kb, *vb;
    __half *Oh, *Ol;
    if (blockIdx.z == 0) { Q=Q1; K=K1; V=V1; kb=kb1; vb=vb1; Oh=O1h; Ol=O1l; }
    else                 { Q=Q2; K=K2; V=V2; kb=kb2; vb=vb2; Oh=O2h; Ol=O2l; }

    const int h   = blockIdx.y;
    const int tid = threadIdx.x, wid = tid >> 5, lane = tid & 31;
    const int q0  = blockIdx.x * QB;
    const int base = q0 - HALF;
    const int jmin = max(0, -base);
    const int jmax = min(NTOK - 1, q0 + QB - 1 + HALF + 1) - base;
    const float scale = 0.088388347648318447f;   // 1/sqrt(128)

    for (int idx = tid; idx < WR * 32; idx += 256) {
        const int j = idx >> 5, dg = idx & 31;
        if (j >= jmin && j <= jmax) {
            const size_t go = (size_t)(base + j) * DM + h * DH + dg * 4;
            const float4 kv = *(const float4*)(K + go);
            Kt[(dg * 4 + 0) * WC + j] = kv.x;
            Kt[(dg * 4 + 1) * WC + j] = kv.y;
            Kt[(dg * 4 + 2) * WC + j] = kv.z;
            Kt[(dg * 4 + 3) * WC + j] = kv.w;
            *(float4*)&Vs[j * 128 + dg * 4] = *(const float4*)(V + go);
        }
    }
    if (tid < 32) {
        const float4 kv = *(const float4*)(kb + h * DH + tid * 4);
        Kt[(tid * 4 + 0) * WC + PADC] = kv.x;
        Kt[(tid * 4 + 1) * WC + PADC] = kv.y;
        Kt[(tid * 4 + 2) * WC + PADC] = kv.z;
        Kt[(tid * 4 + 3) * WC + PADC] = kv.w;
        *(float4*)&Vs[PADC * 128 + tid * 4] = *(const float4*)(vb + h * DH + tid * 4);
    }
    for (int idx = tid; idx < QB * 32; idx += 256) {
        const int q = idx >> 5, dg = idx & 31;
        *(float4*)&Qs[q * 128 + dg * 4] =
            *(const float4*)(Q + (size_t)(q0 + q) * DM + h * DH + dg * 4);
    }
    __syncthreads();

    float* wq = Ws + wid * 68;

#pragma unroll
    for (int qq = 0; qq < 2; qq++) {
        const int n   = q0 + wid * 2 + qq;
        const int lo  = max(0, n - HALF);
        const int hi  = min(NTOK - 1, n + HALF + 1);
        const int cnt = hi - lo + 1;
        const int nz  = max(0, WIN - cnt);
        const int jb  = lo - base;
        const int npos = cnt + (nz > 0 ? 1 : 0);

        const float* qp = Qs + (wid * 2 + qq) * 128;

        int colx[3]; bool act[3];
        float s0 = 0.f, s1 = 0.f, s2 = 0.f;
#pragma unroll
        for (int t = 0; t < 3; t++) {
            const int p = lane + 32 * t;
            act[t] = (p < npos);
            colx[t] = !act[t] ? 0 : (p < cnt ? jb + p : PADC);
        }
        const int c0 = colx[0], c1 = colx[1], c2 = colx[2];

#pragma unroll 4
        for (int d4 = 0; d4 < 32; d4++) {
            const float4 q4 = *(const float4*)&qp[d4 * 4];
            const float* kr0 = &Kt[(d4 * 4) * WC];
            s0 += q4.x * kr0[c0]          + q4.y * kr0[WC + c0]
                + q4.z * kr0[2 * WC + c0] + q4.w * kr0[3 * WC + c0];
            s1 += q4.x * kr0[c1]          + q4.y * kr0[WC + c1]
                + q4.z * kr0[2 * WC + c1] + q4.w * kr0[3 * WC + c1];
            s2 += q4.x * kr0[c2]          + q4.y * kr0[WC + c2]
                + q4.z * kr0[2 * WC + c2] + q4.w * kr0[3 * WC + c2];
        }
        s0 = act[0] ? s0 * scale : -INFINITY;
        s1 = act[1] ? s1 * scale : -INFINITY;
        s2 = act[2] ? s2 * scale : -INFINITY;

        float mx = fmaxf(s0, fmaxf(s1, s2));
#pragma unroll
        for (int o = 16; o; o >>= 1) mx = fmaxf(mx, __shfl_xor_sync(0xffffffffu, mx, o));

        float dsum = 0.f;
#pragma unroll
        for (int t = 0; t < 3; t++) {
            const int p = lane + 32 * t;
            const float sv = (t == 0) ? s0 : (t == 1) ? s1 : s2;
            float wv = 0.f;
            if (act[t]) {
                float e = expf(sv - mx);
                wv = (p == cnt) ? (float)nz * e : e;
                wq[p] = wv;
            }
            dsum += wv;
        }
#pragma unroll
        for (int o = 16; o; o >>= 1) dsum += __shfl_xor_sync(0xffffffffu, dsum, o);
        __syncwarp();

        float4 acc = make_float4(0.f, 0.f, 0.f, 0.f);
        for (int p = 0; p < npos; p++) {
            const float w = wq[p];
            const int c = (p < cnt) ? jb + p : PADC;
            const float4 v4 = *(const float4*)&Vs[c * 128 + lane * 4];
            acc.x += w * v4.x; acc.y += w * v4.y;
            acc.z += w * v4.z; acc.w += w * v4.w;
        }
        __syncwarp();

        const float inv = 1.f / dsum;
        const float o0 = acc.x * inv, o1 = acc.y * inv, o2 = acc.z * inv, o3 = acc.w * inv;

        const size_t oo = (size_t)n * DM + h * DH + lane * 4;
        __half h0 = __float2half(o0), h1 = __float2half(o1);
        __half h2 = __float2half(o2), h3 = __float2half(o3);
        __half2* ph = (__half2*)(Oh + oo);
        ph[0] = __halves2half2(h0, h1); ph[1] = __halves2half2(h2, h3);
        __half2* pl = (__half2*)(Ol + oo);
        pl[0] = __halves2half2(__float2half(o0 - __half2float(h0)),
                               __float2half(o1 - __half2float(h1)));
        pl[1] = __halves2half2(__float2half(o2 - __half2float(h2)),
                               __float2half(o3 - __half2float(h3)));
    }
}

// ---------------------------------------------------------------------------
// Launch
// ---------------------------------------------------------------------------
extern "C" void kernel_launch(void* const* d_in, const int* in_sizes, int n_in,
                              void* d_out, int out_size) {
    const float* images    = (const float*)d_in[0];
    const float* capitions = (const float*)d_in[1];
    const float* tp_w  = (const float*)d_in[3];
    const float* tp_b  = (const float*)d_in[4];
    const float* ip_w  = (const float*)d_in[5];
    const float* ip_b  = (const float*)d_in[6];
    const float* ia_qw = (const float*)d_in[7];
    const float* ia_qb = (const float*)d_in[8];
    const float* ia_kw = (const float*)d_in[9];
    const float* ia_kb = (const float*)d_in[10];
    const float* ia_vw = (const float*)d_in[11];
    const float* ia_vb = (const float*)d_in[12];
    const float* ia_ow = (const float*)d_in[13];
    const float* ia_ob = (const float*)d_in[14];
    const float* ta_qw = (const float*)d_in[15];
    const float* ta_qb = (const float*)d_in[16];
    const float* ta_kw = (const float*)d_in[17];
    const float* ta_kb = (const float*)d_in[18];
    const float* ta_vw = (const float*)d_in[19];
    const float* ta_vb = (const float*)d_in[20];
    const float* ta_ow = (const float*)d_in[21];
    const float* ta_ob = (const float*)d_in[22];

    void* fp = nullptr; cudaGetSymbolAddress(&fp, g_f);
    void* bp = nullptr; cudaGetSymbolAddress(&bp, g_hf);
    float* F = (float*)fp;
    __half* B = (__half*)bp;

    float* g_txt = F + 0 * SZ;  float* g_img = F + 1 * SZ;
    float* g_q1  = F + 2 * SZ;  float* g_k1  = F + 3 * SZ;  float* g_v1 = F + 4 * SZ;
    float* g_q2  = F + 5 * SZ;  float* g_k2  = F + 6 * SZ;  float* g_v2 = F + 7 * SZ;

    size_t cur = 0;
    auto take = [&](size_t n) { __half* p = B + cur; cur += n; return p; };
    const size_t WTP = 1024 * 768, W1 = 1024 * 1024;
    __half *tpw_h = take(WTP);
    __half *ipw_h = take(W1);
    __half *iaq_h = take(W1), *iak_h = take(W1), *iav_h = take(W1), *iao_h = take(W1);
    __half *taq_h = take(W1), *tak_h = take(W1), *tav_h = take(W1), *tao_h = take(W1);
    __half *img_h = take(SZ), *img_l = take(SZ);
    __half *cap_h = take(NTOK * 768), *cap_l = take(NTOK * 768);
    __half *txt_h = take(SZ), *txt_l = take(SZ);
    __half *gim_h = take(SZ), *gim_l = take(SZ);
    __half *o1_h  = take(SZ), *o1_l  = take(SZ);
    __half *o2_h  = take(SZ), *o2_l  = take(SZ);

    float* out_img = (float*)d_out;
    float* out_txt = out_img + SZ;

    cudaFuncSetAttribute(gemm_mma, cudaFuncAttributeMaxDynamicSharedMemorySize, GEMM_SMEM);
    cudaFuncSetAttribute(attn_kernel, cudaFuncAttributeMaxDynamicSharedMemorySize, ATTN_SMEM);

    // 0: convert — weights single fp16, activations split fp16
    CBatch cb = {};
    cb.s[0]  = { tp_w,      tpw_h, nullptr, (int)(WTP / 4) };
    cb.s[1]  = { ip_w,      ipw_h, nullptr, (int)(W1 / 4) };
    cb.s[2]  = { ia_qw,     iaq_h, nullptr, (int)(W1 / 4) };
    cb.s[3]  = { ia_kw,     iak_h, nullptr, (int)(W1 / 4) };
    cb.s[4]  = { ia_vw,     iav_h, nullptr, (int)(W1 / 4) };
    cb.s[5]  = { ia_ow,     iao_h, nullptr, (int)(W1 / 4) };
    cb.s[6]  = { ta_qw,     taq_h, nullptr, (int)(W1 / 4) };
    cb.s[7]  = { ta_kw,     tak_h, nullptr, (int)(W1 / 4) };
    cb.s[8]  = { ta_vw,     tav_h, nullptr, (int)(W1 / 4) };
    cb.s[9]  = { ta_ow,     tao_h, nullptr, (int)(W1 / 4) };
    cb.s[10] = { images,    img_h, img_l,   (int)(SZ / 4) };
    cb.s[11] = { capitions, cap_h, cap_l,   (int)(NTOK * 768 / 4) };
    convert_kernel<<<dim3(1024, 12), 256>>>(cb);

    // 1: modality projections (fp32 out + split fp16 out)
    GB b1 = {};
    b1.d[0] = { cap_h, cap_l, tpw_h, tp_b, nullptr, g_txt, txt_h, txt_l, 768 };
    b1.d[1] = { img_h, img_l, ipw_h, ip_b, nullptr, g_img, gim_h, gim_l, 1024 };
    gemm_mma<<<dim3(8, 4, 2), 256, GEMM_SMEM>>>(b1, DM);

    // 2: Q/K/V for both attentions (fp32 out only)
    GB b2 = {};
    b2.d[0] = { gim_h, gim_l, iaq_h, ia_qb, nullptr, g_q1, nullptr, nullptr, 1024 };
    b2.d[1] = { txt_h, txt_l, iak_h, ia_kb, nullptr, g_k1, nullptr, nullptr, 1024 };
    b2.d[2] = { txt_h, txt_l, iav_h, ia_vb, nullptr, g_v1, nullptr, nullptr, 1024 };
    b2.d[3] = { txt_h, txt_l, taq_h, ta_qb, nullptr, g_q2, nullptr, nullptr, 1024 };
    b2.d[4] = { gim_h, gim_l, tak_h, ta_kb, nullptr, g_k2, nullptr, nullptr, 1024 };
    b2.d[5] = { gim_h, gim_l, tav_h, ta_vb, nullptr, g_v2, nullptr, nullptr, 1024 };
    gemm_mma<<<dim3(8, 4, 6), 256, GEMM_SMEM>>>(b2, DM);

    // 3: windowed attention -> split fp16 outputs
    attn_kernel<<<dim3(NTOK / QB, HEADS, 2), 256, ATTN_SMEM>>>(
        g_q1, g_k1, g_v1, ia_kb, ia_vb, o1_h, o1_l,
        g_q2, g_k2, g_v2, ta_kb, ta_vb, o2_h, o2_l);

    // 4: output projections + residual -> d_out
    GB b4 = {};
    b4.d[0] = { o1_h, o1_l, iao_h, ia_ob, g_img, out_img, nullptr, nullptr, 1024 };
    b4.d[1] = { o2_h, o2_l, tao_h, ta_ob, g_txt, out_txt, nullptr, nullptr, 1024 };
    gemm_mma<<<dim3(8, 4, 2), 256, GEMM_SMEM>>>(b4, DM);
}

// round 9
// speedup vs baseline: 2.5656x; 1.0671x over previous
#include <cuda_runtime.h>
#include <cuda_fp16.h>
#include <math.h>
#include <stdint.h>

// ===========================================================================
// CrossModalFusionModel via mma.sync (HMMA fp16) on sm_103 base target.
// GEMMs: fp16 activation hi/lo split, single-fp16 weights, 2 passes:
//   C = Ahi@Whi + Alo@Whi   (residual A@Wlo ~ 2^-12 -> rel err ~1e-4)
//   R6: hi/lo passes issued as separate 16-HMMA independent groups (ILP fix).
// Attention: fp16 K/Q in smem (half2 dim-pairs), HFMA2 scores, fp32 AV.
// ===========================================================================

#define NTOK  512
#define DM    1024
#define HEADS 8
#define DH    128
#define WIN   64
#define HALF  32

// ---------------------------------------------------------------------------
// Low-level helpers
// ---------------------------------------------------------------------------
__device__ __forceinline__ uint32_t s2u(const void* p) {
    uint32_t a;
    asm("{ .reg .u64 t; cvta.to.shared.u64 t, %1; cvt.u32.u64 %0, t; }" : "=r"(a) : "l"(p));
    return a;
}
__device__ __forceinline__ void cp16(uint32_t smem, const void* g) {
    asm volatile("cp.async.cg.shared.global [%0], [%1], 16;" :: "r"(smem), "l"(g));
}
#define CP_COMMIT() asm volatile("cp.async.commit_group;" ::: "memory")
#define CP_WAIT0()  asm volatile("cp.async.wait_group 0;" ::: "memory")
#define CP_WAIT1()  asm volatile("cp.async.wait_group 1;" ::: "memory")

__device__ __forceinline__ void ldx4(uint32_t r[4], uint32_t addr) {
    asm volatile("ldmatrix.sync.aligned.m8n8.x4.shared.b16 {%0,%1,%2,%3}, [%4];"
        : "=r"(r[0]), "=r"(r[1]), "=r"(r[2]), "=r"(r[3]) : "r"(addr));
}
__device__ __forceinline__ void mma16816(float d[4], const uint32_t a[4],
                                         uint32_t b0, uint32_t b1) {
    asm volatile(
        "mma.sync.aligned.m16n8k16.row.col.f32.f16.f16.f32 "
        "{%0,%1,%2,%3}, {%4,%5,%6,%7}, {%8,%9}, {%0,%1,%2,%3};"
        : "+f"(d[0]), "+f"(d[1]), "+f"(d[2]), "+f"(d[3])
        : "r"(a[0]), "r"(a[1]), "r"(a[2]), "r"(a[3]), "r"(b0), "r"(b1));
}

// ---------------------------------------------------------------------------
// Scratch (static __device__ — no allocation)
// ---------------------------------------------------------------------------
#define SZ (NTOK * DM)                 // 524288
__device__ float   g_f[8 * SZ];        // txt,img,q1,k1,v1,q2,k2,v2 (fp32)
__device__ __half  g_hf[26476544];

// ---------------------------------------------------------------------------
// Conversion: fp32 -> fp16 (hi[,lo]), batched segments. lo==nullptr => single.
// ---------------------------------------------------------------------------
struct CSeg { const float* src; __half *hi, *lo; int n4; };
struct CBatch { CSeg s[12]; };

__global__ __launch_bounds__(256)
void convert_kernel(CBatch cb) {
    CSeg s = cb.s[blockIdx.y];
    int i = blockIdx.x * 256 + threadIdx.x;
    if (i >= s.n4) return;
    float4 x = ((const float4*)s.src)[i];
    __half h0 = __float2half(x.x), h1 = __float2half(x.y);
    __half h2 = __float2half(x.z), h3 = __float2half(x.w);
    __half2* ph = (__half2*)(s.hi) + 2 * i;
    ph[0] = __halves2half2(h0, h1); ph[1] = __halves2half2(h2, h3);
    if (s.lo) {
        __half2* pl = (__half2*)(s.lo) + 2 * i;
        pl[0] = __halves2half2(__float2half(x.x - __half2float(h0)),
                               __float2half(x.y - __half2float(h1)));
        pl[1] = __halves2half2(__float2half(x.z - __half2float(h2)),
                               __float2half(x.w - __half2float(h3)));
    }
}

// ---------------------------------------------------------------------------
// mma.sync GEMM: C[M,N] = A[M,K] @ W[N,K]^T (+bias)(+resid), split-fp16 A.
// ---------------------------------------------------------------------------
struct GD {
    const __half *Ahi, *Alo, *Whi;
    const float *bias, *resid;
    float* C;
    __half *Chi, *Clo;
    int K;
};
struct GB { GD d[6]; };

#define TILE_B    16384
#define BUF_B     (3 * TILE_B)
#define GEMM_SMEM (2 * BUF_B)            // 98304 -> 2 CTAs/SM

__device__ __forceinline__ void load_tile(uint32_t sdst, const __half* src,
                                          int row0, int k0, int K, int tid) {
    const char* g = (const char*)(src + (size_t)row0 * K + k0);
    const size_t rstride = (size_t)K * 2;
#pragma unroll
    for (int it = 0; it < 4; it++) {
        int idx = tid + it * 256;
        int r = idx >> 3, f4 = idx & 7;
        cp16(sdst + (uint32_t)(r * 128 + ((f4 * 16) ^ ((r & 7) << 4))),
             g + (size_t)r * rstride + f4 * 16);
    }
}
__device__ __forceinline__ void load3(uint32_t bo, const GD& g,
                                      int m0, int n0, int k0, int tid) {
    load_tile(bo,              g.Ahi, m0, k0, g.K, tid);
    load_tile(bo + TILE_B,     g.Alo, m0, k0, g.K, tid);
    load_tile(bo + 2 * TILE_B, g.Whi, n0, k0, g.K, tid);
}

__global__ __launch_bounds__(256, 2)
void gemm_mma(GB batch, int N) {
    extern __shared__ char smem[];
    const GD g = batch.d[blockIdx.z];
    const uint32_t sb = s2u(smem);
    const int tid = threadIdx.x, wid = tid >> 5, lane = tid & 31;
    const int m0 = blockIdx.y * 128, n0 = blockIdx.x * 128;
    const int wm = (wid & 3) * 32;
    const int wn = (wid >> 2) * 64;

    float acc[2][8][4];
#pragma unroll
    for (int a = 0; a < 2; a++)
#pragma unroll
        for (int b = 0; b < 8; b++)
#pragma unroll
            for (int c = 0; c < 4; c++) acc[a][b][c] = 0.f;

    const int nch = g.K >> 6;
    const int      lrow = lane & 15;
    const uint32_t cgb  = (uint32_t)((lane >> 4) * 16);
    const uint32_t xm   = (uint32_t)((lrow & 7) << 4);

    load3(sb, g, m0, n0, 0, tid);
    CP_COMMIT();

    for (int i = 0; i < nch; i++) {
        if (i + 1 < nch) {
            load3(sb + (uint32_t)(((i + 1) & 1) * BUF_B), g, m0, n0, (i + 1) << 6, tid);
            CP_COMMIT();
            CP_WAIT1();
        } else {
            CP_WAIT0();
        }
        __syncthreads();

        const uint32_t bo = sb + (uint32_t)((i & 1) * BUF_B);
        const uint32_t aHi = bo + (uint32_t)((wm + lrow) * 128);
        const uint32_t aLo = aHi + TILE_B;
        const uint32_t bHi = bo + 2 * TILE_B + (uint32_t)((wn + lrow) * 128);

#pragma unroll
        for (int ks = 0; ks < 4; ks++) {
            const uint32_t co = ((uint32_t)(ks * 32) + cgb) ^ xm;
            uint32_t ah[2][4], al[2][4], bh[4][4];
#pragma unroll
            for (int mf = 0; mf < 2; mf++) {
                ldx4(ah[mf], aHi + (uint32_t)(mf * 16 * 128) + co);
                ldx4(al[mf], aLo + (uint32_t)(mf * 16 * 128) + co);
            }
#pragma unroll
            for (int p = 0; p < 4; p++)
                ldx4(bh[p], bHi + (uint32_t)(p * 16 * 128) + co);
            // Pass 1 (hi): 16 independent HMMA
#pragma unroll
            for (int mf = 0; mf < 2; mf++)
#pragma unroll
                for (int nf = 0; nf < 8; nf++) {
                    const int p = nf >> 1, o = nf & 1;
                    mma16816(acc[mf][nf], ah[mf], bh[p][o], bh[p][o + 2]);
                }
            // Pass 2 (lo): 16 independent HMMA (dep distance to pass 1 = 16)
#pragma unroll
            for (int mf = 0; mf < 2; mf++)
#pragma unroll
                for (int nf = 0; nf < 8; nf++) {
                    const int p = nf >> 1, o = nf & 1;
                    mma16816(acc[mf][nf], al[mf], bh[p][o], bh[p][o + 2]);
                }
        }
        __syncthreads();
    }

    const int qr = lane >> 2, qc = (lane & 3) * 2;
#pragma unroll
    for (int mf = 0; mf < 2; mf++) {
        const int r0 = m0 + wm + mf * 16 + qr;
#pragma unroll
        for (int nf = 0; nf < 8; nf++) {
            const int c = n0 + wn + nf * 8 + qc;
            const float2 bv = *(const float2*)(g.bias + c);
            float o00 = acc[mf][nf][0] + bv.x, o01 = acc[mf][nf][1] + bv.y;
            float o10 = acc[mf][nf][2] + bv.x, o11 = acc[mf][nf][3] + bv.y;
            const size_t off0 = (size_t)r0 * N + c;
            const size_t off1 = off0 + (size_t)8 * N;
            if (g.resid) {
                float2 ra = *(const float2*)(g.resid + off0);
                float2 rb = *(const float2*)(g.resid + off1);
                o00 += ra.x; o01 += ra.y; o10 += rb.x; o11 += rb.y;
            }
            *(float2*)(g.C + off0) = make_float2(o00, o01);
            *(float2*)(g.C + off1) = make_float2(o10, o11);
            if (g.Chi) {
                __half h00 = __float2half(o00), h01 = __float2half(o01);
                __half h10 = __float2half(o10), h11 = __float2half(o11);
                *(__half2*)(g.Chi + off0) = __halves2half2(h00, h01);
                *(__half2*)(g.Chi + off1) = __halves2half2(h10, h11);
                *(__half2*)(g.Clo + off0) = __halves2half2(
                    __float2half(o00 - __half2float(h00)),
                    __float2half(o01 - __half2float(h01)));
                *(__half2*)(g.Clo + off1) = __halves2half2(
                    __float2half(o10 - __half2float(h10)),
                    __float2half(o11 - __half2float(h11)));
            }
        }
    }
}

// ---------------------------------------------------------------------------
// Sliding-window attention v3: grid (NTOK/QB, HEADS, 2), block 256.
// Smem: Ks2 half2[82][65] (K rows as dim-pairs, row 81 = kb),
//       Vs fp32[82][128] (row 81 = vb), Qs2 half2[16][65], Ws[8][88].
// Lane owns window cols {lane, lane+32, min(lane+64,81)}; HFMA2 scores,
// per-query mask -> exp -> weights in smem -> fp32 AV.
// ---------------------------------------------------------------------------
#define QB    16
#define WR    81                      // real window rows 0..80
#define PADC  81                      // pad row/col index
#define KROW  65                      // half2 words per K/Q row (64 + 1 pad)
#define OFF_KS   0
#define OFF_VS   21328                // 82*65*4 = 21320, aligned to 16
#define OFF_QS   (OFF_VS + 82*128*4)  // 63312
#define OFF_WS   (OFF_QS + 16*KROW*4) // 67472
#define ATTN_SMEM (OFF_WS + 8*88*4 + 16)   // 70304

__global__ __launch_bounds__(256)
void attn_kernel(const float* __restrict__ Q1, const float* __restrict__ K1,
                 const float* __restrict__ V1, const float* __restrict__ kb1,
                 const float* __restrict__ vb1,
                 __half* __restrict__ O1h, __half* __restrict__ O1l,
                 const float* __restrict__ Q2, const float* __restrict__ K2,
                 const float* __restrict__ V2, const float* __restrict__ kb2,
                 const float* __restrict__ vb2,
                 __half* __restrict__ O2h, __half* __restrict__ O2l) {
    extern __shared__ char smraw[];
    __half2* Ks2 = (__half2*)(smraw + OFF_KS);    // [82][65]
    float*   Vs  = (float*)(smraw + OFF_VS);      // [82][128]
    __half2* Qs2 = (__half2*)(smraw + OFF_QS);    // [16][65]
    float*   Ws  = (float*)(smraw + OFF_WS);      // [8][88]

    const float *Q, *K, *V, *kb, *vb;
    __half *Oh, *Ol;
    if (blockIdx.z == 0) { Q=Q1; K=K1; V=V1; kb=kb1; vb=vb1; Oh=O1h; Ol=O1l; }
    else                 { Q=Q2; K=K2; V=V2; kb=kb2; vb=vb2; Oh=O2h; Ol=O2l; }

    const int h   = blockIdx.y;
    const int tid = threadIdx.x, wid = tid >> 5, lane = tid & 31;
    const int q0  = blockIdx.x * QB;
    const int base = q0 - HALF;
    const int jmin = max(0, -base);
    const int jmax = min(NTOK - 1, q0 + QB - 1 + HALF + 1) - base;
    const float scale = 0.088388347648318447f;

    // ---- load K (fp16 dim-pairs), V (fp32), pad row, Q (fp16) ----
    for (int idx = tid; idx < WR * 32; idx += 256) {
        const int j = idx >> 5, dg = idx & 31;
        if (j >= jmin && j <= jmax) {
            const size_t go = (size_t)(base + j) * DM + h * DH + dg * 4;
            const float4 kv = *(const float4*)(K + go);
            Ks2[j * KROW + dg * 2 + 0] = __floats2half2_rn(kv.x, kv.y);
            Ks2[j * KROW + dg * 2 + 1] = __floats2half2_rn(kv.z, kv.w);
            *(float4*)&Vs[j * 128 + dg * 4] = *(const float4*)(V + go);
        }
    }
    if (tid < 32) {
        const float4 kv = *(const float4*)(kb + h * DH + tid * 4);
        Ks2[PADC * KROW + tid * 2 + 0] = __floats2half2_rn(kv.x, kv.y);
        Ks2[PADC * KROW + tid * 2 + 1] = __floats2half2_rn(kv.z, kv.w);
        *(float4*)&Vs[PADC * 128 + tid * 4] = *(const float4*)(vb + h * DH + tid * 4);
    }
    for (int idx = tid; idx < QB * 32; idx += 256) {
        const int q = idx >> 5, dg = idx & 31;
        const float4 qv = *(const float4*)(Q + (size_t)(q0 + q) * DM + h * DH + dg * 4);
        Qs2[q * KROW + dg * 2 + 0] = __floats2half2_rn(qv.x, qv.y);
        Qs2[q * KROW + dg * 2 + 1] = __floats2half2_rn(qv.z, qv.w);
    }
    __syncthreads();

    float* wq = Ws + wid * 88;

#pragma unroll
    for (int qq = 0; qq < 2; qq++) {
        const int qi  = wid * 2 + qq;
        const int n   = q0 + qi;
        const int lo  = max(0, n - HALF);
        const int hi  = min(NTOK - 1, n + HALF + 1);
        const int cnt = hi - lo + 1;
        const int nz  = max(0, WIN - cnt);
        const int jb  = lo - base;

        const __half2* qp = Qs2 + qi * KROW;
        const int j0 = lane, j1 = lane + 32, j2 = lane + 64;
        const __half2* k0 = Ks2 + j0 * KROW;
        const __half2* k1 = Ks2 + j1 * KROW;
        const __half2* k2 = Ks2 + min(j2, PADC) * KROW;

        __half2 a0 = __floats2half2_rn(0.f, 0.f);
        __half2 a1 = a0, a2 = a0;
#pragma unroll 8
        for (int d2 = 0; d2 < 64; d2++) {
            const __half2 q2 = qp[d2];
            a0 = __hfma2(q2, k0[d2], a0);
            a1 = __hfma2(q2, k1[d2], a1);
            a2 = __hfma2(q2, k2[d2], a2);
        }
        float s0 = __low2float(a0) + __high2float(a0);
        float s1 = __low2float(a1) + __high2float(a1);
        float s2 = __low2float(a2) + __high2float(a2);

        const bool v0 = (j0 >= jb) && (j0 < jb + cnt);
        const bool v1 = (j1 >= jb) && (j1 < jb + cnt);
        const bool v2 = ((j2 >= jb) && (j2 < jb + cnt)) || (j2 == PADC);
        s0 = v0 ? s0 * scale : -INFINITY;
        s1 = v1 ? s1 * scale : -INFINITY;
        s2 = v2 ? s2 * scale : -INFINITY;

        float mx = fmaxf(s0, fmaxf(s1, s2));
#pragma unroll
        for (int o = 16; o; o >>= 1) mx = fmaxf(mx, __shfl_xor_sync(0xffffffffu, mx, o));

        float w0 = v0 ? expf(s0 - mx) : 0.f;
        float w1 = v1 ? expf(s1 - mx) : 0.f;
        float w2 = v2 ? expf(s2 - mx) : 0.f;
        if (j2 == PADC) w2 *= (float)nz;

        float dsum = w0 + w1 + w2;
#pragma unroll
        for (int o = 16; o; o >>= 1) dsum += __shfl_xor_sync(0xffffffffu, dsum, o);

        wq[j0] = w0;
        wq[j1] = w1;
        if (j2 <= PADC) wq[j2] = w2;
        __syncwarp();

        // AV (fp32): lane owns dims lane*4..+3
        float4 acc = make_float4(0.f, 0.f, 0.f, 0.f);
        for (int p = 0; p < cnt; p++) {
            const int j = jb + p;
            const float w = wq[j];
            const float4 v4 = *(const float4*)&Vs[j * 128 + lane * 4];
            acc.x += w * v4.x; acc.y += w * v4.y;
            acc.z += w * v4.z; acc.w += w * v4.w;
        }
        {
            const float w = wq[PADC];
            const float4 v4 = *(const float4*)&Vs[PADC * 128 + lane * 4];
            acc.x += w * v4.x; acc.y += w * v4.y;
            acc.z += w * v4.z; acc.w += w * v4.w;
        }
        __syncwarp();

        const float inv = 1.f / dsum;
        const float o0 = acc.x * inv, o1 = acc.y * inv, o2 = acc.z * inv, o3 = acc.w * inv;

        const size_t oo = (size_t)n * DM + h * DH + lane * 4;
        __half h0 = __float2half(o0), h1 = __float2half(o1);
        __half h2 = __float2half(o2), h3 = __float2half(o3);
        __half2* ph = (__half2*)(Oh + oo);
        ph[0] = __halves2half2(h0, h1); ph[1] = __halves2half2(h2, h3);
        __half2* pl = (__half2*)(Ol + oo);
        pl[0] = __halves2half2(__float2half(o0 - __half2float(h0)),
                               __float2half(o1 - __half2float(h1)));
        pl[1] = __halves2half2(__float2half(o2 - __half2float(h2)),
                               __float2half(o3 - __half2float(h3)));
    }
}

// ---------------------------------------------------------------------------
// Launch
// ---------------------------------------------------------------------------
extern "C" void kernel_launch(void* const* d_in, const int* in_sizes, int n_in,
                              void* d_out, int out_size) {
    const float* images    = (const float*)d_in[0];
    const float* capitions = (const float*)d_in[1];
    const float* tp_w  = (const float*)d_in[3];
    const float* tp_b  = (const float*)d_in[4];
    const float* ip_w  = (const float*)d_in[5];
    const float* ip_b  = (const float*)d_in[6];
    const float* ia_qw = (const float*)d_in[7];
    const float* ia_qb = (const float*)d_in[8];
    const float* ia_kw = (const float*)d_in[9];
    const float* ia_kb = (const float*)d_in[10];
    const float* ia_vw = (const float*)d_in[11];
    const float* ia_vb = (const float*)d_in[12];
    const float* ia_ow = (const float*)d_in[13];
    const float* ia_ob = (const float*)d_in[14];
    const float* ta_qw = (const float*)d_in[15];
    const float* ta_qb = (const float*)d_in[16];
    const float* ta_kw = (const float*)d_in[17];
    const float* ta_kb = (const float*)d_in[18];
    const float* ta_vw = (const float*)d_in[19];
    const float* ta_vb = (const float*)d_in[20];
    const float* ta_ow = (const float*)d_in[21];
    const float* ta_ob = (const float*)d_in[22];

    void* fp = nullptr; cudaGetSymbolAddress(&fp, g_f);
    void* bp = nullptr; cudaGetSymbolAddress(&bp, g_hf);
    float* F = (float*)fp;
    __half* B = (__half*)bp;

    float* g_txt = F + 0 * SZ;  float* g_img = F + 1 * SZ;
    float* g_q1  = F + 2 * SZ;  float* g_k1  = F + 3 * SZ;  float* g_v1 = F + 4 * SZ;
    float* g_q2  = F + 5 * SZ;  float* g_k2  = F + 6 * SZ;  float* g_v2 = F + 7 * SZ;

    size_t cur = 0;
    auto take = [&](size_t n) { __half* p = B + cur; cur += n; return p; };
    const size_t WTP = 1024 * 768, W1 = 1024 * 1024;
    __half *tpw_h = take(WTP);
    __half *ipw_h = take(W1);
    __half *iaq_h = take(W1), *iak_h = take(W1), *iav_h = take(W1), *iao_h = take(W1);
    __half *taq_h = take(W1), *tak_h = take(W1), *tav_h = take(W1), *tao_h = take(W1);
    __half *img_h = take(SZ), *img_l = take(SZ);
    __half *cap_h = take(NTOK * 768), *cap_l = take(NTOK * 768);
    __half *txt_h = take(SZ), *txt_l = take(SZ);
    __half *gim_h = take(SZ), *gim_l = take(SZ);
    __half *o1_h  = take(SZ), *o1_l  = take(SZ);
    __half *o2_h  = take(SZ), *o2_l  = take(SZ);

    float* out_img = (float*)d_out;
    float* out_txt = out_img + SZ;

    cudaFuncSetAttribute(gemm_mma, cudaFuncAttributeMaxDynamicSharedMemorySize, GEMM_SMEM);
    cudaFuncSetAttribute(attn_kernel, cudaFuncAttributeMaxDynamicSharedMemorySize, ATTN_SMEM);

    // 0: convert — weights single fp16, activations split fp16
    CBatch cb = {};
    cb.s[0]  = { tp_w,      tpw_h, nullptr, (int)(WTP / 4) };
    cb.s[1]  = { ip_w,      ipw_h, nullptr, (int)(W1 / 4) };
    cb.s[2]  = { ia_qw,     iaq_h, nullptr, (int)(W1 / 4) };
    cb.s[3]  = { ia_kw,     iak_h, nullptr, (int)(W1 / 4) };
    cb.s[4]  = { ia_vw,     iav_h, nullptr, (int)(W1 / 4) };
    cb.s[5]  = { ia_ow,     iao_h, nullptr, (int)(W1 / 4) };
    cb.s[6]  = { ta_qw,     taq_h, nullptr, (int)(W1 / 4) };
    cb.s[7]  = { ta_kw,     tak_h, nullptr, (int)(W1 / 4) };
    cb.s[8]  = { ta_vw,     tav_h, nullptr, (int)(W1 / 4) };
    cb.s[9]  = { ta_ow,     tao_h, nullptr, (int)(W1 / 4) };
    cb.s[10] = { images,    img_h, img_l,   (int)(SZ / 4) };
    cb.s[11] = { capitions, cap_h, cap_l,   (int)(NTOK * 768 / 4) };
    convert_kernel<<<dim3(1024, 12), 256>>>(cb);

    // 1: modality projections (fp32 out + split fp16 out)
    GB b1 = {};
    b1.d[0] = { cap_h, cap_l, tpw_h, tp_b, nullptr, g_txt, txt_h, txt_l, 768 };
    b1.d[1] = { img_h, img_l, ipw_h, ip_b, nullptr, g_img, gim_h, gim_l, 1024 };
    gemm_mma<<<dim3(8, 4, 2), 256, GEMM_SMEM>>>(b1, DM);

    // 2: Q/K/V for both attentions (fp32 out only)
    GB b2 = {};
    b2.d[0] = { gim_h, gim_l, iaq_h, ia_qb, nullptr, g_q1, nullptr, nullptr, 1024 };
    b2.d[1] = { txt_h, txt_l, iak_h, ia_kb, nullptr, g_k1, nullptr, nullptr, 1024 };
    b2.d[2] = { txt_h, txt_l, iav_h, ia_vb, nullptr, g_v1, nullptr, nullptr, 1024 };
    b2.d[3] = { txt_h, txt_l, taq_h, ta_qb, nullptr, g_q2, nullptr, nullptr, 1024 };
    b2.d[4] = { gim_h, gim_l, tak_h, ta_kb, nullptr, g_k2, nullptr, nullptr, 1024 };
    b2.d[5] = { gim_h, gim_l, tav_h, ta_vb, nullptr, g_v2, nullptr, nullptr, 1024 };
    gemm_mma<<<dim3(8, 4, 6), 256, GEMM_SMEM>>>(b2, DM);

    // 3: windowed attention -> split fp16 outputs
    attn_kernel<<<dim3(NTOK / QB, HEADS, 2), 256, ATTN_SMEM>>>(
        g_q1, g_k1, g_v1, ia_kb, ia_vb, o1_h, o1_l,
        g_q2, g_k2, g_v2, ta_kb, ta_vb, o2_h, o2_l);

    // 4: output projections + residual -> d_out
    GB b4 = {};
    b4.d[0] = { o1_h, o1_l, iao_h, ia_ob, g_img, out_img, nullptr, nullptr, 1024 };
    b4.d[1] = { o2_h, o2_l, tao_h, ta_ob, g_txt, out_txt, nullptr, nullptr, 1024 };
    gemm_mma<<<dim3(8, 4, 2), 256, GEMM_SMEM>>>(b4, DM);
}

// round 10
// speedup vs baseline: 3.2110x; 1.2516x over previous
#include <cuda_runtime.h>
#include <cuda_fp16.h>
#include <math.h>
#include <stdint.h>

// ===========================================================================
// CrossModalFusionModel via mma.sync (HMMA fp16) on sm_103 base target.
// Stage 1 (modality proj): 2-pass split-fp16 (feeds residual -> accuracy).
// Stage 2 (QKV) & stage 4 (o-proj): single-pass fp16 (error attenuated by
// softmax flatness + small attention contribution vs residual).
// Attention: fp16 K/Q smem HFMA2 scores, fp32 AV.
// ===========================================================================

#define NTOK  512
#define DM    1024
#define HEADS 8
#define DH    128
#define WIN   64
#define HALF  32

__device__ __forceinline__ uint32_t s2u(const void* p) {
    uint32_t a;
    asm("{ .reg .u64 t; cvta.to.shared.u64 t, %1; cvt.u32.u64 %0, t; }" : "=r"(a) : "l"(p));
    return a;
}
__device__ __forceinline__ void cp16(uint32_t smem, const void* g) {
    asm volatile("cp.async.cg.shared.global [%0], [%1], 16;" :: "r"(smem), "l"(g));
}
#define CP_COMMIT() asm volatile("cp.async.commit_group;" ::: "memory")
#define CP_WAIT0()  asm volatile("cp.async.wait_group 0;" ::: "memory")
#define CP_WAIT1()  asm volatile("cp.async.wait_group 1;" ::: "memory")

__device__ __forceinline__ void ldx4(uint32_t r[4], uint32_t addr) {
    asm volatile("ldmatrix.sync.aligned.m8n8.x4.shared.b16 {%0,%1,%2,%3}, [%4];"
        : "=r"(r[0]), "=r"(r[1]), "=r"(r[2]), "=r"(r[3]) : "r"(addr));
}
__device__ __forceinline__ void mma16816(float d[4], const uint32_t a[4],
                                         uint32_t b0, uint32_t b1) {
    asm volatile(
        "mma.sync.aligned.m16n8k16.row.col.f32.f16.f16.f32 "
        "{%0,%1,%2,%3}, {%4,%5,%6,%7}, {%8,%9}, {%0,%1,%2,%3};"
        : "+f"(d[0]), "+f"(d[1]), "+f"(d[2]), "+f"(d[3])
        : "r"(a[0]), "r"(a[1]), "r"(a[2]), "r"(a[3]), "r"(b0), "r"(b1));
}

#define SZ (NTOK * DM)
__device__ float   g_f[8 * SZ];
__device__ __half  g_hf[26476544];

// ---------------------------------------------------------------------------
// Conversion: fp32 -> fp16 (hi[,lo])
// ---------------------------------------------------------------------------
struct CSeg { const float* src; __half *hi, *lo; int n4; };
struct CBatch { CSeg s[12]; };

__global__ __launch_bounds__(256)
void convert_kernel(CBatch cb) {
    CSeg s = cb.s[blockIdx.y];
    int i = blockIdx.x * 256 + threadIdx.x;
    if (i >= s.n4) return;
    float4 x = ((const float4*)s.src)[i];
    __half h0 = __float2half(x.x), h1 = __float2half(x.y);
    __half h2 = __float2half(x.z), h3 = __float2half(x.w);
    __half2* ph = (__half2*)(s.hi) + 2 * i;
    ph[0] = __halves2half2(h0, h1); ph[1] = __halves2half2(h2, h3);
    if (s.lo) {
        __half2* pl = (__half2*)(s.lo) + 2 * i;
        pl[0] = __halves2half2(__float2half(x.x - __half2float(h0)),
                               __float2half(x.y - __half2float(h1)));
        pl[1] = __halves2half2(__float2half(x.z - __half2float(h2)),
                               __float2half(x.w - __half2float(h3)));
    }
}

// ---------------------------------------------------------------------------
// mma.sync GEMM. SPLIT=true: C = Ahi@W + Alo@W; SPLIT=false: C = Ahi@W.
// ---------------------------------------------------------------------------
struct GD {
    const __half *Ahi, *Alo, *Whi;
    const float *bias, *resid;
    float* C;
    __half *Chi, *Clo;
    int K;
};
struct GB { GD d[6]; };

#define TILE_B    16384
#define GEMM_SMEM_S (6 * TILE_B)   // split: (A,Alo,W) x2 buffers = 98304
#define GEMM_SMEM_1 (4 * TILE_B)   // single: (A,W) x2 buffers = 65536

__device__ __forceinline__ void load_tile(uint32_t sdst, const __half* src,
                                          int row0, int k0, int K, int tid) {
    const char* g = (const char*)(src + (size_t)row0 * K + k0);
    const size_t rstride = (size_t)K * 2;
#pragma unroll
    for (int it = 0; it < 4; it++) {
        int idx = tid + it * 256;
        int r = idx >> 3, f4 = idx & 7;
        cp16(sdst + (uint32_t)(r * 128 + ((f4 * 16) ^ ((r & 7) << 4))),
             g + (size_t)r * rstride + f4 * 16);
    }
}

template<bool SPLIT>
__global__ __launch_bounds__(256, 2)
void gemm_mma(GB batch, int N) {
    extern __shared__ char smem[];
    const GD g = batch.d[blockIdx.z];
    const uint32_t sb = s2u(smem);
    const int tid = threadIdx.x, wid = tid >> 5, lane = tid & 31;
    const int m0 = blockIdx.y * 128, n0 = blockIdx.x * 128;
    const int wm = (wid & 3) * 32;
    const int wn = (wid >> 2) * 64;
    constexpr uint32_t TPB   = SPLIT ? 3 : 2;          // tiles per buffer
    constexpr uint32_t BUF_B = TPB * TILE_B;
    constexpr uint32_t WOFF  = (TPB - 1) * TILE_B;     // W tile offset

    float acc[2][8][4];
#pragma unroll
    for (int a = 0; a < 2; a++)
#pragma unroll
        for (int b = 0; b < 8; b++)
#pragma unroll
            for (int c = 0; c < 4; c++) acc[a][b][c] = 0.f;

    const int nch = g.K >> 6;
    const int      lrow = lane & 15;
    const uint32_t cgb  = (uint32_t)((lane >> 4) * 16);
    const uint32_t xm   = (uint32_t)((lrow & 7) << 4);

    auto loadbuf = [&](uint32_t bo, int k0) {
        load_tile(bo, g.Ahi, m0, k0, g.K, tid);
        if (SPLIT) load_tile(bo + TILE_B, g.Alo, m0, k0, g.K, tid);
        load_tile(bo + WOFF, g.Whi, n0, k0, g.K, tid);
    };

    loadbuf(sb, 0);
    CP_COMMIT();

    for (int i = 0; i < nch; i++) {
        if (i + 1 < nch) {
            loadbuf(sb + (uint32_t)(((i + 1) & 1) * BUF_B), (i + 1) << 6);
            CP_COMMIT();
            CP_WAIT1();
        } else {
            CP_WAIT0();
        }
        __syncthreads();

        const uint32_t bo = sb + (uint32_t)((i & 1) * BUF_B);
        const uint32_t aHi = bo + (uint32_t)((wm + lrow) * 128);
        const uint32_t bHi = bo + WOFF + (uint32_t)((wn + lrow) * 128);

#pragma unroll
        for (int ks = 0; ks < 4; ks++) {
            const uint32_t co = ((uint32_t)(ks * 32) + cgb) ^ xm;
            uint32_t ah[2][4], bh[4][4];
#pragma unroll
            for (int mf = 0; mf < 2; mf++)
                ldx4(ah[mf], aHi + (uint32_t)(mf * 16 * 128) + co);
#pragma unroll
            for (int p = 0; p < 4; p++)
                ldx4(bh[p], bHi + (uint32_t)(p * 16 * 128) + co);
#pragma unroll
            for (int mf = 0; mf < 2; mf++)
#pragma unroll
                for (int nf = 0; nf < 8; nf++) {
                    const int p = nf >> 1, o = nf & 1;
                    mma16816(acc[mf][nf], ah[mf], bh[p][o], bh[p][o + 2]);
                }
            if (SPLIT) {
                uint32_t al[2][4];
                const uint32_t aLo = aHi + TILE_B;
#pragma unroll
                for (int mf = 0; mf < 2; mf++)
                    ldx4(al[mf], aLo + (uint32_t)(mf * 16 * 128) + co);
#pragma unroll
                for (int mf = 0; mf < 2; mf++)
#pragma unroll
                    for (int nf = 0; nf < 8; nf++) {
                        const int p = nf >> 1, o = nf & 1;
                        mma16816(acc[mf][nf], al[mf], bh[p][o], bh[p][o + 2]);
                    }
            }
        }
        __syncthreads();
    }

    const int qr = lane >> 2, qc = (lane & 3) * 2;
#pragma unroll
    for (int mf = 0; mf < 2; mf++) {
        const int r0 = m0 + wm + mf * 16 + qr;
#pragma unroll
        for (int nf = 0; nf < 8; nf++) {
            const int c = n0 + wn + nf * 8 + qc;
            const float2 bv = *(const float2*)(g.bias + c);
            float o00 = acc[mf][nf][0] + bv.x, o01 = acc[mf][nf][1] + bv.y;
            float o10 = acc[mf][nf][2] + bv.x, o11 = acc[mf][nf][3] + bv.y;
            const size_t off0 = (size_t)r0 * N + c;
            const size_t off1 = off0 + (size_t)8 * N;
            if (g.resid) {
                float2 ra = *(const float2*)(g.resid + off0);
                float2 rb = *(const float2*)(g.resid + off1);
                o00 += ra.x; o01 += ra.y; o10 += rb.x; o11 += rb.y;
            }
            *(float2*)(g.C + off0) = make_float2(o00, o01);
            *(float2*)(g.C + off1) = make_float2(o10, o11);
            if (g.Chi) {
                __half h00 = __float2half(o00), h01 = __float2half(o01);
                __half h10 = __float2half(o10), h11 = __float2half(o11);
                *(__half2*)(g.Chi + off0) = __halves2half2(h00, h01);
                *(__half2*)(g.Chi + off1) = __halves2half2(h10, h11);
                *(__half2*)(g.Clo + off0) = __halves2half2(
                    __float2half(o00 - __half2float(h00)),
                    __float2half(o01 - __half2float(h01)));
                *(__half2*)(g.Clo + off1) = __halves2half2(
                    __float2half(o10 - __half2float(h10)),
                    __float2half(o11 - __half2float(h11)));
            }
        }
    }
}

// ---------------------------------------------------------------------------
// Sliding-window attention: grid (NTOK/QB, HEADS, 2), block 256.
// Output: single fp16 (feeds single-pass stage-4 GEMM).
// ---------------------------------------------------------------------------
#define QB    16
#define WR    81
#define PADC  81
#define KROW  65
#define OFF_KS   0
#define OFF_VS   21328
#define OFF_QS   (OFF_VS + 82*128*4)
#define OFF_WS   (OFF_QS + 16*KROW*4)
#define ATTN_SMEM (OFF_WS + 8*88*4 + 16)

__global__ __launch_bounds__(256)
void attn_kernel(const float* __restrict__ Q1, const float* __restrict__ K1,
                 const float* __restrict__ V1, const float* __restrict__ kb1,
                 const float* __restrict__ vb1, __half* __restrict__ O1h,
                 const float* __restrict__ Q2, const float* __restrict__ K2,
                 const float* __restrict__ V2, const float* __restrict__ kb2,
                 const float* __restrict__ vb2, __half* __restrict__ O2h) {
    extern __shared__ char smraw[];
    __half2* Ks2 = (__half2*)(smraw + OFF_KS);
    float*   Vs  = (float*)(smraw + OFF_VS);
    __half2* Qs2 = (__half2*)(smraw + OFF_QS);
    float*   Ws  = (float*)(smraw + OFF_WS);

    const float *Q, *K, *V, *kb, *vb;
    __half *Oh;
    if (blockIdx.z == 0) { Q=Q1; K=K1; V=V1; kb=kb1; vb=vb1; Oh=O1h; }
    else                 { Q=Q2; K=K2; V=V2; kb=kb2; vb=vb2; Oh=O2h; }

    const int h   = blockIdx.y;
    const int tid = threadIdx.x, wid = tid >> 5, lane = tid & 31;
    const int q0  = blockIdx.x * QB;
    const int base = q0 - HALF;
    const int jmin = max(0, -base);
    const int jmax = min(NTOK - 1, q0 + QB - 1 + HALF + 1) - base;
    const float scale = 0.088388347648318447f;

    for (int idx = tid; idx < WR * 32; idx += 256) {
        const int j = idx >> 5, dg = idx & 31;
        if (j >= jmin && j <= jmax) {
            const size_t go = (size_t)(base + j) * DM + h * DH + dg * 4;
            const float4 kv = *(const float4*)(K + go);
            Ks2[j * KROW + dg * 2 + 0] = __floats2half2_rn(kv.x, kv.y);
            Ks2[j * KROW + dg * 2 + 1] = __floats2half2_rn(kv.z, kv.w);
            *(float4*)&Vs[j * 128 + dg * 4] = *(const float4*)(V + go);
        }
    }
    if (tid < 32) {
        const float4 kv = *(const float4*)(kb + h * DH + tid * 4);
        Ks2[PADC * KROW + tid * 2 + 0] = __floats2half2_rn(kv.x, kv.y);
        Ks2[PADC * KROW + tid * 2 + 1] = __floats2half2_rn(kv.z, kv.w);
        *(float4*)&Vs[PADC * 128 + tid * 4] = *(const float4*)(vb + h * DH + tid * 4);
    }
    for (int idx = tid; idx < QB * 32; idx += 256) {
        const int q = idx >> 5, dg = idx & 31;
        const float4 qv = *(const float4*)(Q + (size_t)(q0 + q) * DM + h * DH + dg * 4);
        Qs2[q * KROW + dg * 2 + 0] = __floats2half2_rn(qv.x, qv.y);
        Qs2[q * KROW + dg * 2 + 1] = __floats2half2_rn(qv.z, qv.w);
    }
    __syncthreads();

    float* wq = Ws + wid * 88;

#pragma unroll
    for (int qq = 0; qq < 2; qq++) {
        const int qi  = wid * 2 + qq;
        const int n   = q0 + qi;
        const int lo  = max(0, n - HALF);
        const int hi  = min(NTOK - 1, n + HALF + 1);
        const int cnt = hi - lo + 1;
        const int nz  = max(0, WIN - cnt);
        const int jb  = lo - base;

        const __half2* qp = Qs2 + qi * KROW;
        const int j0 = lane, j1 = lane + 32, j2 = lane + 64;
        const __half2* k0 = Ks2 + j0 * KROW;
        const __half2* k1 = Ks2 + j1 * KROW;
        const __half2* k2 = Ks2 + min(j2, PADC) * KROW;

        __half2 a0 = __floats2half2_rn(0.f, 0.f);
        __half2 a1 = a0, a2 = a0;
#pragma unroll 8
        for (int d2 = 0; d2 < 64; d2++) {
            const __half2 q2 = qp[d2];
            a0 = __hfma2(q2, k0[d2], a0);
            a1 = __hfma2(q2, k1[d2], a1);
            a2 = __hfma2(q2, k2[d2], a2);
        }
        float s0 = __low2float(a0) + __high2float(a0);
        float s1 = __low2float(a1) + __high2float(a1);
        float s2 = __low2float(a2) + __high2float(a2);

        const bool v0 = (j0 >= jb) && (j0 < jb + cnt);
        const bool v1 = (j1 >= jb) && (j1 < jb + cnt);
        const bool v2 = ((j2 >= jb) && (j2 < jb + cnt)) || (j2 == PADC);
        s0 = v0 ? s0 * scale : -INFINITY;
        s1 = v1 ? s1 * scale : -INFINITY;
        s2 = v2 ? s2 * scale : -INFINITY;

        float mx = fmaxf(s0, fmaxf(s1, s2));
#pragma unroll
        for (int o = 16; o; o >>= 1) mx = fmaxf(mx, __shfl_xor_sync(0xffffffffu, mx, o));

        float w0 = v0 ? expf(s0 - mx) : 0.f;
        float w1 = v1 ? expf(s1 - mx) : 0.f;
        float w2 = v2 ? expf(s2 - mx) : 0.f;
        if (j2 == PADC) w2 *= (float)nz;

        float dsum = w0 + w1 + w2;
#pragma unroll
        for (int o = 16; o; o >>= 1) dsum += __shfl_xor_sync(0xffffffffu, dsum, o);

        wq[j0] = w0;
        wq[j1] = w1;
        if (j2 <= PADC) wq[j2] = w2;
        __syncwarp();

        float4 acc = make_float4(0.f, 0.f, 0.f, 0.f);
        for (int p = 0; p < cnt; p++) {
            const int j = jb + p;
            const float w = wq[j];
            const float4 v4 = *(const float4*)&Vs[j * 128 + lane * 4];
            acc.x += w * v4.x; acc.y += w * v4.y;
            acc.z += w * v4.z; acc.w += w * v4.w;
        }
        {
            const float w = wq[PADC];
            const float4 v4 = *(const float4*)&Vs[PADC * 128 + lane * 4];
            acc.x += w * v4.x; acc.y += w * v4.y;
            acc.z += w * v4.z; acc.w += w * v4.w;
        }
        __syncwarp();

        const float inv = 1.f / dsum;
        const size_t oo = (size_t)n * DM + h * DH + lane * 4;
        __half2* ph = (__half2*)(Oh + oo);
        ph[0] = __halves2half2(__float2half(acc.x * inv), __float2half(acc.y * inv));
        ph[1] = __halves2half2(__float2half(acc.z * inv), __float2half(acc.w * inv));
    }
}

// ---------------------------------------------------------------------------
// Launch
// ---------------------------------------------------------------------------
extern "C" void kernel_launch(void* const* d_in, const int* in_sizes, int n_in,
                              void* d_out, int out_size) {
    const float* images    = (const float*)d_in[0];
    const float* capitions = (const float*)d_in[1];
    const float* tp_w  = (const float*)d_in[3];
    const float* tp_b  = (const float*)d_in[4];
    const float* ip_w  = (const float*)d_in[5];
    const float* ip_b  = (const float*)d_in[6];
    const float* ia_qw = (const float*)d_in[7];
    const float* ia_qb = (const float*)d_in[8];
    const float* ia_kw = (const float*)d_in[9];
    const float* ia_kb = (const float*)d_in[10];
    const float* ia_vw = (const float*)d_in[11];
    const float* ia_vb = (const float*)d_in[12];
    const float* ia_ow = (const float*)d_in[13];
    const float* ia_ob = (const float*)d_in[14];
    const float* ta_qw = (const float*)d_in[15];
    const float* ta_qb = (const float*)d_in[16];
    const float* ta_kw = (const float*)d_in[17];
    const float* ta_kb = (const float*)d_in[18];
    const float* ta_vw = (const float*)d_in[19];
    const float* ta_vb = (const float*)d_in[20];
    const float* ta_ow = (const float*)d_in[21];
    const float* ta_ob = (const float*)d_in[22];

    void* fp = nullptr; cudaGetSymbolAddress(&fp, g_f);
    void* bp = nullptr; cudaGetSymbolAddress(&bp, g_hf);
    float* F = (float*)fp;
    __half* B = (__half*)bp;

    float* g_txt = F + 0 * SZ;  float* g_img = F + 1 * SZ;
    float* g_q1  = F + 2 * SZ;  float* g_k1  = F + 3 * SZ;  float* g_v1 = F + 4 * SZ;
    float* g_q2  = F + 5 * SZ;  float* g_k2  = F + 6 * SZ;  float* g_v2 = F + 7 * SZ;

    size_t cur = 0;
    auto take = [&](size_t n) { __half* p = B + cur; cur += n; return p; };
    const size_t WTP = 1024 * 768, W1 = 1024 * 1024;
    __half *tpw_h = take(WTP);
    __half *ipw_h = take(W1);
    __half *iaq_h = take(W1), *iak_h = take(W1), *iav_h = take(W1), *iao_h = take(W1);
    __half *taq_h = take(W1), *tak_h = take(W1), *tav_h = take(W1), *tao_h = take(W1);
    __half *img_h = take(SZ), *img_l = take(SZ);
    __half *cap_h = take(NTOK * 768), *cap_l = take(NTOK * 768);
    __half *txt_h = take(SZ), *txt_l = take(SZ);
    __half *gim_h = take(SZ), *gim_l = take(SZ);
    __half *o1_h  = take(SZ);
    __half *o2_h  = take(SZ);

    float* out_img = (float*)d_out;
    float* out_txt = out_img + SZ;

    cudaFuncSetAttribute(gemm_mma<true>,  cudaFuncAttributeMaxDynamicSharedMemorySize, GEMM_SMEM_S);
    cudaFuncSetAttribute(gemm_mma<false>, cudaFuncAttributeMaxDynamicSharedMemorySize, GEMM_SMEM_1);
    cudaFuncSetAttribute(attn_kernel, cudaFuncAttributeMaxDynamicSharedMemorySize, ATTN_SMEM);

    // 0: convert — weights single fp16, inputs split fp16
    CBatch cb = {};
    cb.s[0]  = { tp_w,      tpw_h, nullptr, (int)(WTP / 4) };
    cb.s[1]  = { ip_w,      ipw_h, nullptr, (int)(W1 / 4) };
    cb.s[2]  = { ia_qw,     iaq_h, nullptr, (int)(W1 / 4) };
    cb.s[3]  = { ia_kw,     iak_h, nullptr, (int)(W1 / 4) };
    cb.s[4]  = { ia_vw,     iav_h, nullptr, (int)(W1 / 4) };
    cb.s[5]  = { ia_ow,     iao_h, nullptr, (int)(W1 / 4) };
    cb.s[6]  = { ta_qw,     taq_h, nullptr, (int)(W1 / 4) };
    cb.s[7]  = { ta_kw,     tak_h, nullptr, (int)(W1 / 4) };
    cb.s[8]  = { ta_vw,     tav_h, nullptr, (int)(W1 / 4) };
    cb.s[9]  = { ta_ow,     tao_h, nullptr, (int)(W1 / 4) };
    cb.s[10] = { images,    img_h, img_l,   (int)(SZ / 4) };
    cb.s[11] = { capitions, cap_h, cap_l,   (int)(NTOK * 768 / 4) };
    convert_kernel<<<dim3(1024, 12), 256>>>(cb);

    // 1: modality projections — SPLIT (feeds residual + all activations)
    GB b1 = {};
    b1.d[0] = { cap_h, cap_l, tpw_h, tp_b, nullptr, g_txt, txt_h, txt_l, 768 };
    b1.d[1] = { img_h, img_l, ipw_h, ip_b, nullptr, g_img, gim_h, gim_l, 1024 };
    gemm_mma<true><<<dim3(8, 4, 2), 256, GEMM_SMEM_S>>>(b1, DM);

    // 2: Q/K/V — single-pass fp16
    GB b2 = {};
    b2.d[0] = { gim_h, nullptr, iaq_h, ia_qb, nullptr, g_q1, nullptr, nullptr, 1024 };
    b2.d[1] = { txt_h, nullptr, iak_h, ia_kb, nullptr, g_k1, nullptr, nullptr, 1024 };
    b2.d[2] = { txt_h, nullptr, iav_h, ia_vb, nullptr, g_v1, nullptr, nullptr, 1024 };
    b2.d[3] = { txt_h, nullptr, taq_h, ta_qb, nullptr, g_q2, nullptr, nullptr, 1024 };
    b2.d[4] = { gim_h, nullptr, tak_h, ta_kb, nullptr, g_k2, nullptr, nullptr, 1024 };
    b2.d[5] = { gim_h, nullptr, tav_h, ta_vb, nullptr, g_v2, nullptr, nullptr, 1024 };
    gemm_mma<false><<<dim3(8, 4, 6), 256, GEMM_SMEM_1>>>(b2, DM);

    // 3: windowed attention -> fp16 outputs
    attn_kernel<<<dim3(NTOK / QB, HEADS, 2), 256, ATTN_SMEM>>>(
        g_q1, g_k1, g_v1, ia_kb, ia_vb, o1_h,
        g_q2, g_k2, g_v2, ta_kb, ta_vb, o2_h);

    // 4: output projections + residual -> d_out — single-pass fp16
    GB b4 = {};
    b4.d[0] = { o1_h, nullptr, iao_h, ia_ob, g_img, out_img, nullptr, nullptr, 1024 };
    b4.d[1] = { o2_h, nullptr, tao_h, ta_ob, g_txt, out_txt, nullptr, nullptr, 1024 };
    gemm_mma<false><<<dim3(8, 4, 2), 256, GEMM_SMEM_1>>>(b4, DM);
}

// round 11
// speedup vs baseline: 3.4899x; 1.0869x over previous
#include <cuda_runtime.h>
#include <cuda_fp16.h>
#include <math.h>
#include <stdint.h>

// ===========================================================================
// CrossModalFusionModel via mma.sync (HMMA fp16) on sm_103 base target.
// Stage 1 (modality proj): 2-pass split-fp16 -> fp32 + split-fp16 out.
// Stage 2 (QKV): single-pass fp16, fp16-ONLY output (feeds attention).
// Stage 4 (o-proj): single-pass fp16 -> fp32 d_out (+resid).
// Attention: all-fp16 Q/K/V smem, HFMA2 scores, fp32 accum AV.
// ===========================================================================

#define NTOK  512
#define DM    1024
#define HEADS 8
#define DH    128
#define WIN   64
#define HALF  32

__device__ __forceinline__ uint32_t s2u(const void* p) {
    uint32_t a;
    asm("{ .reg .u64 t; cvta.to.shared.u64 t, %1; cvt.u32.u64 %0, t; }" : "=r"(a) : "l"(p));
    return a;
}
__device__ __forceinline__ void cp16(uint32_t smem, const void* g) {
    asm volatile("cp.async.cg.shared.global [%0], [%1], 16;" :: "r"(smem), "l"(g));
}
#define CP_COMMIT() asm volatile("cp.async.commit_group;" ::: "memory")
#define CP_WAIT0()  asm volatile("cp.async.wait_group 0;" ::: "memory")
#define CP_WAIT1()  asm volatile("cp.async.wait_group 1;" ::: "memory")

__device__ __forceinline__ void ldx4(uint32_t r[4], uint32_t addr) {
    asm volatile("ldmatrix.sync.aligned.m8n8.x4.shared.b16 {%0,%1,%2,%3}, [%4];"
        : "=r"(r[0]), "=r"(r[1]), "=r"(r[2]), "=r"(r[3]) : "r"(addr));
}
__device__ __forceinline__ void mma16816(float d[4], const uint32_t a[4],
                                         uint32_t b0, uint32_t b1) {
    asm volatile(
        "mma.sync.aligned.m16n8k16.row.col.f32.f16.f16.f32 "
        "{%0,%1,%2,%3}, {%4,%5,%6,%7}, {%8,%9}, {%0,%1,%2,%3};"
        : "+f"(d[0]), "+f"(d[1]), "+f"(d[2]), "+f"(d[3])
        : "r"(a[0]), "r"(a[1]), "r"(a[2]), "r"(a[3]), "r"(b0), "r"(b1));
}

#define SZ (NTOK * DM)
__device__ float   g_f[2 * SZ];         // txt, img (fp32, residuals)
__device__ __half  g_hf[20 * 1024 * 1024];

// ---------------------------------------------------------------------------
// Conversion: fp32 -> fp16 (hi[,lo])
// ---------------------------------------------------------------------------
struct CSeg { const float* src; __half *hi, *lo; int n4; };
struct CBatch { CSeg s[12]; };

__global__ __launch_bounds__(256)
void convert_kernel(CBatch cb) {
    CSeg s = cb.s[blockIdx.y];
    int i = blockIdx.x * 256 + threadIdx.x;
    if (i >= s.n4) return;
    float4 x = ((const float4*)s.src)[i];
    __half h0 = __float2half(x.x), h1 = __float2half(x.y);
    __half h2 = __float2half(x.z), h3 = __float2half(x.w);
    __half2* ph = (__half2*)(s.hi) + 2 * i;
    ph[0] = __halves2half2(h0, h1); ph[1] = __halves2half2(h2, h3);
    if (s.lo) {
        __half2* pl = (__half2*)(s.lo) + 2 * i;
        pl[0] = __halves2half2(__float2half(x.x - __half2float(h0)),
                               __float2half(x.y - __half2float(h1)));
        pl[1] = __halves2half2(__float2half(x.z - __half2float(h2)),
                               __float2half(x.w - __half2float(h3)));
    }
}

// ---------------------------------------------------------------------------
// mma.sync GEMM. SPLIT: C = Ahi@W + Alo@W. Outputs: fp32 C (opt), fp16 Chi
// (opt), fp16 Clo (opt).
// ---------------------------------------------------------------------------
struct GD {
    const __half *Ahi, *Alo, *Whi;
    const float *bias, *resid;
    float* C;
    __half *Chi, *Clo;
    int K;
};
struct GB { GD d[6]; };

#define TILE_B    16384
#define GEMM_SMEM_S (6 * TILE_B)
#define GEMM_SMEM_1 (4 * TILE_B)

__device__ __forceinline__ void load_tile(uint32_t sdst, const __half* src,
                                          int row0, int k0, int K, int tid) {
    const char* g = (const char*)(src + (size_t)row0 * K + k0);
    const size_t rstride = (size_t)K * 2;
#pragma unroll
    for (int it = 0; it < 4; it++) {
        int idx = tid + it * 256;
        int r = idx >> 3, f4 = idx & 7;
        cp16(sdst + (uint32_t)(r * 128 + ((f4 * 16) ^ ((r & 7) << 4))),
             g + (size_t)r * rstride + f4 * 16);
    }
}

template<bool SPLIT>
__global__ __launch_bounds__(256, 2)
void gemm_mma(GB batch, int N) {
    extern __shared__ char smem[];
    const GD g = batch.d[blockIdx.z];
    const uint32_t sb = s2u(smem);
    const int tid = threadIdx.x, wid = tid >> 5, lane = tid & 31;
    const int m0 = blockIdx.y * 128, n0 = blockIdx.x * 128;
    const int wm = (wid & 3) * 32;
    const int wn = (wid >> 2) * 64;
    constexpr uint32_t TPB   = SPLIT ? 3 : 2;
    constexpr uint32_t BUF_B = TPB * TILE_B;
    constexpr uint32_t WOFF  = (TPB - 1) * TILE_B;

    float acc[2][8][4];
#pragma unroll
    for (int a = 0; a < 2; a++)
#pragma unroll
        for (int b = 0; b < 8; b++)
#pragma unroll
            for (int c = 0; c < 4; c++) acc[a][b][c] = 0.f;

    const int nch = g.K >> 6;
    const int      lrow = lane & 15;
    const uint32_t cgb  = (uint32_t)((lane >> 4) * 16);
    const uint32_t xm   = (uint32_t)((lrow & 7) << 4);

    auto loadbuf = [&](uint32_t bo, int k0) {
        load_tile(bo, g.Ahi, m0, k0, g.K, tid);
        if (SPLIT) load_tile(bo + TILE_B, g.Alo, m0, k0, g.K, tid);
        load_tile(bo + WOFF, g.Whi, n0, k0, g.K, tid);
    };

    loadbuf(sb, 0);
    CP_COMMIT();

    for (int i = 0; i < nch; i++) {
        if (i + 1 < nch) {
            loadbuf(sb + (uint32_t)(((i + 1) & 1) * BUF_B), (i + 1) << 6);
            CP_COMMIT();
            CP_WAIT1();
        } else {
            CP_WAIT0();
        }
        __syncthreads();

        const uint32_t bo = sb + (uint32_t)((i & 1) * BUF_B);
        const uint32_t aHi = bo + (uint32_t)((wm + lrow) * 128);
        const uint32_t bHi = bo + WOFF + (uint32_t)((wn + lrow) * 128);

#pragma unroll
        for (int ks = 0; ks < 4; ks++) {
            const uint32_t co = ((uint32_t)(ks * 32) + cgb) ^ xm;
            uint32_t ah[2][4], bh[4][4];
#pragma unroll
            for (int mf = 0; mf < 2; mf++)
                ldx4(ah[mf], aHi + (uint32_t)(mf * 16 * 128) + co);
#pragma unroll
            for (int p = 0; p < 4; p++)
                ldx4(bh[p], bHi + (uint32_t)(p * 16 * 128) + co);
#pragma unroll
            for (int mf = 0; mf < 2; mf++)
#pragma unroll
                for (int nf = 0; nf < 8; nf++) {
                    const int p = nf >> 1, o = nf & 1;
                    mma16816(acc[mf][nf], ah[mf], bh[p][o], bh[p][o + 2]);
                }
            if (SPLIT) {
                uint32_t al[2][4];
                const uint32_t aLo = aHi + TILE_B;
#pragma unroll
                for (int mf = 0; mf < 2; mf++)
                    ldx4(al[mf], aLo + (uint32_t)(mf * 16 * 128) + co);
#pragma unroll
                for (int mf = 0; mf < 2; mf++)
#pragma unroll
                    for (int nf = 0; nf < 8; nf++) {
                        const int p = nf >> 1, o = nf & 1;
                        mma16816(acc[mf][nf], al[mf], bh[p][o], bh[p][o + 2]);
                    }
            }
        }
        __syncthreads();
    }

    const int qr = lane >> 2, qc = (lane & 3) * 2;
#pragma unroll
    for (int mf = 0; mf < 2; mf++) {
        const int r0 = m0 + wm + mf * 16 + qr;
#pragma unroll
        for (int nf = 0; nf < 8; nf++) {
            const int c = n0 + wn + nf * 8 + qc;
            const float2 bv = *(const float2*)(g.bias + c);
            float o00 = acc[mf][nf][0] + bv.x, o01 = acc[mf][nf][1] + bv.y;
            float o10 = acc[mf][nf][2] + bv.x, o11 = acc[mf][nf][3] + bv.y;
            const size_t off0 = (size_t)r0 * N + c;
            const size_t off1 = off0 + (size_t)8 * N;
            if (g.resid) {
                float2 ra = *(const float2*)(g.resid + off0);
                float2 rb = *(const float2*)(g.resid + off1);
                o00 += ra.x; o01 += ra.y; o10 += rb.x; o11 += rb.y;
            }
            if (g.C) {
                *(float2*)(g.C + off0) = make_float2(o00, o01);
                *(float2*)(g.C + off1) = make_float2(o10, o11);
            }
            if (g.Chi) {
                __half h00 = __float2half(o00), h01 = __float2half(o01);
                __half h10 = __float2half(o10), h11 = __float2half(o11);
                *(__half2*)(g.Chi + off0) = __halves2half2(h00, h01);
                *(__half2*)(g.Chi + off1) = __halves2half2(h10, h11);
                if (g.Clo) {
                    *(__half2*)(g.Clo + off0) = __halves2half2(
                        __float2half(o00 - __half2float(h00)),
                        __float2half(o01 - __half2float(h01)));
                    *(__half2*)(g.Clo + off1) = __halves2half2(
                        __float2half(o10 - __half2float(h10)),
                        __float2half(o11 - __half2float(h11)));
                }
            }
        }
    }
}

// ---------------------------------------------------------------------------
// Sliding-window attention: all-fp16 Q/K/V inputs. grid (NTOK/QB, HEADS, 2).
// Smem: Ks2 half2[82][65] (stride 65: conflict-free score reads),
//       Vs2 half2[82][66] (stride 66: aligned LDS.64 in AV),
//       Qs2 half2[16][65], Ws[8][88].
// ---------------------------------------------------------------------------
#define QB    16
#define WR    81
#define PADC  81
#define KROW  65
#define VROW  66
#define OFF_KS   0
#define OFF_VS   21328                        // 82*65*4=21320 -> pad 21328
#define OFF_QS   (OFF_VS + 82*VROW*4)         // +21648 = 42976
#define OFF_WS   (OFF_QS + 16*KROW*4)         // +4160  = 47136
#define ATTN_SMEM (OFF_WS + 8*88*4 + 16)      // 49968

__global__ __launch_bounds__(256)
void attn_kernel(const __half* __restrict__ Q1, const __half* __restrict__ K1,
                 const __half* __restrict__ V1, const float* __restrict__ kb1,
                 const float* __restrict__ vb1, __half* __restrict__ O1h,
                 const __half* __restrict__ Q2, const __half* __restrict__ K2,
                 const __half* __restrict__ V2, const float* __restrict__ kb2,
                 const float* __restrict__ vb2, __half* __restrict__ O2h) {
    extern __shared__ char smraw[];
    __half2* Ks2 = (__half2*)(smraw + OFF_KS);
    __half2* Vs2 = (__half2*)(smraw + OFF_VS);
    __half2* Qs2 = (__half2*)(smraw + OFF_QS);
    float*   Ws  = (float*)(smraw + OFF_WS);

    const __half *Q, *K, *V;
    const float *kb, *vb;
    __half *Oh;
    if (blockIdx.z == 0) { Q=Q1; K=K1; V=V1; kb=kb1; vb=vb1; Oh=O1h; }
    else                 { Q=Q2; K=K2; V=V2; kb=kb2; vb=vb2; Oh=O2h; }

    const int h   = blockIdx.y;
    const int tid = threadIdx.x, wid = tid >> 5, lane = tid & 31;
    const int q0  = blockIdx.x * QB;
    const int base = q0 - HALF;
    const int jmin = max(0, -base);
    const int jmax = min(NTOK - 1, q0 + QB - 1 + HALF + 1) - base;
    const float scale = 0.088388347648318447f;

    // ---- load K/V (fp16, 16B chunks), pad row, Q ----
    for (int idx = tid; idx < WR * 16; idx += 256) {
        const int j = idx >> 4, w16 = idx & 15;      // w16: which 8-half chunk
        if (j >= jmin && j <= jmax) {
            const size_t go = (size_t)(base + j) * DM + h * DH + w16 * 8;
            const uint4 kv = *(const uint4*)(K + go);
            __half2* kd = Ks2 + j * KROW + w16 * 4;
            kd[0] = *(const __half2*)&kv.x; kd[1] = *(const __half2*)&kv.y;
            kd[2] = *(const __half2*)&kv.z; kd[3] = *(const __half2*)&kv.w;
            const uint4 vv = *(const uint4*)(V + go);
            uint2* vd = (uint2*)(Vs2 + j * VROW + w16 * 4);
            vd[0] = make_uint2(vv.x, vv.y);
            vd[1] = make_uint2(vv.z, vv.w);
        }
    }
    if (tid < 32) {                                   // pad slot (kb, vb)
        const float4 kv = *(const float4*)(kb + h * DH + tid * 4);
        Ks2[PADC * KROW + tid * 2 + 0] = __floats2half2_rn(kv.x, kv.y);
        Ks2[PADC * KROW + tid * 2 + 1] = __floats2half2_rn(kv.z, kv.w);
        const float4 vv = *(const float4*)(vb + h * DH + tid * 4);
        Vs2[PADC * VROW + tid * 2 + 0] = __floats2half2_rn(vv.x, vv.y);
        Vs2[PADC * VROW + tid * 2 + 1] = __floats2half2_rn(vv.z, vv.w);
    }
    {
        const int idx = tid;                          // QB*16 == 256
        const int q = idx >> 4, w16 = idx & 15;
        const uint4 qv = *(const uint4*)(Q + (size_t)(q0 + q) * DM + h * DH + w16 * 8);
        __half2* qd = Qs2 + q * KROW + w16 * 4;
        qd[0] = *(const __half2*)&qv.x; qd[1] = *(const __half2*)&qv.y;
        qd[2] = *(const __half2*)&qv.z; qd[3] = *(const __half2*)&qv.w;
    }
    __syncthreads();

    float* wq = Ws + wid * 88;

#pragma unroll
    for (int qq = 0; qq < 2; qq++) {
        const int qi  = wid * 2 + qq;
        const int n   = q0 + qi;
        const int lo  = max(0, n - HALF);
        const int hi  = min(NTOK - 1, n + HALF + 1);
        const int cnt = hi - lo + 1;
        const int nz  = max(0, WIN - cnt);
        const int jb  = lo - base;

        const __half2* qp = Qs2 + qi * KROW;
        const int j0 = lane, j1 = lane + 32, j2 = lane + 64;
        const __half2* k0 = Ks2 + j0 * KROW;
        const __half2* k1 = Ks2 + j1 * KROW;
        const __half2* k2 = Ks2 + min(j2, PADC) * KROW;

        __half2 a0 = __floats2half2_rn(0.f, 0.f);
        __half2 a1 = a0, a2 = a0;
#pragma unroll 8
        for (int d2 = 0; d2 < 64; d2++) {
            const __half2 q2 = qp[d2];
            a0 = __hfma2(q2, k0[d2], a0);
            a1 = __hfma2(q2, k1[d2], a1);
            a2 = __hfma2(q2, k2[d2], a2);
        }
        float s0 = __low2float(a0) + __high2float(a0);
        float s1 = __low2float(a1) + __high2float(a1);
        float s2 = __low2float(a2) + __high2float(a2);

        const bool v0 = (j0 >= jb) && (j0 < jb + cnt);
        const bool v1 = (j1 >= jb) && (j1 < jb + cnt);
        const bool v2 = ((j2 >= jb) && (j2 < jb + cnt)) || (j2 == PADC);
        s0 = v0 ? s0 * scale : -INFINITY;
        s1 = v1 ? s1 * scale : -INFINITY;
        s2 = v2 ? s2 * scale : -INFINITY;

        float mx = fmaxf(s0, fmaxf(s1, s2));
#pragma unroll
        for (int o = 16; o; o >>= 1) mx = fmaxf(mx, __shfl_xor_sync(0xffffffffu, mx, o));

        float w0 = v0 ? expf(s0 - mx) : 0.f;
        float w1 = v1 ? expf(s1 - mx) : 0.f;
        float w2 = v2 ? expf(s2 - mx) : 0.f;
        if (j2 == PADC) w2 *= (float)nz;

        float dsum = w0 + w1 + w2;
#pragma unroll
        for (int o = 16; o; o >>= 1) dsum += __shfl_xor_sync(0xffffffffu, dsum, o);

        wq[j0] = w0;
        wq[j1] = w1;
        if (j2 <= PADC) wq[j2] = w2;
        __syncwarp();

        // AV (fp32 accum, fp16 V): lane owns dims lane*4..+3 (2 half2 words)
        float4 acc = make_float4(0.f, 0.f, 0.f, 0.f);
        for (int p = 0; p < cnt; p++) {
            const int j = jb + p;
            const float w = wq[j];
            const uint2 vraw = *(const uint2*)(Vs2 + j * VROW + lane * 2);
            const float2 fa = __half22float2(*(const __half2*)&vraw.x);
            const float2 fb = __half22float2(*(const __half2*)&vraw.y);
            acc.x += w * fa.x; acc.y += w * fa.y;
            acc.z += w * fb.x; acc.w += w * fb.y;
        }
        {
            const float w = wq[PADC];
            const uint2 vraw = *(const uint2*)(Vs2 + PADC * VROW + lane * 2);
            const float2 fa = __half22float2(*(const __half2*)&vraw.x);
            const float2 fb = __half22float2(*(const __half2*)&vraw.y);
            acc.x += w * fa.x; acc.y += w * fa.y;
            acc.z += w * fb.x; acc.w += w * fb.y;
        }
        __syncwarp();

        const float inv = 1.f / dsum;
        const size_t oo = (size_t)n * DM + h * DH + lane * 4;
        __half2* ph = (__half2*)(Oh + oo);
        ph[0] = __halves2half2(__float2half(acc.x * inv), __float2half(acc.y * inv));
        ph[1] = __halves2half2(__float2half(acc.z * inv), __float2half(acc.w * inv));
    }
}

// ---------------------------------------------------------------------------
// Launch
// ---------------------------------------------------------------------------
extern "C" void kernel_launch(void* const* d_in, const int* in_sizes, int n_in,
                              void* d_out, int out_size) {
    const float* images    = (const float*)d_in[0];
    const float* capitions = (const float*)d_in[1];
    const float* tp_w  = (const float*)d_in[3];
    const float* tp_b  = (const float*)d_in[4];
    const float* ip_w  = (const float*)d_in[5];
    const float* ip_b  = (const float*)d_in[6];
    const float* ia_qw = (const float*)d_in[7];
    const float* ia_qb = (const float*)d_in[8];
    const float* ia_kw = (const float*)d_in[9];
    const float* ia_kb = (const float*)d_in[10];
    const float* ia_vw = (const float*)d_in[11];
    const float* ia_vb = (const float*)d_in[12];
    const float* ia_ow = (const float*)d_in[13];
    const float* ia_ob = (const float*)d_in[14];
    const float* ta_qw = (const float*)d_in[15];
    const float* ta_qb = (const float*)d_in[16];
    const float* ta_kw = (const float*)d_in[17];
    const float* ta_kb = (const float*)d_in[18];
    const float* ta_vw = (const float*)d_in[19];
    const float* ta_vb = (const float*)d_in[20];
    const float* ta_ow = (const float*)d_in[21];
    const float* ta_ob = (const float*)d_in[22];

    void* fp = nullptr; cudaGetSymbolAddress(&fp, g_f);
    void* bp = nullptr; cudaGetSymbolAddress(&bp, g_hf);
    float* F = (float*)fp;
    __half* B = (__half*)bp;

    float* g_txt = F + 0 * SZ;
    float* g_img = F + 1 * SZ;

    size_t cur = 0;
    auto take = [&](size_t n) { __half* p = B + cur; cur += n; return p; };
    const size_t WTP = 1024 * 768, W1 = 1024 * 1024;
    __half *tpw_h = take(WTP);
    __half *ipw_h = take(W1);
    __half *iaq_h = take(W1), *iak_h = take(W1), *iav_h = take(W1), *iao_h = take(W1);
    __half *taq_h = take(W1), *tak_h = take(W1), *tav_h = take(W1), *tao_h = take(W1);
    __half *img_h = take(SZ), *img_l = take(SZ);
    __half *cap_h = take(NTOK * 768), *cap_l = take(NTOK * 768);
    __half *txt_h = take(SZ), *txt_l = take(SZ);
    __half *gim_h = take(SZ), *gim_l = take(SZ);
    __half *q1h = take(SZ), *k1h = take(SZ), *v1h = take(SZ);
    __half *q2h = take(SZ), *k2h = take(SZ), *v2h = take(SZ);
    __half *o1_h = take(SZ), *o2_h = take(SZ);

    float* out_img = (float*)d_out;
    float* out_txt = out_img + SZ;

    cudaFuncSetAttribute(gemm_mma<true>,  cudaFuncAttributeMaxDynamicSharedMemorySize, GEMM_SMEM_S);
    cudaFuncSetAttribute(gemm_mma<false>, cudaFuncAttributeMaxDynamicSharedMemorySize, GEMM_SMEM_1);
    cudaFuncSetAttribute(attn_kernel, cudaFuncAttributeMaxDynamicSharedMemorySize, ATTN_SMEM);

    // 0: convert — weights single fp16, inputs split fp16
    CBatch cb = {};
    cb.s[0]  = { tp_w,      tpw_h, nullptr, (int)(WTP / 4) };
    cb.s[1]  = { ip_w,      ipw_h, nullptr, (int)(W1 / 4) };
    cb.s[2]  = { ia_qw,     iaq_h, nullptr, (int)(W1 / 4) };
    cb.s[3]  = { ia_kw,     iak_h, nullptr, (int)(W1 / 4) };
    cb.s[4]  = { ia_vw,     iav_h, nullptr, (int)(W1 / 4) };
    cb.s[5]  = { ia_ow,     iao_h, nullptr, (int)(W1 / 4) };
    cb.s[6]  = { ta_qw,     taq_h, nullptr, (int)(W1 / 4) };
    cb.s[7]  = { ta_kw,     tak_h, nullptr, (int)(W1 / 4) };
    cb.s[8]  = { ta_vw,     tav_h, nullptr, (int)(W1 / 4) };
    cb.s[9]  = { ta_ow,     tao_h, nullptr, (int)(W1 / 4) };
    cb.s[10] = { images,    img_h, img_l,   (int)(SZ / 4) };
    cb.s[11] = { capitions, cap_h, cap_l,   (int)(NTOK * 768 / 4) };
    convert_kernel<<<dim3(1024, 12), 256>>>(cb);

    // 1: modality projections — SPLIT; fp32 (residual) + split fp16 out
    GB b1 = {};
    b1.d[0] = { cap_h, cap_l, tpw_h, tp_b, nullptr, g_txt, txt_h, txt_l, 768 };
    b1.d[1] = { img_h, img_l, ipw_h, ip_b, nullptr, g_img, gim_h, gim_l, 1024 };
    gemm_mma<true><<<dim3(8, 4, 2), 256, GEMM_SMEM_S>>>(b1, DM);

    // 2: Q/K/V — single-pass fp16, fp16-only outputs
    GB b2 = {};
    b2.d[0] = { gim_h, nullptr, iaq_h, ia_qb, nullptr, nullptr, q1h, nullptr, 1024 };
    b2.d[1] = { txt_h, nullptr, iak_h, ia_kb, nullptr, nullptr, k1h, nullptr, 1024 };
    b2.d[2] = { txt_h, nullptr, iav_h, ia_vb, nullptr, nullptr, v1h, nullptr, 1024 };
    b2.d[3] = { txt_h, nullptr, taq_h, ta_qb, nullptr, nullptr, q2h, nullptr, 1024 };
    b2.d[4] = { gim_h, nullptr, tak_h, ta_kb, nullptr, nullptr, k2h, nullptr, 1024 };
    b2.d[5] = { gim_h, nullptr, tav_h, ta_vb, nullptr, nullptr, v2h, nullptr, 1024 };
    gemm_mma<false><<<dim3(8, 4, 6), 256, GEMM_SMEM_1>>>(b2, DM);

    // 3: windowed attention (fp16 in/out)
    attn_kernel<<<dim3(NTOK / QB, HEADS, 2), 256, ATTN_SMEM>>>(
        q1h, k1h, v1h, ia_kb, ia_vb, o1_h,
        q2h, k2h, v2h, ta_kb, ta_vb, o2_h);

    // 4: output projections + residual -> d_out
    GB b4 = {};
    b4.d[0] = { o1_h, nullptr, iao_h, ia_ob, g_img, out_img, nullptr, nullptr, 1024 };
    b4.d[1] = { o2_h, nullptr, tao_h, ta_ob, g_txt, out_txt, nullptr, nullptr, 1024 };
    gemm_mma<false><<<dim3(8, 4, 2), 256, GEMM_SMEM_1>>>(b4, DM);
}

// round 13
// speedup vs baseline: 3.6910x; 1.0576x over previous
#include <cuda_runtime.h>
#include <cuda_fp16.h>
#include <math.h>
#include <stdint.h>

// ===========================================================================
// CrossModalFusionModel via mma.sync (HMMA fp16) on sm_103 base target.
// Stage 1: 2-pass split-fp16 GEMM (+ fused convert workers for QKV weights).
// Stage 2: single-pass fp16 QKV GEMM (+ fused convert workers for O weights).
// Stage 4: single-pass fp16 o-proj + residual -> d_out.
// Attention: all-fp16 Q/K/V smem, HFMA2 scores, fp32 accum AV.
// R13: pre-convert kernel is grid-stride (R12 dropped coverage of large
//      weight segments -> half of ip_w unconverted -> rel_err 0.707).
// ===========================================================================

#define NTOK  512
#define DM    1024
#define HEADS 8
#define DH    128
#define WIN   64
#define HALF  32

__device__ __forceinline__ uint32_t s2u(const void* p) {
    uint32_t a;
    asm("{ .reg .u64 t; cvta.to.shared.u64 t, %1; cvt.u32.u64 %0, t; }" : "=r"(a) : "l"(p));
    return a;
}
__device__ __forceinline__ void cp16(uint32_t smem, const void* g) {
    asm volatile("cp.async.cg.shared.global [%0], [%1], 16;" :: "r"(smem), "l"(g));
}
#define CP_COMMIT() asm volatile("cp.async.commit_group;" ::: "memory")
#define CP_WAIT0()  asm volatile("cp.async.wait_group 0;" ::: "memory")
#define CP_WAIT1()  asm volatile("cp.async.wait_group 1;" ::: "memory")

__device__ __forceinline__ void ldx4(uint32_t r[4], uint32_t addr) {
    asm volatile("ldmatrix.sync.aligned.m8n8.x4.shared.b16 {%0,%1,%2,%3}, [%4];"
        : "=r"(r[0]), "=r"(r[1]), "=r"(r[2]), "=r"(r[3]) : "r"(addr));
}
__device__ __forceinline__ void mma16816(float d[4], const uint32_t a[4],
                                         uint32_t b0, uint32_t b1) {
    asm volatile(
        "mma.sync.aligned.m16n8k16.row.col.f32.f16.f16.f32 "
        "{%0,%1,%2,%3}, {%4,%5,%6,%7}, {%8,%9}, {%0,%1,%2,%3};"
        : "+f"(d[0]), "+f"(d[1]), "+f"(d[2]), "+f"(d[3])
        : "r"(a[0]), "r"(a[1]), "r"(a[2]), "r"(a[3]), "r"(b0), "r"(b1));
}

#define SZ (NTOK * DM)
__device__ float   g_f[2 * SZ];         // txt, img (fp32 residuals)
__device__ __half  g_hf[20 * 1024 * 1024];

// ---------------------------------------------------------------------------
// Conversion segments: fp32 -> fp16 (hi[,lo])
// ---------------------------------------------------------------------------
struct CSeg { const float* src; __half *hi, *lo; int n4; };
struct CBatch { CSeg s[6]; };

__device__ __forceinline__ void conv_one(const CSeg& s, int i) {
    float4 x = ((const float4*)s.src)[i];
    __half h0 = __float2half(x.x), h1 = __float2half(x.y);
    __half h2 = __float2half(x.z), h3 = __float2half(x.w);
    __half2* ph = (__half2*)(s.hi) + 2 * i;
    ph[0] = __halves2half2(h0, h1); ph[1] = __halves2half2(h2, h3);
    if (s.lo) {
        __half2* pl = (__half2*)(s.lo) + 2 * i;
        pl[0] = __halves2half2(__float2half(x.x - __half2float(h0)),
                               __float2half(x.y - __half2float(h1)));
        pl[1] = __halves2half2(__float2half(x.z - __half2float(h2)),
                               __float2half(x.w - __half2float(h3)));
    }
}

__global__ __launch_bounds__(256)
void convert_kernel(CBatch cb) {
    CSeg s = cb.s[blockIdx.y];
    const int stride = gridDim.x * 256;
    for (int i = blockIdx.x * 256 + threadIdx.x; i < s.n4; i += stride)
        conv_one(s, i);
}

// ---------------------------------------------------------------------------
// mma.sync GEMM (+ optional fused convert workers at blockIdx.z >= zgemm).
// ---------------------------------------------------------------------------
struct GD {
    const __half *Ahi, *Alo, *Whi;
    const float *bias, *resid;
    float* C;
    __half *Chi, *Clo;
    int K;
};
struct GB { GD d[6]; };

#define TILE_B    16384
#define GEMM_SMEM_S (6 * TILE_B)
#define GEMM_SMEM_1 (4 * TILE_B)

__device__ __forceinline__ void load_tile(uint32_t sdst, const __half* src,
                                          int row0, int k0, int K, int tid) {
    const char* g = (const char*)(src + (size_t)row0 * K + k0);
    const size_t rstride = (size_t)K * 2;
#pragma unroll
    for (int it = 0; it < 4; it++) {
        int idx = tid + it * 256;
        int r = idx >> 3, f4 = idx & 7;
        cp16(sdst + (uint32_t)(r * 128 + ((f4 * 16) ^ ((r & 7) << 4))),
             g + (size_t)r * rstride + f4 * 16);
    }
}

template<bool SPLIT>
__global__ __launch_bounds__(256, 2)
void gemm_mma(GB batch, int N, CBatch wc, int nseg, int zgemm) {
    const int tid = threadIdx.x;

    // ---- fused convert workers (idle-SM filler) ----
    if ((int)blockIdx.z >= zgemm) {
        const int worker  = ((int)blockIdx.z - zgemm) * 32 + blockIdx.y * 8 + blockIdx.x;
        const int nworker = ((int)gridDim.z - zgemm) * 32;
        const int gthr    = worker * 256 + tid;
        const int gstride = nworker * 256;
        for (int s = 0; s < nseg; s++)
            for (int i = gthr; i < wc.s[s].n4; i += gstride)
                conv_one(wc.s[s], i);
        return;
    }

    extern __shared__ char smem[];
    const GD g = batch.d[blockIdx.z];
    const uint32_t sb = s2u(smem);
    const int wid = tid >> 5, lane = tid & 31;
    const int m0 = blockIdx.y * 128, n0 = blockIdx.x * 128;
    const int wm = (wid & 3) * 32;
    const int wn = (wid >> 2) * 64;
    constexpr uint32_t TPB   = SPLIT ? 3 : 2;
    constexpr uint32_t BUF_B = TPB * TILE_B;
    constexpr uint32_t WOFF  = (TPB - 1) * TILE_B;

    float acc[2][8][4];
#pragma unroll
    for (int a = 0; a < 2; a++)
#pragma unroll
        for (int b = 0; b < 8; b++)
#pragma unroll
            for (int c = 0; c < 4; c++) acc[a][b][c] = 0.f;

    const int nch = g.K >> 6;
    const int      lrow = lane & 15;
    const uint32_t cgb  = (uint32_t)((lane >> 4) * 16);
    const uint32_t xm   = (uint32_t)((lrow & 7) << 4);

    auto loadbuf = [&](uint32_t bo, int k0) {
        load_tile(bo, g.Ahi, m0, k0, g.K, tid);
        if (SPLIT) load_tile(bo + TILE_B, g.Alo, m0, k0, g.K, tid);
        load_tile(bo + WOFF, g.Whi, n0, k0, g.K, tid);
    };

    loadbuf(sb, 0);
    CP_COMMIT();

    for (int i = 0; i < nch; i++) {
        if (i + 1 < nch) {
            loadbuf(sb + (uint32_t)(((i + 1) & 1) * BUF_B), (i + 1) << 6);
            CP_COMMIT();
            CP_WAIT1();
        } else {
            CP_WAIT0();
        }
        __syncthreads();

        const uint32_t bo = sb + (uint32_t)((i & 1) * BUF_B);
        const uint32_t aHi = bo + (uint32_t)((wm + lrow) * 128);
        const uint32_t bHi = bo + WOFF + (uint32_t)((wn + lrow) * 128);

#pragma unroll
        for (int ks = 0; ks < 4; ks++) {
            const uint32_t co = ((uint32_t)(ks * 32) + cgb) ^ xm;
            uint32_t ah[2][4], bh[4][4];
#pragma unroll
            for (int mf = 0; mf < 2; mf++)
                ldx4(ah[mf], aHi + (uint32_t)(mf * 16 * 128) + co);
#pragma unroll
            for (int p = 0; p < 4; p++)
                ldx4(bh[p], bHi + (uint32_t)(p * 16 * 128) + co);
#pragma unroll
            for (int mf = 0; mf < 2; mf++)
#pragma unroll
                for (int nf = 0; nf < 8; nf++) {
                    const int p = nf >> 1, o = nf & 1;
                    mma16816(acc[mf][nf], ah[mf], bh[p][o], bh[p][o + 2]);
                }
            if (SPLIT) {
                uint32_t al[2][4];
                const uint32_t aLo = aHi + TILE_B;
#pragma unroll
                for (int mf = 0; mf < 2; mf++)
                    ldx4(al[mf], aLo + (uint32_t)(mf * 16 * 128) + co);
#pragma unroll
                for (int mf = 0; mf < 2; mf++)
#pragma unroll
                    for (int nf = 0; nf < 8; nf++) {
                        const int p = nf >> 1, o = nf & 1;
                        mma16816(acc[mf][nf], al[mf], bh[p][o], bh[p][o + 2]);
                    }
            }
        }
        __syncthreads();
    }

    const int qr = lane >> 2, qc = (lane & 3) * 2;
#pragma unroll
    for (int mf = 0; mf < 2; mf++) {
        const int r0 = m0 + wm + mf * 16 + qr;
#pragma unroll
        for (int nf = 0; nf < 8; nf++) {
            const int c = n0 + wn + nf * 8 + qc;
            const float2 bv = *(const float2*)(g.bias + c);
            float o00 = acc[mf][nf][0] + bv.x, o01 = acc[mf][nf][1] + bv.y;
            float o10 = acc[mf][nf][2] + bv.x, o11 = acc[mf][nf][3] + bv.y;
            const size_t off0 = (size_t)r0 * N + c;
            const size_t off1 = off0 + (size_t)8 * N;
            if (g.resid) {
                float2 ra = *(const float2*)(g.resid + off0);
                float2 rb = *(const float2*)(g.resid + off1);
                o00 += ra.x; o01 += ra.y; o10 += rb.x; o11 += rb.y;
            }
            if (g.C) {
                *(float2*)(g.C + off0) = make_float2(o00, o01);
                *(float2*)(g.C + off1) = make_float2(o10, o11);
            }
            if (g.Chi) {
                __half h00 = __float2half(o00), h01 = __float2half(o01);
                __half h10 = __float2half(o10), h11 = __float2half(o11);
                *(__half2*)(g.Chi + off0) = __halves2half2(h00, h01);
                *(__half2*)(g.Chi + off1) = __halves2half2(h10, h11);
                if (g.Clo) {
                    *(__half2*)(g.Clo + off0) = __halves2half2(
                        __float2half(o00 - __half2float(h00)),
                        __float2half(o01 - __half2float(h01)));
                    *(__half2*)(g.Clo + off1) = __halves2half2(
                        __float2half(o10 - __half2float(h10)),
                        __float2half(o11 - __half2float(h11)));
                }
            }
        }
    }
}

// ---------------------------------------------------------------------------
// Sliding-window attention: all-fp16 Q/K/V. grid (NTOK/QB, HEADS, 2).
// ---------------------------------------------------------------------------
#define QB    16
#define WR    81
#define PADC  81
#define KROW  65
#define VROW  66
#define OFF_KS   0
#define OFF_VS   21328
#define OFF_QS   (OFF_VS + 82*VROW*4)
#define OFF_WS   (OFF_QS + 16*KROW*4)
#define ATTN_SMEM (OFF_WS + 8*88*4 + 16)

__global__ __launch_bounds__(256)
void attn_kernel(const __half* __restrict__ Q1, const __half* __restrict__ K1,
                 const __half* __restrict__ V1, const float* __restrict__ kb1,
                 const float* __restrict__ vb1, __half* __restrict__ O1h,
                 const __half* __restrict__ Q2, const __half* __restrict__ K2,
                 const __half* __restrict__ V2, const float* __restrict__ kb2,
                 const float* __restrict__ vb2, __half* __restrict__ O2h) {
    extern __shared__ char smraw[];
    __half2* Ks2 = (__half2*)(smraw + OFF_KS);
    __half2* Vs2 = (__half2*)(smraw + OFF_VS);
    __half2* Qs2 = (__half2*)(smraw + OFF_QS);
    float*   Ws  = (float*)(smraw + OFF_WS);

    const __half *Q, *K, *V;
    const float *kb, *vb;
    __half *Oh;
    if (blockIdx.z == 0) { Q=Q1; K=K1; V=V1; kb=kb1; vb=vb1; Oh=O1h; }
    else                 { Q=Q2; K=K2; V=V2; kb=kb2; vb=vb2; Oh=O2h; }

    const int h   = blockIdx.y;
    const int tid = threadIdx.x, wid = tid >> 5, lane = tid & 31;
    const int q0  = blockIdx.x * QB;
    const int base = q0 - HALF;
    const int jmin = max(0, -base);
    const int jmax = min(NTOK - 1, q0 + QB - 1 + HALF + 1) - base;
    const float scale = 0.088388347648318447f;

    for (int idx = tid; idx < WR * 16; idx += 256) {
        const int j = idx >> 4, w16 = idx & 15;
        if (j >= jmin && j <= jmax) {
            const size_t go = (size_t)(base + j) * DM + h * DH + w16 * 8;
            const uint4 kv = *(const uint4*)(K + go);
            __half2* kd = Ks2 + j * KROW + w16 * 4;
            kd[0] = *(const __half2*)&kv.x; kd[1] = *(const __half2*)&kv.y;
            kd[2] = *(const __half2*)&kv.z; kd[3] = *(const __half2*)&kv.w;
            const uint4 vv = *(const uint4*)(V + go);
            uint2* vd = (uint2*)(Vs2 + j * VROW + w16 * 4);
            vd[0] = make_uint2(vv.x, vv.y);
            vd[1] = make_uint2(vv.z, vv.w);
        }
    }
    if (tid < 32) {
        const float4 kv = *(const float4*)(kb + h * DH + tid * 4);
        Ks2[PADC * KROW + tid * 2 + 0] = __floats2half2_rn(kv.x, kv.y);
        Ks2[PADC * KROW + tid * 2 + 1] = __floats2half2_rn(kv.z, kv.w);
        const float4 vv = *(const float4*)(vb + h * DH + tid * 4);
        Vs2[PADC * VROW + tid * 2 + 0] = __floats2half2_rn(vv.x, vv.y);
        Vs2[PADC * VROW + tid * 2 + 1] = __floats2half2_rn(vv.z, vv.w);
    }
    {
        const int q = tid >> 4, w16 = tid & 15;
        const uint4 qv = *(const uint4*)(Q + (size_t)(q0 + q) * DM + h * DH + w16 * 8);
        __half2* qd = Qs2 + q * KROW + w16 * 4;
        qd[0] = *(const __half2*)&qv.x; qd[1] = *(const __half2*)&qv.y;
        qd[2] = *(const __half2*)&qv.z; qd[3] = *(const __half2*)&qv.w;
    }
    __syncthreads();

    float* wq = Ws + wid * 88;

#pragma unroll
    for (int qq = 0; qq < 2; qq++) {
        const int qi  = wid * 2 + qq;
        const int n   = q0 + qi;
        const int lo  = max(0, n - HALF);
        const int hi  = min(NTOK - 1, n + HALF + 1);
        const int cnt = hi - lo + 1;
        const int nz  = max(0, WIN - cnt);
        const int jb  = lo - base;

        const __half2* qp = Qs2 + qi * KROW;
        const int j0 = lane, j1 = lane + 32, j2 = lane + 64;
        const __half2* k0 = Ks2 + j0 * KROW;
        const __half2* k1 = Ks2 + j1 * KROW;
        const __half2* k2 = Ks2 + min(j2, PADC) * KROW;

        __half2 a0 = __floats2half2_rn(0.f, 0.f);
        __half2 a1 = a0, a2 = a0;
#pragma unroll 8
        for (int d2 = 0; d2 < 64; d2++) {
            const __half2 q2 = qp[d2];
            a0 = __hfma2(q2, k0[d2], a0);
            a1 = __hfma2(q2, k1[d2], a1);
            a2 = __hfma2(q2, k2[d2], a2);
        }
        float s0 = __low2float(a0) + __high2float(a0);
        float s1 = __low2float(a1) + __high2float(a1);
        float s2 = __low2float(a2) + __high2float(a2);

        const bool v0 = (j0 >= jb) && (j0 < jb + cnt);
        const bool v1 = (j1 >= jb) && (j1 < jb + cnt);
        const bool v2 = ((j2 >= jb) && (j2 < jb + cnt)) || (j2 == PADC);
        s0 = v0 ? s0 * scale : -INFINITY;
        s1 = v1 ? s1 * scale : -INFINITY;
        s2 = v2 ? s2 * scale : -INFINITY;

        float mx = fmaxf(s0, fmaxf(s1, s2));
#pragma unroll
        for (int o = 16; o; o >>= 1) mx = fmaxf(mx, __shfl_xor_sync(0xffffffffu, mx, o));

        float w0 = v0 ? expf(s0 - mx) : 0.f;
        float w1 = v1 ? expf(s1 - mx) : 0.f;
        float w2 = v2 ? expf(s2 - mx) : 0.f;
        if (j2 == PADC) w2 *= (float)nz;

        float dsum = w0 + w1 + w2;
#pragma unroll
        for (int o = 16; o; o >>= 1) dsum += __shfl_xor_sync(0xffffffffu, dsum, o);

        wq[j0] = w0;
        wq[j1] = w1;
        if (j2 <= PADC) wq[j2] = w2;
        __syncwarp();

        float4 acc = make_float4(0.f, 0.f, 0.f, 0.f);
        for (int p = 0; p < cnt; p++) {
            const int j = jb + p;
            const float w = wq[j];
            const uint2 vraw = *(const uint2*)(Vs2 + j * VROW + lane * 2);
            const float2 fa = __half22float2(*(const __half2*)&vraw.x);
            const float2 fb = __half22float2(*(const __half2*)&vraw.y);
            acc.x += w * fa.x; acc.y += w * fa.y;
            acc.z += w * fb.x; acc.w += w * fb.y;
        }
        {
            const float w = wq[PADC];
            const uint2 vraw = *(const uint2*)(Vs2 + PADC * VROW + lane * 2);
            const float2 fa = __half22float2(*(const __half2*)&vraw.x);
            const float2 fb = __half22float2(*(const __half2*)&vraw.y);
            acc.x += w * fa.x; acc.y += w * fa.y;
            acc.z += w * fb.x; acc.w += w * fb.y;
        }
        __syncwarp();

        const float inv = 1.f / dsum;
        const size_t oo = (size_t)n * DM + h * DH + lane * 4;
        __half2* ph = (__half2*)(Oh + oo);
        ph[0] = __halves2half2(__float2half(acc.x * inv), __float2half(acc.y * inv));
        ph[1] = __halves2half2(__float2half(acc.z * inv), __float2half(acc.w * inv));
    }
}

// ---------------------------------------------------------------------------
// Launch
// ---------------------------------------------------------------------------
extern "C" void kernel_launch(void* const* d_in, const int* in_sizes, int n_in,
                              void* d_out, int out_size) {
    const float* images    = (const float*)d_in[0];
    const float* capitions = (const float*)d_in[1];
    const float* tp_w  = (const float*)d_in[3];
    const float* tp_b  = (const float*)d_in[4];
    const float* ip_w  = (const float*)d_in[5];
    const float* ip_b  = (const float*)d_in[6];
    const float* ia_qw = (const float*)d_in[7];
    const float* ia_qb = (const float*)d_in[8];
    const float* ia_kw = (const float*)d_in[9];
    const float* ia_kb = (const float*)d_in[10];
    const float* ia_vw = (const float*)d_in[11];
    const float* ia_vb = (const float*)d_in[12];
    const float* ia_ow = (const float*)d_in[13];
    const float* ia_ob = (const float*)d_in[14];
    const float* ta_qw = (const float*)d_in[15];
    const float* ta_qb = (const float*)d_in[16];
    const float* ta_kw = (const float*)d_in[17];
    const float* ta_kb = (const float*)d_in[18];
    const float* ta_vw = (const float*)d_in[19];
    const float* ta_vb = (const float*)d_in[20];
    const float* ta_ow = (const float*)d_in[21];
    const float* ta_ob = (const float*)d_in[22];

    void* fp = nullptr; cudaGetSymbolAddress(&fp, g_f);
    void* bp = nullptr; cudaGetSymbolAddress(&bp, g_hf);
    float* F = (float*)fp;
    __half* B = (__half*)bp;

    float* g_txt = F + 0 * SZ;
    float* g_img = F + 1 * SZ;

    size_t cur = 0;
    auto take = [&](size_t n) { __half* p = B + cur; cur += n; return p; };
    const size_t WTP = 1024 * 768, W1 = 1024 * 1024;
    __half *tpw_h = take(WTP);
    __half *ipw_h = take(W1);
    __half *iaq_h = take(W1), *iak_h = take(W1), *iav_h = take(W1), *iao_h = take(W1);
    __half *taq_h = take(W1), *tak_h = take(W1), *tav_h = take(W1), *tao_h = take(W1);
    __half *img_h = take(SZ), *img_l = take(SZ);
    __half *cap_h = take(NTOK * 768), *cap_l = take(NTOK * 768);
    __half *txt_h = take(SZ), *txt_l = take(SZ);
    __half *gim_h = take(SZ), *gim_l = take(SZ);
    __half *q1h = take(SZ), *k1h = take(SZ), *v1h = take(SZ);
    __half *q2h = take(SZ), *k2h = take(SZ), *v2h = take(SZ);
    __half *o1_h = take(SZ), *o2_h = take(SZ);

    float* out_img = (float*)d_out;
    float* out_txt = out_img + SZ;

    cudaFuncSetAttribute(gemm_mma<true>,  cudaFuncAttributeMaxDynamicSharedMemorySize, GEMM_SMEM_S);
    cudaFuncSetAttribute(gemm_mma<false>, cudaFuncAttributeMaxDynamicSharedMemorySize, GEMM_SMEM_1);
    cudaFuncSetAttribute(attn_kernel, cudaFuncAttributeMaxDynamicSharedMemorySize, ATTN_SMEM);

    const CBatch empty = {};

    // 0: pre-convert (grid-stride) — inputs (split) + stage-1 weights only
    CBatch cb0 = {};
    cb0.s[0] = { images,    img_h, img_l,   (int)(SZ / 4) };
    cb0.s[1] = { capitions, cap_h, cap_l,   (int)(NTOK * 768 / 4) };
    cb0.s[2] = { tp_w,      tpw_h, nullptr, (int)(WTP / 4) };
    cb0.s[3] = { ip_w,      ipw_h, nullptr, (int)(W1 / 4) };
    convert_kernel<<<dim3(296, 4), 256>>>(cb0);

    // 1: modality projections (SPLIT) + fused convert of 6 QKV weights
    GB b1 = {};
    b1.d[0] = { cap_h, cap_l, tpw_h, tp_b, nullptr, g_txt, txt_h, txt_l, 768 };
    b1.d[1] = { img_h, img_l, ipw_h, ip_b, nullptr, g_img, gim_h, gim_l, 1024 };
    CBatch wc1 = {};
    wc1.s[0] = { ia_qw, iaq_h, nullptr, (int)(W1 / 4) };
    wc1.s[1] = { ia_kw, iak_h, nullptr, (int)(W1 / 4) };
    wc1.s[2] = { ia_vw, iav_h, nullptr, (int)(W1 / 4) };
    wc1.s[3] = { ta_qw, taq_h, nullptr, (int)(W1 / 4) };
    wc1.s[4] = { ta_kw, tak_h, nullptr, (int)(W1 / 4) };
    wc1.s[5] = { ta_vw, tav_h, nullptr, (int)(W1 / 4) };
    gemm_mma<true><<<dim3(8, 4, 2 + 8), 256, GEMM_SMEM_S>>>(b1, DM, wc1, 6, 2);

    // 2: Q/K/V GEMMs + fused convert of 2 O weights
    GB b2 = {};
    b2.d[0] = { gim_h, nullptr, iaq_h, ia_qb, nullptr, nullptr, q1h, nullptr, 1024 };
    b2.d[1] = { txt_h, nullptr, iak_h, ia_kb, nullptr, nullptr, k1h, nullptr, 1024 };
    b2.d[2] = { txt_h, nullptr, iav_h, ia_vb, nullptr, nullptr, v1h, nullptr, 1024 };
    b2.d[3] = { txt_h, nullptr, taq_h, ta_qb, nullptr, nullptr, q2h, nullptr, 1024 };
    b2.d[4] = { gim_h, nullptr, tak_h, ta_kb, nullptr, nullptr, k2h, nullptr, 1024 };
    b2.d[5] = { gim_h, nullptr, tav_h, ta_vb, nullptr, nullptr, v2h, nullptr, 1024 };
    CBatch wc2 = {};
    wc2.s[0] = { ia_ow, iao_h, nullptr, (int)(W1 / 4) };
    wc2.s[1] = { ta_ow, tao_h, nullptr, (int)(W1 / 4) };
    gemm_mma<false><<<dim3(8, 4, 6 + 2), 256, GEMM_SMEM_1>>>(b2, DM, wc2, 2, 6);

    // 3: windowed attention (fp16 in/out)
    attn_kernel<<<dim3(NTOK / QB, HEADS, 2), 256, ATTN_SMEM>>>(
        q1h, k1h, v1h, ia_kb, ia_vb, o1_h,
        q2h, k2h, v2h, ta_kb, ta_vb, o2_h);

    // 4: output projections + residual -> d_out
    GB b4 = {};
    b4.d[0] = { o1_h, nullptr, iao_h, ia_ob, g_img, out_img, nullptr, nullptr, 1024 };
    b4.d[1] = { o2_h, nullptr, tao_h, ta_ob, g_txt, out_txt, nullptr, nullptr, 1024 };
    gemm_mma<false><<<dim3(8, 4, 2), 256, GEMM_SMEM_1>>>(b4, DM, empty, 0, 2);
}

// round 15
// speedup vs baseline: 4.5219x; 1.2251x over previous
#include <cuda_runtime.h>
#include <cuda_fp16.h>
#include <math.h>
#include <stdint.h>

// ===========================================================================
// CrossModalFusionModel via mma.sync (HMMA fp16) on sm_103 base target.
// Stage 1: 2-pass split-fp16 GEMM, MT=64 tiles (128 CTAs) + fused QKV converts.
// Stage 2: single-pass fp16 QKV GEMM, MT=128 (192 CTAs) + fused O converts.
// Stage 4: single-pass fp16 o-proj, MT=64 (128 CTAs) + residual -> d_out.
// Attention: all-fp16 smem, shared-K fused 2-query score loop, fp32 AV.
// ===========================================================================

#define NTOK  512
#define DM    1024
#define HEADS 8
#define DH    128
#define WIN   64
#define HALF  32

__device__ __forceinline__ uint32_t s2u(const void* p) {
    uint32_t a;
    asm("{ .reg .u64 t; cvta.to.shared.u64 t, %1; cvt.u32.u64 %0, t; }" : "=r"(a) : "l"(p));
    return a;
}
__device__ __forceinline__ void cp16(uint32_t smem, const void* g) {
    asm volatile("cp.async.cg.shared.global [%0], [%1], 16;" :: "r"(smem), "l"(g));
}
#define CP_COMMIT() asm volatile("cp.async.commit_group;" ::: "memory")
#define CP_WAIT0()  asm volatile("cp.async.wait_group 0;" ::: "memory")
#define CP_WAIT1()  asm volatile("cp.async.wait_group 1;" ::: "memory")

__device__ __forceinline__ void ldx4(uint32_t r[4], uint32_t addr) {
    asm volatile("ldmatrix.sync.aligned.m8n8.x4.shared.b16 {%0,%1,%2,%3}, [%4];"
        : "=r"(r[0]), "=r"(r[1]), "=r"(r[2]), "=r"(r[3]) : "r"(addr));
}
__device__ __forceinline__ void mma16816(float d[4], const uint32_t a[4],
                                         uint32_t b0, uint32_t b1) {
    asm volatile(
        "mma.sync.aligned.m16n8k16.row.col.f32.f16.f16.f32 "
        "{%0,%1,%2,%3}, {%4,%5,%6,%7}, {%8,%9}, {%0,%1,%2,%3};"
        : "+f"(d[0]), "+f"(d[1]), "+f"(d[2]), "+f"(d[3])
        : "r"(a[0]), "r"(a[1]), "r"(a[2]), "r"(a[3]), "r"(b0), "r"(b1));
}

#define SZ (NTOK * DM)
__device__ float   g_f[2 * SZ];         // txt, img (fp32 residuals)
__device__ __half  g_hf[20 * 1024 * 1024];

// ---------------------------------------------------------------------------
// Conversion segments: fp32 -> fp16 (hi[,lo])
// ---------------------------------------------------------------------------
struct CSeg { const float* src; __half *hi, *lo; int n4; };
struct CBatch { CSeg s[6]; };

__device__ __forceinline__ void conv_one(const CSeg& s, int i) {
    float4 x = ((const float4*)s.src)[i];
    __half h0 = __float2half(x.x), h1 = __float2half(x.y);
    __half h2 = __float2half(x.z), h3 = __float2half(x.w);
    __half2* ph = (__half2*)(s.hi) + 2 * i;
    ph[0] = __halves2half2(h0, h1); ph[1] = __halves2half2(h2, h3);
    if (s.lo) {
        __half2* pl = (__half2*)(s.lo) + 2 * i;
        pl[0] = __halves2half2(__float2half(x.x - __half2float(h0)),
                               __float2half(x.y - __half2float(h1)));
        pl[1] = __halves2half2(__float2half(x.z - __half2float(h2)),
                               __float2half(x.w - __half2float(h3)));
    }
}

__global__ __launch_bounds__(256)
void convert_kernel(CBatch cb) {
    CSeg s = cb.s[blockIdx.y];
    const int stride = gridDim.x * 256;
    for (int i = blockIdx.x * 256 + threadIdx.x; i < s.n4; i += stride)
        conv_one(s, i);
}

// ---------------------------------------------------------------------------
// mma.sync GEMM (+ fused convert workers at blockIdx.z >= zgemm).
// MT: M-tile (64 or 128). N-tile fixed 128.
// ---------------------------------------------------------------------------
struct GD {
    const __half *Ahi, *Alo, *Whi;
    const float *bias, *resid;
    float* C;
    __half *Chi, *Clo;
    int K;
};
struct GB { GD d[6]; };

#define WTILE_B 16384
#define GEMM_SMEM_64S  (2 * (2 * 8192 + 16384))   // 65536
#define GEMM_SMEM_128  (2 * (16384 + 16384))      // 65536
#define GEMM_SMEM_64   (2 * (8192 + 16384))       // 49152

template<int ROWS>
__device__ __forceinline__ void load_tile(uint32_t sdst, const __half* src,
                                          int row0, int k0, int K, int tid) {
    const char* g = (const char*)(src + (size_t)row0 * K + k0);
    const size_t rstride = (size_t)K * 2;
#pragma unroll
    for (int it = 0; it < ROWS / 32; it++) {
        int idx = tid + it * 256;
        int r = idx >> 3, f4 = idx & 7;
        cp16(sdst + (uint32_t)(r * 128 + ((f4 * 16) ^ ((r & 7) << 4))),
             g + (size_t)r * rstride + f4 * 16);
    }
}

template<int MT, bool SPLIT>
__global__ __launch_bounds__(256, 2)
void gemm_mma(GB batch, int N, CBatch wc, int nseg, int zgemm) {
    const int tid = threadIdx.x;

    // ---- fused convert workers (idle-SM filler) ----
    if ((int)blockIdx.z >= zgemm) {
        const int pb = gridDim.x * gridDim.y;
        const int worker  = ((int)blockIdx.z - zgemm) * pb + blockIdx.y * gridDim.x + blockIdx.x;
        const int nworker = ((int)gridDim.z - zgemm) * pb;
        const int gthr    = worker * 256 + tid;
        const int gstride = nworker * 256;
        for (int s = 0; s < nseg; s++)
            for (int i = gthr; i < wc.s[s].n4; i += gstride)
                conv_one(wc.s[s], i);
        return;
    }

    extern __shared__ char smem[];
    const GD g = batch.d[blockIdx.z];
    const uint32_t sb = s2u(smem);
    const int wid = tid >> 5, lane = tid & 31;
    const int m0 = blockIdx.y * MT, n0 = blockIdx.x * 128;
    constexpr int ATILE = MT * 128;                       // bytes
    constexpr uint32_t WOFF  = (SPLIT ? 2 : 1) * ATILE;
    constexpr uint32_t BUF_B = WOFF + WTILE_B;
    constexpr int NF = (MT == 128) ? 8 : 4;               // 8-col frags per warp
    const int wm = (MT == 128) ? (wid & 3) * 32 : (wid & 1) * 32;
    const int wn = (MT == 128) ? (wid >> 2) * 64 : (wid >> 1) * 32;

    float acc[2][NF][4];
#pragma unroll
    for (int a = 0; a < 2; a++)
#pragma unroll
        for (int b = 0; b < NF; b++)
#pragma unroll
            for (int c = 0; c < 4; c++) acc[a][b][c] = 0.f;

    const int nch = g.K >> 6;
    const int      lrow = lane & 15;
    const uint32_t cgb  = (uint32_t)((lane >> 4) * 16);
    const uint32_t xm   = (uint32_t)((lrow & 7) << 4);

    auto loadbuf = [&](uint32_t bo, int k0) {
        load_tile<MT>(bo, g.Ahi, m0, k0, g.K, tid);
        if (SPLIT) load_tile<MT>(bo + ATILE, g.Alo, m0, k0, g.K, tid);
        load_tile<128>(bo + WOFF, g.Whi, n0, k0, g.K, tid);
    };

    loadbuf(sb, 0);
    CP_COMMIT();

    for (int i = 0; i < nch; i++) {
        if (i + 1 < nch) {
            loadbuf(sb + (uint32_t)(((i + 1) & 1) * BUF_B), (i + 1) << 6);
            CP_COMMIT();
            CP_WAIT1();
        } else {
            CP_WAIT0();
        }
        __syncthreads();

        const uint32_t bo = sb + (uint32_t)((i & 1) * BUF_B);
        const uint32_t aHi = bo + (uint32_t)((wm + lrow) * 128);
        const uint32_t bHi = bo + WOFF + (uint32_t)((wn + lrow) * 128);

#pragma unroll
        for (int ks = 0; ks < 4; ks++) {
            const uint32_t co = ((uint32_t)(ks * 32) + cgb) ^ xm;
            uint32_t ah[2][4], bh[NF / 2][4];
#pragma unroll
            for (int mf = 0; mf < 2; mf++)
                ldx4(ah[mf], aHi + (uint32_t)(mf * 16 * 128) + co);
#pragma unroll
            for (int p = 0; p < NF / 2; p++)
                ldx4(bh[p], bHi + (uint32_t)(p * 16 * 128) + co);
#pragma unroll
            for (int mf = 0; mf < 2; mf++)
#pragma unroll
                for (int nf = 0; nf < NF; nf++) {
                    const int p = nf >> 1, o = nf & 1;
                    mma16816(acc[mf][nf], ah[mf], bh[p][o], bh[p][o + 2]);
                }
            if (SPLIT) {
                uint32_t al[2][4];
                const uint32_t aLo = aHi + ATILE;
#pragma unroll
                for (int mf = 0; mf < 2; mf++)
                    ldx4(al[mf], aLo + (uint32_t)(mf * 16 * 128) + co);
#pragma unroll
                for (int mf = 0; mf < 2; mf++)
#pragma unroll
                    for (int nf = 0; nf < NF; nf++) {
                        const int p = nf >> 1, o = nf & 1;
                        mma16816(acc[mf][nf], al[mf], bh[p][o], bh[p][o + 2]);
                    }
            }
        }
        __syncthreads();
    }

    const int qr = lane >> 2, qc = (lane & 3) * 2;
#pragma unroll
    for (int mf = 0; mf < 2; mf++) {
        const int r0 = m0 + wm + mf * 16 + qr;
#pragma unroll
        for (int nf = 0; nf < NF; nf++) {
            const int c = n0 + wn + nf * 8 + qc;
            const float2 bv = *(const float2*)(g.bias + c);
            float o00 = acc[mf][nf][0] + bv.x, o01 = acc[mf][nf][1] + bv.y;
            float o10 = acc[mf][nf][2] + bv.x, o11 = acc[mf][nf][3] + bv.y;
            const size_t off0 = (size_t)r0 * N + c;
            const size_t off1 = off0 + (size_t)8 * N;
            if (g.resid) {
                float2 ra = *(const float2*)(g.resid + off0);
                float2 rb = *(const float2*)(g.resid + off1);
                o00 += ra.x; o01 += ra.y; o10 += rb.x; o11 += rb.y;
            }
            if (g.C) {
                *(float2*)(g.C + off0) = make_float2(o00, o01);
                *(float2*)(g.C + off1) = make_float2(o10, o11);
            }
            if (g.Chi) {
                __half h00 = __float2half(o00), h01 = __float2half(o01);
                __half h10 = __float2half(o10), h11 = __float2half(o11);
                *(__half2*)(g.Chi + off0) = __halves2half2(h00, h01);
                *(__half2*)(g.Chi + off1) = __halves2half2(h10, h11);
                if (g.Clo) {
                    *(__half2*)(g.Clo + off0) = __halves2half2(
                        __float2half(o00 - __half2float(h00)),
                        __float2half(o01 - __half2float(h01)));
                    *(__half2*)(g.Clo + off1) = __halves2half2(
                        __float2half(o10 - __half2float(h10)),
                        __float2half(o11 - __half2float(h11)));
                }
            }
        }
    }
}

// ---------------------------------------------------------------------------
// Sliding-window attention: all-fp16 Q/K/V. grid (NTOK/QB, HEADS, 2).
// Fused 2-query score loop: K column reads shared by both warp queries.
// ---------------------------------------------------------------------------
#define QB    16
#define WR    81
#define PADC  81
#define KROW  65
#define VROW  66
#define OFF_KS   0
#define OFF_VS   21328
#define OFF_QS   (OFF_VS + 82*VROW*4)
#define OFF_WS   (OFF_QS + 16*KROW*4)
#define ATTN_SMEM (OFF_WS + 16*88*4 + 16)

__global__ __launch_bounds__(256)
void attn_kernel(const __half* __restrict__ Q1, const __half* __restrict__ K1,
                 const __half* __restrict__ V1, const float* __restrict__ kb1,
                 const float* __restrict__ vb1, __half* __restrict__ O1h,
                 const __half* __restrict__ Q2, const __half* __restrict__ K2,
                 const __half* __restrict__ V2, const float* __restrict__ kb2,
                 const float* __restrict__ vb2, __half* __restrict__ O2h) {
    extern __shared__ char smraw[];
    __half2* Ks2 = (__half2*)(smraw + OFF_KS);
    __half2* Vs2 = (__half2*)(smraw + OFF_VS);
    __half2* Qs2 = (__half2*)(smraw + OFF_QS);
    float*   Ws  = (float*)(smraw + OFF_WS);

    const __half *Q, *K, *V;
    const float *kb, *vb;
    __half *Oh;
    if (blockIdx.z == 0) { Q=Q1; K=K1; V=V1; kb=kb1; vb=vb1; Oh=O1h; }
    else                 { Q=Q2; K=K2; V=V2; kb=kb2; vb=vb2; Oh=O2h; }

    const int h   = blockIdx.y;
    const int tid = threadIdx.x, wid = tid >> 5, lane = tid & 31;
    const int q0  = blockIdx.x * QB;
    const int base = q0 - HALF;
    const int jmin = max(0, -base);
    const int jmax = min(NTOK - 1, q0 + QB - 1 + HALF + 1) - base;
    const float scale = 0.088388347648318447f;

    for (int idx = tid; idx < WR * 16; idx += 256) {
        const int j = idx >> 4, w16 = idx & 15;
        if (j >= jmin && j <= jmax) {
            const size_t go = (size_t)(base + j) * DM + h * DH + w16 * 8;
            const uint4 kv = *(const uint4*)(K + go);
            __half2* kd = Ks2 + j * KROW + w16 * 4;
            kd[0] = *(const __half2*)&kv.x; kd[1] = *(const __half2*)&kv.y;
            kd[2] = *(const __half2*)&kv.z; kd[3] = *(const __half2*)&kv.w;
            const uint4 vv = *(const uint4*)(V + go);
            uint2* vd = (uint2*)(Vs2 + j * VROW + w16 * 4);
            vd[0] = make_uint2(vv.x, vv.y);
            vd[1] = make_uint2(vv.z, vv.w);
        }
    }
    if (tid < 32) {
        const float4 kv = *(const float4*)(kb + h * DH + tid * 4);
        Ks2[PADC * KROW + tid * 2 + 0] = __floats2half2_rn(kv.x, kv.y);
        Ks2[PADC * KROW + tid * 2 + 1] = __floats2half2_rn(kv.z, kv.w);
        const float4 vv = *(const float4*)(vb + h * DH + tid * 4);
        Vs2[PADC * VROW + tid * 2 + 0] = __floats2half2_rn(vv.x, vv.y);
        Vs2[PADC * VROW + tid * 2 + 1] = __floats2half2_rn(vv.z, vv.w);
    }
    {
        const int q = tid >> 4, w16 = tid & 15;
        const uint4 qv = *(const uint4*)(Q + (size_t)(q0 + q) * DM + h * DH + w16 * 8);
        __half2* qd = Qs2 + q * KROW + w16 * 4;
        qd[0] = *(const __half2*)&qv.x; qd[1] = *(const __half2*)&qv.y;
        qd[2] = *(const __half2*)&qv.z; qd[3] = *(const __half2*)&qv.w;
    }
    __syncthreads();

    // ---- fused score loop: both warp queries share the K column reads ----
    const int j0 = lane, j1 = lane + 32, j2 = lane + 64;
    const __half2* k0 = Ks2 + j0 * KROW;
    const __half2* k1 = Ks2 + j1 * KROW;
    const __half2* k2 = Ks2 + min(j2, PADC) * KROW;
    const __half2* qpA = Qs2 + (wid * 2 + 0) * KROW;
    const __half2* qpB = Qs2 + (wid * 2 + 1) * KROW;

    const __half2 hz = __floats2half2_rn(0.f, 0.f);
    __half2 a0A = hz, a1A = hz, a2A = hz, a0B = hz, a1B = hz, a2B = hz;
#pragma unroll 8
    for (int d2 = 0; d2 < 64; d2++) {
        const __half2 k0v = k0[d2], k1v = k1[d2], k2v = k2[d2];
        const __half2 qA = qpA[d2], qB = qpB[d2];
        a0A = __hfma2(qA, k0v, a0A);
        a1A = __hfma2(qA, k1v, a1A);
        a2A = __hfma2(qA, k2v, a2A);
        a0B = __hfma2(qB, k0v, a0B);
        a1B = __hfma2(qB, k1v, a1B);
        a2B = __hfma2(qB, k2v, a2B);
    }
    const float r0A = __low2float(a0A) + __high2float(a0A);
    const float r1A = __low2float(a1A) + __high2float(a1A);
    const float r2A = __low2float(a2A) + __high2float(a2A);
    const float r0B = __low2float(a0B) + __high2float(a0B);
    const float r1B = __low2float(a1B) + __high2float(a1B);
    const float r2B = __low2float(a2B) + __high2float(a2B);

#pragma unroll
    for (int qq = 0; qq < 2; qq++) {
        const int n   = q0 + wid * 2 + qq;
        const int lo  = max(0, n - HALF);
        const int hi  = min(NTOK - 1, n + HALF + 1);
        const int cnt = hi - lo + 1;
        const int nz  = max(0, WIN - cnt);
        const int jb  = lo - base;
        float* wq = Ws + (wid * 2 + qq) * 88;

        float s0 = qq ? r0B : r0A;
        float s1 = qq ? r1B : r1A;
        float s2 = qq ? r2B : r2A;

        const bool v0 = (j0 >= jb) && (j0 < jb + cnt);
        const bool v1 = (j1 >= jb) && (j1 < jb + cnt);
        const bool v2 = ((j2 >= jb) && (j2 < jb + cnt)) || (j2 == PADC);
        s0 = v0 ? s0 * scale : -INFINITY;
        s1 = v1 ? s1 * scale : -INFINITY;
        s2 = v2 ? s2 * scale : -INFINITY;

        float mx = fmaxf(s0, fmaxf(s1, s2));
#pragma unroll
        for (int o = 16; o; o >>= 1) mx = fmaxf(mx, __shfl_xor_sync(0xffffffffu, mx, o));

        float w0 = v0 ? expf(s0 - mx) : 0.f;
        float w1 = v1 ? expf(s1 - mx) : 0.f;
        float w2 = v2 ? expf(s2 - mx) : 0.f;
        if (j2 == PADC) w2 *= (float)nz;

        float dsum = w0 + w1 + w2;
#pragma unroll
        for (int o = 16; o; o >>= 1) dsum += __shfl_xor_sync(0xffffffffu, dsum, o);

        wq[j0] = w0;
        wq[j1] = w1;
        if (j2 <= PADC) wq[j2] = w2;
        __syncwarp();

        float4 acc = make_float4(0.f, 0.f, 0.f, 0.f);
        for (int p = 0; p < cnt; p++) {
            const int j = jb + p;
            const float w = wq[j];
            const uint2 vraw = *(const uint2*)(Vs2 + j * VROW + lane * 2);
            const float2 fa = __half22float2(*(const __half2*)&vraw.x);
            const float2 fb = __half22float2(*(const __half2*)&vraw.y);
            acc.x += w * fa.x; acc.y += w * fa.y;
            acc.z += w * fb.x; acc.w += w * fb.y;
        }
        {
            const float w = wq[PADC];
            const uint2 vraw = *(const uint2*)(Vs2 + PADC * VROW + lane * 2);
            const float2 fa = __half22float2(*(const __half2*)&vraw.x);
            const float2 fb = __half22float2(*(const __half2*)&vraw.y);
            acc.x += w * fa.x; acc.y += w * fa.y;
            acc.z += w * fb.x; acc.w += w * fb.y;
        }
        __syncwarp();

        const float inv = 1.f / dsum;
        const size_t oo = (size_t)n * DM + h * DH + lane * 4;
        __half2* ph = (__half2*)(Oh + oo);
        ph[0] = __halves2half2(__float2half(acc.x * inv), __float2half(acc.y * inv));
        ph[1] = __halves2half2(__float2half(acc.z * inv), __float2half(acc.w * inv));
    }
}

// ---------------------------------------------------------------------------
// Launch
// ---------------------------------------------------------------------------
extern "C" void kernel_launch(void* const* d_in, const int* in_sizes, int n_in,
                              void* d_out, int out_size) {
    const float* images    = (const float*)d_in[0];
    const float* capitions = (const float*)d_in[1];
    const float* tp_w  = (const float*)d_in[3];
    const float* tp_b  = (const float*)d_in[4];
    const float* ip_w  = (const float*)d_in[5];
    const float* ip_b  = (const float*)d_in[6];
    const float* ia_qw = (const float*)d_in[7];
    const float* ia_qb = (const float*)d_in[8];
    const float* ia_kw = (const float*)d_in[9];
    const float* ia_kb = (const float*)d_in[10];
    const float* ia_vw = (const float*)d_in[11];
    const float* ia_vb = (const float*)d_in[12];
    const float* ia_ow = (const float*)d_in[13];
    const float* ia_ob = (const float*)d_in[14];
    const float* ta_qw = (const float*)d_in[15];
    const float* ta_qb = (const float*)d_in[16];
    const float* ta_kw = (const float*)d_in[17];
    const float* ta_kb = (const float*)d_in[18];
    const float* ta_vw = (const float*)d_in[19];
    const float* ta_vb = (const float*)d_in[20];
    const float* ta_ow = (const float*)d_in[21];
    const float* ta_ob = (const float*)d_in[22];

    void* fp = nullptr; cudaGetSymbolAddress(&fp, g_f);
    void* bp = nullptr; cudaGetSymbolAddress(&bp, g_hf);
    float* F = (float*)fp;
    __half* B = (__half*)bp;

    float* g_txt = F + 0 * SZ;
    float* g_img = F + 1 * SZ;

    size_t cur = 0;
    auto take = [&](size_t n) { __half* p = B + cur; cur += n; return p; };
    const size_t WTP = 1024 * 768, W1 = 1024 * 1024;
    __half *tpw_h = take(WTP);
    __half *ipw_h = take(W1);
    __half *iaq_h = take(W1), *iak_h = take(W1), *iav_h = take(W1), *iao_h = take(W1);
    __half *taq_h = take(W1), *tak_h = take(W1), *tav_h = take(W1), *tao_h = take(W1);
    __half *img_h = take(SZ), *img_l = take(SZ);
    __half *cap_h = take(NTOK * 768), *cap_l = take(NTOK * 768);
    __half *txt_h = take(SZ), *txt_l = take(SZ);
    __half *gim_h = take(SZ), *gim_l = take(SZ);
    __half *q1h = take(SZ), *k1h = take(SZ), *v1h = take(SZ);
    __half *q2h = take(SZ), *k2h = take(SZ), *v2h = take(SZ);
    __half *o1_h = take(SZ), *o2_h = take(SZ);

    float* out_img = (float*)d_out;
    float* out_txt = out_img + SZ;

    cudaFuncSetAttribute((const void*)&gemm_mma<64, true>,
                         cudaFuncAttributeMaxDynamicSharedMemorySize, GEMM_SMEM_64S);
    cudaFuncSetAttribute((const void*)&gemm_mma<128, false>,
                         cudaFuncAttributeMaxDynamicSharedMemorySize, GEMM_SMEM_128);
    cudaFuncSetAttribute((const void*)&gemm_mma<64, false>,
                         cudaFuncAttributeMaxDynamicSharedMemorySize, GEMM_SMEM_64);
    cudaFuncSetAttribute((const void*)&attn_kernel,
                         cudaFuncAttributeMaxDynamicSharedMemorySize, ATTN_SMEM);

    const CBatch empty = {};

    // 0: pre-convert (grid-stride) — inputs (split) + stage-1 weights only
    CBatch cb0 = {};
    cb0.s[0] = { images,    img_h, img_l,   (int)(SZ / 4) };
    cb0.s[1] = { capitions, cap_h, cap_l,   (int)(NTOK * 768 / 4) };
    cb0.s[2] = { tp_w,      tpw_h, nullptr, (int)(WTP / 4) };
    cb0.s[3] = { ip_w,      ipw_h, nullptr, (int)(W1 / 4) };
    convert_kernel<<<dim3(296, 4), 256>>>(cb0);

    // 1: modality projections (SPLIT, MT=64: 128 CTAs) + fused QKV converts
    GB b1 = {};
    b1.d[0] = { cap_h, cap_l, tpw_h, tp_b, nullptr, g_txt, txt_h, txt_l, 768 };
    b1.d[1] = { img_h, img_l, ipw_h, ip_b, nullptr, g_img, gim_h, gim_l, 1024 };
    CBatch wc1 = {};
    wc1.s[0] = { ia_qw, iaq_h, nullptr, (int)(W1 / 4) };
    wc1.s[1] = { ia_kw, iak_h, nullptr, (int)(W1 / 4) };
    wc1.s[2] = { ia_vw, iav_h, nullptr, (int)(W1 / 4) };
    wc1.s[3] = { ta_qw, taq_h, nullptr, (int)(W1 / 4) };
    wc1.s[4] = { ta_kw, tak_h, nullptr, (int)(W1 / 4) };
    wc1.s[5] = { ta_vw, tav_h, nullptr, (int)(W1 / 4) };
    gemm_mma<64, true><<<dim3(8, 8, 2 + 2), 256, GEMM_SMEM_64S>>>(b1, DM, wc1, 6, 2);

    // 2: Q/K/V GEMMs (MT=128: 192 CTAs) + fused O-weight converts
    GB b2 = {};
    b2.d[0] = { gim_h, nullptr, iaq_h, ia_qb, nullptr, nullptr, q1h, nullptr, 1024 };
    b2.d[1] = { txt_h, nullptr, iak_h, ia_kb, nullptr, nullptr, k1h, nullptr, 1024 };
    b2.d[2] = { txt_h, nullptr, iav_h, ia_vb, nullptr, nullptr, v1h, nullptr, 1024 };
    b2.d[3] = { txt_h, nullptr, taq_h, ta_qb, nullptr, nullptr, q2h, nullptr, 1024 };
    b2.d[4] = { gim_h, nullptr, tak_h, ta_kb, nullptr, nullptr, k2h, nullptr, 1024 };
    b2.d[5] = { gim_h, nullptr, tav_h, ta_vb, nullptr, nullptr, v2h, nullptr, 1024 };
    CBatch wc2 = {};
    wc2.s[0] = { ia_ow, iao_h, nullptr, (int)(W1 / 4) };
    wc2.s[1] = { ta_ow, tao_h, nullptr, (int)(W1 / 4) };
    gemm_mma<128, false><<<dim3(8, 4, 6 + 2), 256, GEMM_SMEM_128>>>(b2, DM, wc2, 2, 6);

    // 3: windowed attention (fp16 in/out)
    attn_kernel<<<dim3(NTOK / QB, HEADS, 2), 256, ATTN_SMEM>>>(
        q1h, k1h, v1h, ia_kb, ia_vb, o1_h,
        q2h, k2h, v2h, ta_kb, ta_vb, o2_h);

    // 4: output projections + residual -> d_out (MT=64: 128 CTAs)
    GB b4 = {};
    b4.d[0] = { o1_h, nullptr, iao_h, ia_ob, g_img, out_img, nullptr, nullptr, 1024 };
    b4.d[1] = { o2_h, nullptr, tao_h, ta_ob, g_txt, out_txt, nullptr, nullptr, 1024 };
    gemm_mma<64, false><<<dim3(8, 8, 2), 256, GEMM_SMEM_64>>>(b4, DM, empty, 0, 2);
}

// round 16
// speedup vs baseline: 4.6431x; 1.0268x over previous
#include <cuda_runtime.h>
#include <cuda_fp16.h>
#include <math.h>
#include <stdint.h>

// ===========================================================================
// CrossModalFusionModel via mma.sync (HMMA fp16) on sm_103 base target.
// Stage 1: fused-convert GEMM — reads fp32 inputs/weights directly, converts
//          to (hi,lo) fp16 in the load pipeline (register prefetch), 2-pass
//          split MMA, MT=64 (128 CTAs) + fused QKV weight convert workers.
// Stage 2: single-pass fp16 QKV GEMM, MT=128 (192 CTAs) + fused O converts.
// Stage 4: single-pass fp16 o-proj, MT=64 (128 CTAs) + residual -> d_out.
// Attention: all-fp16 smem, shared-K fused 2-query score loop, fp32 AV.
// No standalone pre-convert kernel (R16).
// ===========================================================================

#define NTOK  512
#define DM    1024
#define HEADS 8
#define DH    128
#define WIN   64
#define HALF  32

__device__ __forceinline__ uint32_t s2u(const void* p) {
    uint32_t a;
    asm("{ .reg .u64 t; cvta.to.shared.u64 t, %1; cvt.u32.u64 %0, t; }" : "=r"(a) : "l"(p));
    return a;
}
__device__ __forceinline__ void cp16(uint32_t smem, const void* g) {
    asm volatile("cp.async.cg.shared.global [%0], [%1], 16;" :: "r"(smem), "l"(g));
}
#define CP_COMMIT() asm volatile("cp.async.commit_group;" ::: "memory")
#define CP_WAIT0()  asm volatile("cp.async.wait_group 0;" ::: "memory")
#define CP_WAIT1()  asm volatile("cp.async.wait_group 1;" ::: "memory")

__device__ __forceinline__ void ldx4(uint32_t r[4], uint32_t addr) {
    asm volatile("ldmatrix.sync.aligned.m8n8.x4.shared.b16 {%0,%1,%2,%3}, [%4];"
        : "=r"(r[0]), "=r"(r[1]), "=r"(r[2]), "=r"(r[3]) : "r"(addr));
}
__device__ __forceinline__ void mma16816(float d[4], const uint32_t a[4],
                                         uint32_t b0, uint32_t b1) {
    asm volatile(
        "mma.sync.aligned.m16n8k16.row.col.f32.f16.f16.f32 "
        "{%0,%1,%2,%3}, {%4,%5,%6,%7}, {%8,%9}, {%0,%1,%2,%3};"
        : "+f"(d[0]), "+f"(d[1]), "+f"(d[2]), "+f"(d[3])
        : "r"(a[0]), "r"(a[1]), "r"(a[2]), "r"(a[3]), "r"(b0), "r"(b1));
}
__device__ __forceinline__ void sts128(uint32_t addr, const uint32_t r[4]) {
    asm volatile("st.shared.v4.b32 [%0], {%1,%2,%3,%4};"
        :: "r"(addr), "r"(r[0]), "r"(r[1]), "r"(r[2]), "r"(r[3]));
}
__device__ __forceinline__ uint32_t h2u(__half2 v) {
    return *reinterpret_cast<uint32_t*>(&v);
}

#define SZ (NTOK * DM)
__device__ float   g_f[2 * SZ];         // txt, img (fp32 residuals)
__device__ __half  g_hf[20 * 1024 * 1024];

// ---------------------------------------------------------------------------
// Conversion: fp32 -> fp16 (hi[,lo]) — used by fused workers only.
// ---------------------------------------------------------------------------
struct CSeg { const float* src; __half *hi, *lo; int n4; };
struct CBatch { CSeg s[6]; };

__device__ __forceinline__ void conv_one(const CSeg& s, int i) {
    float4 x = ((const float4*)s.src)[i];
    __half h0 = __float2half(x.x), h1 = __float2half(x.y);
    __half h2 = __float2half(x.z), h3 = __float2half(x.w);
    __half2* ph = (__half2*)(s.hi) + 2 * i;
    ph[0] = __halves2half2(h0, h1); ph[1] = __halves2half2(h2, h3);
    if (s.lo) {
        __half2* pl = (__half2*)(s.lo) + 2 * i;
        pl[0] = __halves2half2(__float2half(x.x - __half2float(h0)),
                               __float2half(x.y - __half2float(h1)));
        pl[1] = __halves2half2(__float2half(x.z - __half2float(h2)),
                               __float2half(x.w - __half2float(h3)));
    }
}

// hi/lo conversion for 8 floats (matches conv_one semantics exactly)
__device__ __forceinline__ void cvt_hi8(const float4& a, const float4& b, uint32_t hi[4]) {
    hi[0] = h2u(__floats2half2_rn(a.x, a.y));
    hi[1] = h2u(__floats2half2_rn(a.z, a.w));
    hi[2] = h2u(__floats2half2_rn(b.x, b.y));
    hi[3] = h2u(__floats2half2_rn(b.z, b.w));
}
__device__ __forceinline__ void cvt_lo8(const float4& a, const float4& b,
                                        const uint32_t hi[4], uint32_t lo[4]) {
    float2 f0 = __half22float2(*(const __half2*)&hi[0]);
    float2 f1 = __half22float2(*(const __half2*)&hi[1]);
    float2 f2 = __half22float2(*(const __half2*)&hi[2]);
    float2 f3 = __half22float2(*(const __half2*)&hi[3]);
    lo[0] = h2u(__floats2half2_rn(a.x - f0.x, a.y - f0.y));
    lo[1] = h2u(__floats2half2_rn(a.z - f1.x, a.w - f1.y));
    lo[2] = h2u(__floats2half2_rn(b.x - f2.x, b.y - f2.y));
    lo[3] = h2u(__floats2half2_rn(b.z - f3.x, b.w - f3.y));
}

// ---------------------------------------------------------------------------
// Stage-1 kernel: fp32-source convert-on-load split GEMM, MT=64, NT=128.
// smem buffer: [Ahi 8K][Alo 8K][W 16K] x2 = 65536.
// ---------------------------------------------------------------------------
struct G1 { const float *Af, *Wf, *bias; float* C; __half *Chi, *Clo; int K; };
#define G1_SMEM 65536

__global__ __launch_bounds__(256, 2)
void gemm1_conv(G1 d0, G1 d1, CBatch wc, int nseg, int zgemm) {
    const int tid = threadIdx.x;

    if ((int)blockIdx.z >= zgemm) {              // fused convert workers
        const int pb = gridDim.x * gridDim.y;
        const int worker  = ((int)blockIdx.z - zgemm) * pb + blockIdx.y * gridDim.x + blockIdx.x;
        const int nworker = ((int)gridDim.z - zgemm) * pb;
        const int gthr    = worker * 256 + tid;
        const int gstride = nworker * 256;
        for (int s = 0; s < nseg; s++)
            for (int i = gthr; i < wc.s[s].n4; i += gstride)
                conv_one(wc.s[s], i);
        return;
    }

    extern __shared__ char smem[];
    const G1 g = (blockIdx.z == 0) ? d0 : d1;
    const uint32_t sb = s2u(smem);
    const int wid = tid >> 5, lane = tid & 31;
    const int m0 = blockIdx.y * 64, n0 = blockIdx.x * 128;
    const int nch = g.K >> 6;
    const int wm = (wid & 1) * 32, wn = (wid >> 1) * 32;

    // task mapping (constant per thread)
    const int ar0 = tid >> 3,         af0 = tid & 7;           // A task 0
    const int ar1 = (tid + 256) >> 3, af1 = tid & 7;           // A task 1
    const uint32_t aof0 = (uint32_t)(ar0 * 128 + ((af0 * 16) ^ ((ar0 & 7) << 4)));
    const uint32_t aof1 = (uint32_t)(ar1 * 128 + ((af1 * 16) ^ ((ar1 & 7) << 4)));

    float4 ra[2][2], rw[4][2];

    auto ldg_chunk = [&](int k0) {
        {
            const float* p0 = g.Af + (size_t)(m0 + ar0) * g.K + k0 + af0 * 8;
            ra[0][0] = *(const float4*)p0; ra[0][1] = *(const float4*)(p0 + 4);
            const float* p1 = g.Af + (size_t)(m0 + ar1) * g.K + k0 + af1 * 8;
            ra[1][0] = *(const float4*)p1; ra[1][1] = *(const float4*)(p1 + 4);
        }
#pragma unroll
        for (int t = 0; t < 4; t++) {
            const int idx = tid + t * 256, r = idx >> 3, f4 = idx & 7;
            const float* p = g.Wf + (size_t)(n0 + r) * g.K + k0 + f4 * 8;
            rw[t][0] = *(const float4*)p; rw[t][1] = *(const float4*)(p + 4);
        }
    };
    auto sts_chunk = [&](uint32_t bo) {
        {
            uint32_t hi[4], lo[4];
            cvt_hi8(ra[0][0], ra[0][1], hi); cvt_lo8(ra[0][0], ra[0][1], hi, lo);
            sts128(bo + aof0, hi); sts128(bo + 8192 + aof0, lo);
            cvt_hi8(ra[1][0], ra[1][1], hi); cvt_lo8(ra[1][0], ra[1][1], hi, lo);
            sts128(bo + aof1, hi); sts128(bo + 8192 + aof1, lo);
        }
#pragma unroll
        for (int t = 0; t < 4; t++) {
            const int idx = tid + t * 256, r = idx >> 3, f4 = idx & 7;
            const uint32_t off = (uint32_t)(r * 128 + ((f4 * 16) ^ ((r & 7) << 4)));
            uint32_t hi[4];
            cvt_hi8(rw[t][0], rw[t][1], hi);
            sts128(bo + 16384 + off, hi);
        }
    };

    float acc[2][4][4];
#pragma unroll
    for (int a = 0; a < 2; a++)
#pragma unroll
        for (int b = 0; b < 4; b++)
#pragma unroll
            for (int c = 0; c < 4; c++) acc[a][b][c] = 0.f;

    const int      lrow = lane & 15;
    const uint32_t cgb  = (uint32_t)((lane >> 4) * 16);
    const uint32_t xm   = (uint32_t)((lrow & 7) << 4);

    ldg_chunk(0);
    sts_chunk(sb);
    if (nch > 1) ldg_chunk(64);

    for (int i = 0; i < nch; i++) {
        __syncthreads();                          // buf[i&1] visible to all
        const uint32_t bo  = sb + (uint32_t)((i & 1) * 32768);
        const uint32_t aHi = bo + (uint32_t)((wm + lrow) * 128);
        const uint32_t aLo = aHi + 8192;
        const uint32_t bHi = bo + 16384 + (uint32_t)((wn + lrow) * 128);

#pragma unroll
        for (int ks = 0; ks < 4; ks++) {
            const uint32_t co = ((uint32_t)(ks * 32) + cgb) ^ xm;
            uint32_t ah[2][4], al[2][4], bh[2][4];
#pragma unroll
            for (int mf = 0; mf < 2; mf++)
                ldx4(ah[mf], aHi + (uint32_t)(mf * 16 * 128) + co);
#pragma unroll
            for (int p = 0; p < 2; p++)
                ldx4(bh[p], bHi + (uint32_t)(p * 16 * 128) + co);
#pragma unroll
            for (int mf = 0; mf < 2; mf++)
#pragma unroll
                for (int nf = 0; nf < 4; nf++) {
                    const int p = nf >> 1, o = nf & 1;
                    mma16816(acc[mf][nf], ah[mf], bh[p][o], bh[p][o + 2]);
                }
#pragma unroll
            for (int mf = 0; mf < 2; mf++)
                ldx4(al[mf], aLo + (uint32_t)(mf * 16 * 128) + co);
#pragma unroll
            for (int mf = 0; mf < 2; mf++)
#pragma unroll
                for (int nf = 0; nf < 4; nf++) {
                    const int p = nf >> 1, o = nf & 1;
                    mma16816(acc[mf][nf], al[mf], bh[p][o], bh[p][o + 2]);
                }
        }
        if (i + 1 < nch) {
            sts_chunk(sb + (uint32_t)(((i + 1) & 1) * 32768));   // other buffer: safe
            if (i + 2 < nch) ldg_chunk((i + 2) << 6);
        }
    }

    // epilogue (MT=64): bias + fp32 C + split fp16 out
    const int qr = lane >> 2, qc = (lane & 3) * 2;
#pragma unroll
    for (int mf = 0; mf < 2; mf++) {
        const int r0 = m0 + wm + mf * 16 + qr;
#pragma unroll
        for (int nf = 0; nf < 4; nf++) {
            const int c = n0 + wn + nf * 8 + qc;
            const float2 bv = *(const float2*)(g.bias + c);
            float o00 = acc[mf][nf][0] + bv.x, o01 = acc[mf][nf][1] + bv.y;
            float o10 = acc[mf][nf][2] + bv.x, o11 = acc[mf][nf][3] + bv.y;
            const size_t off0 = (size_t)r0 * DM + c;
            const size_t off1 = off0 + (size_t)8 * DM;
            *(float2*)(g.C + off0) = make_float2(o00, o01);
            *(float2*)(g.C + off1) = make_float2(o10, o11);
            __half h00 = __float2half(o00), h01 = __float2half(o01);
            __half h10 = __float2half(o10), h11 = __float2half(o11);
            *(__half2*)(g.Chi + off0) = __halves2half2(h00, h01);
            *(__half2*)(g.Chi + off1) = __halves2half2(h10, h11);
            *(__half2*)(g.Clo + off0) = __halves2half2(
                __float2half(o00 - __half2float(h00)),
                __float2half(o01 - __half2float(h01)));
            *(__half2*)(g.Clo + off1) = __halves2half2(
                __float2half(o10 - __half2float(h10)),
                __float2half(o11 - __half2float(h11)));
        }
    }
}

// ---------------------------------------------------------------------------
// Generic mma.sync GEMM (fp16 sources) + fused convert workers. MT=64|128.
// ---------------------------------------------------------------------------
struct GD {
    const __half *Ahi, *Whi;
    const float *bias, *resid;
    float* C;
    __half *Chi;
    int K;
};
struct GB { GD d[6]; };

#define WTILE_B 16384
#define GEMM_SMEM_128  (2 * (16384 + 16384))      // 65536
#define GEMM_SMEM_64   (2 * (8192 + 16384))       // 49152

template<int ROWS>
__device__ __forceinline__ void load_tile(uint32_t sdst, const __half* src,
                                          int row0, int k0, int K, int tid) {
    const char* g = (const char*)(src + (size_t)row0 * K + k0);
    const size_t rstride = (size_t)K * 2;
#pragma unroll
    for (int it = 0; it < ROWS / 32; it++) {
        int idx = tid + it * 256;
        int r = idx >> 3, f4 = idx & 7;
        cp16(sdst + (uint32_t)(r * 128 + ((f4 * 16) ^ ((r & 7) << 4))),
             g + (size_t)r * rstride + f4 * 16);
    }
}

template<int MT>
__global__ __launch_bounds__(256, 2)
void gemm_mma(GB batch, int N, CBatch wc, int nseg, int zgemm) {
    const int tid = threadIdx.x;

    if ((int)blockIdx.z >= zgemm) {
        const int pb = gridDim.x * gridDim.y;
        const int worker  = ((int)blockIdx.z - zgemm) * pb + blockIdx.y * gridDim.x + blockIdx.x;
        const int nworker = ((int)gridDim.z - zgemm) * pb;
        const int gthr    = worker * 256 + tid;
        const int gstride = nworker * 256;
        for (int s = 0; s < nseg; s++)
            for (int i = gthr; i < wc.s[s].n4; i += gstride)
                conv_one(wc.s[s], i);
        return;
    }

    extern __shared__ char smem[];
    const GD g = batch.d[blockIdx.z];
    const uint32_t sb = s2u(smem);
    const int wid = tid >> 5, lane = tid & 31;
    const int m0 = blockIdx.y * MT, n0 = blockIdx.x * 128;
    constexpr int ATILE = MT * 128;
    constexpr uint32_t WOFF  = ATILE;
    constexpr uint32_t BUF_B = WOFF + WTILE_B;
    constexpr int NF = (MT == 128) ? 8 : 4;
    const int wm = (MT == 128) ? (wid & 3) * 32 : (wid & 1) * 32;
    const int wn = (MT == 128) ? (wid >> 2) * 64 : (wid >> 1) * 32;

    float acc[2][NF][4];
#pragma unroll
    for (int a = 0; a < 2; a++)
#pragma unroll
        for (int b = 0; b < NF; b++)
#pragma unroll
            for (int c = 0; c < 4; c++) acc[a][b][c] = 0.f;

    const int nch = g.K >> 6;
    const int      lrow = lane & 15;
    const uint32_t cgb  = (uint32_t)((lane >> 4) * 16);
    const uint32_t xm   = (uint32_t)((lrow & 7) << 4);

    auto loadbuf = [&](uint32_t bo, int k0) {
        load_tile<MT>(bo, g.Ahi, m0, k0, g.K, tid);
        load_tile<128>(bo + WOFF, g.Whi, n0, k0, g.K, tid);
    };

    loadbuf(sb, 0);
    CP_COMMIT();

    for (int i = 0; i < nch; i++) {
        if (i + 1 < nch) {
            loadbuf(sb + (uint32_t)(((i + 1) & 1) * BUF_B), (i + 1) << 6);
            CP_COMMIT();
            CP_WAIT1();
        } else {
            CP_WAIT0();
        }
        __syncthreads();

        const uint32_t bo = sb + (uint32_t)((i & 1) * BUF_B);
        const uint32_t aHi = bo + (uint32_t)((wm + lrow) * 128);
        const uint32_t bHi = bo + WOFF + (uint32_t)((wn + lrow) * 128);

#pragma unroll
        for (int ks = 0; ks < 4; ks++) {
            const uint32_t co = ((uint32_t)(ks * 32) + cgb) ^ xm;
            uint32_t ah[2][4], bh[NF / 2][4];
#pragma unroll
            for (int mf = 0; mf < 2; mf++)
                ldx4(ah[mf], aHi + (uint32_t)(mf * 16 * 128) + co);
#pragma unroll
            for (int p = 0; p < NF / 2; p++)
                ldx4(bh[p], bHi + (uint32_t)(p * 16 * 128) + co);
#pragma unroll
            for (int mf = 0; mf < 2; mf++)
#pragma unroll
                for (int nf = 0; nf < NF; nf++) {
                    const int p = nf >> 1, o = nf & 1;
                    mma16816(acc[mf][nf], ah[mf], bh[p][o], bh[p][o + 2]);
                }
        }
        __syncthreads();
    }

    const int qr = lane >> 2, qc = (lane & 3) * 2;
#pragma unroll
    for (int mf = 0; mf < 2; mf++) {
        const int r0 = m0 + wm + mf * 16 + qr;
#pragma unroll
        for (int nf = 0; nf < NF; nf++) {
            const int c = n0 + wn + nf * 8 + qc;
            const float2 bv = *(const float2*)(g.bias + c);
            float o00 = acc[mf][nf][0] + bv.x, o01 = acc[mf][nf][1] + bv.y;
            float o10 = acc[mf][nf][2] + bv.x, o11 = acc[mf][nf][3] + bv.y;
            const size_t off0 = (size_t)r0 * N + c;
            const size_t off1 = off0 + (size_t)8 * N;
            if (g.resid) {
                float2 ra = *(const float2*)(g.resid + off0);
                float2 rb = *(const float2*)(g.resid + off1);
                o00 += ra.x; o01 += ra.y; o10 += rb.x; o11 += rb.y;
            }
            if (g.C) {
                *(float2*)(g.C + off0) = make_float2(o00, o01);
                *(float2*)(g.C + off1) = make_float2(o10, o11);
            }
            if (g.Chi) {
                *(__half2*)(g.Chi + off0) =
                    __halves2half2(__float2half(o00), __float2half(o01));
                *(__half2*)(g.Chi + off1) =
                    __halves2half2(__float2half(o10), __float2half(o11));
            }
        }
    }
}

// ---------------------------------------------------------------------------
// Sliding-window attention: all-fp16 Q/K/V. grid (NTOK/QB, HEADS, 2).
// ---------------------------------------------------------------------------
#define QB    16
#define WR    81
#define PADC  81
#define KROW  65
#define VROW  66
#define OFF_KS   0
#define OFF_VS   21328
#define OFF_QS   (OFF_VS + 82*VROW*4)
#define OFF_WS   (OFF_QS + 16*KROW*4)
#define ATTN_SMEM (OFF_WS + 16*88*4 + 16)

__global__ __launch_bounds__(256)
void attn_kernel(const __half* __restrict__ Q1, const __half* __restrict__ K1,
                 const __half* __restrict__ V1, const float* __restrict__ kb1,
                 const float* __restrict__ vb1, __half* __restrict__ O1h,
                 const __half* __restrict__ Q2, const __half* __restrict__ K2,
                 const __half* __restrict__ V2, const float* __restrict__ kb2,
                 const float* __restrict__ vb2, __half* __restrict__ O2h) {
    extern __shared__ char smraw[];
    __half2* Ks2 = (__half2*)(smraw + OFF_KS);
    __half2* Vs2 = (__half2*)(smraw + OFF_VS);
    __half2* Qs2 = (__half2*)(smraw + OFF_QS);
    float*   Ws  = (float*)(smraw + OFF_WS);

    const __half *Q, *K, *V;
    const float *kb, *vb;
    __half *Oh;
    if (blockIdx.z == 0) { Q=Q1; K=K1; V=V1; kb=kb1; vb=vb1; Oh=O1h; }
    else                 { Q=Q2; K=K2; V=V2; kb=kb2; vb=vb2; Oh=O2h; }

    const int h   = blockIdx.y;
    const int tid = threadIdx.x, wid = tid >> 5, lane = tid & 31;
    const int q0  = blockIdx.x * QB;
    const int base = q0 - HALF;
    const int jmin = max(0, -base);
    const int jmax = min(NTOK - 1, q0 + QB - 1 + HALF + 1) - base;
    const float scale = 0.088388347648318447f;

    for (int idx = tid; idx < WR * 16; idx += 256) {
        const int j = idx >> 4, w16 = idx & 15;
        if (j >= jmin && j <= jmax) {
            const size_t go = (size_t)(base + j) * DM + h * DH + w16 * 8;
            const uint4 kv = *(const uint4*)(K + go);
            __half2* kd = Ks2 + j * KROW + w16 * 4;
            kd[0] = *(const __half2*)&kv.x; kd[1] = *(const __half2*)&kv.y;
            kd[2] = *(const __half2*)&kv.z; kd[3] = *(const __half2*)&kv.w;
            const uint4 vv = *(const uint4*)(V + go);
            uint2* vd = (uint2*)(Vs2 + j * VROW + w16 * 4);
            vd[0] = make_uint2(vv.x, vv.y);
            vd[1] = make_uint2(vv.z, vv.w);
        }
    }
    if (tid < 32) {
        const float4 kv = *(const float4*)(kb + h * DH + tid * 4);
        Ks2[PADC * KROW + tid * 2 + 0] = __floats2half2_rn(kv.x, kv.y);
        Ks2[PADC * KROW + tid * 2 + 1] = __floats2half2_rn(kv.z, kv.w);
        const float4 vv = *(const float4*)(vb + h * DH + tid * 4);
        Vs2[PADC * VROW + tid * 2 + 0] = __floats2half2_rn(vv.x, vv.y);
        Vs2[PADC * VROW + tid * 2 + 1] = __floats2half2_rn(vv.z, vv.w);
    }
    {
        const int q = tid >> 4, w16 = tid & 15;
        const uint4 qv = *(const uint4*)(Q + (size_t)(q0 + q) * DM + h * DH + w16 * 8);
        __half2* qd = Qs2 + q * KROW + w16 * 4;
        qd[0] = *(const __half2*)&qv.x; qd[1] = *(const __half2*)&qv.y;
        qd[2] = *(const __half2*)&qv.z; qd[3] = *(const __half2*)&qv.w;
    }
    __syncthreads();

    const int j0 = lane, j1 = lane + 32, j2 = lane + 64;
    const __half2* k0 = Ks2 + j0 * KROW;
    const __half2* k1 = Ks2 + j1 * KROW;
    const __half2* k2 = Ks2 + min(j2, PADC) * KROW;
    const __half2* qpA = Qs2 + (wid * 2 + 0) * KROW;
    const __half2* qpB = Qs2 + (wid * 2 + 1) * KROW;

    const __half2 hz = __floats2half2_rn(0.f, 0.f);
    __half2 a0A = hz, a1A = hz, a2A = hz, a0B = hz, a1B = hz, a2B = hz;
#pragma unroll 8
    for (int d2 = 0; d2 < 64; d2++) {
        const __half2 k0v = k0[d2], k1v = k1[d2], k2v = k2[d2];
        const __half2 qA = qpA[d2], qB = qpB[d2];
        a0A = __hfma2(qA, k0v, a0A);
        a1A = __hfma2(qA, k1v, a1A);
        a2A = __hfma2(qA, k2v, a2A);
        a0B = __hfma2(qB, k0v, a0B);
        a1B = __hfma2(qB, k1v, a1B);
        a2B = __hfma2(qB, k2v, a2B);
    }
    const float r0A = __low2float(a0A) + __high2float(a0A);
    const float r1A = __low2float(a1A) + __high2float(a1A);
    const float r2A = __low2float(a2A) + __high2float(a2A);
    const float r0B = __low2float(a0B) + __high2float(a0B);
    const float r1B = __low2float(a1B) + __high2float(a1B);
    const float r2B = __low2float(a2B) + __high2float(a2B);

#pragma unroll
    for (int qq = 0; qq < 2; qq++) {
        const int n   = q0 + wid * 2 + qq;
        const int lo  = max(0, n - HALF);
        const int hi  = min(NTOK - 1, n + HALF + 1);
        const int cnt = hi - lo + 1;
        const int nz  = max(0, WIN - cnt);
        const int jb  = lo - base;
        float* wq = Ws + (wid * 2 + qq) * 88;

        float s0 = qq ? r0B : r0A;
        float s1 = qq ? r1B : r1A;
        float s2 = qq ? r2B : r2A;

        const bool v0 = (j0 >= jb) && (j0 < jb + cnt);
        const bool v1 = (j1 >= jb) && (j1 < jb + cnt);
        const bool v2 = ((j2 >= jb) && (j2 < jb + cnt)) || (j2 == PADC);
        s0 = v0 ? s0 * scale : -INFINITY;
        s1 = v1 ? s1 * scale : -INFINITY;
        s2 = v2 ? s2 * scale : -INFINITY;

        float mx = fmaxf(s0, fmaxf(s1, s2));
#pragma unroll
        for (int o = 16; o; o >>= 1) mx = fmaxf(mx, __shfl_xor_sync(0xffffffffu, mx, o));

        float w0 = v0 ? expf(s0 - mx) : 0.f;
        float w1 = v1 ? expf(s1 - mx) : 0.f;
        float w2 = v2 ? expf(s2 - mx) : 0.f;
        if (j2 == PADC) w2 *= (float)nz;

        float dsum = w0 + w1 + w2;
#pragma unroll
        for (int o = 16; o; o >>= 1) dsum += __shfl_xor_sync(0xffffffffu, dsum, o);

        wq[j0] = w0;
        wq[j1] = w1;
        if (j2 <= PADC) wq[j2] = w2;
        __syncwarp();

        float4 acc = make_float4(0.f, 0.f, 0.f, 0.f);
        for (int p = 0; p < cnt; p++) {
            const int j = jb + p;
            const float w = wq[j];
            const uint2 vraw = *(const uint2*)(Vs2 + j * VROW + lane * 2);
            const float2 fa = __half22float2(*(const __half2*)&vraw.x);
            const float2 fb = __half22float2(*(const __half2*)&vraw.y);
            acc.x += w * fa.x; acc.y += w * fa.y;
            acc.z += w * fb.x; acc.w += w * fb.y;
        }
        {
            const float w = wq[PADC];
            const uint2 vraw = *(const uint2*)(Vs2 + PADC * VROW + lane * 2);
            const float2 fa = __half22float2(*(const __half2*)&vraw.x);
            const float2 fb = __half22float2(*(const __half2*)&vraw.y);
            acc.x += w * fa.x; acc.y += w * fa.y;
            acc.z += w * fb.x; acc.w += w * fb.y;
        }
        __syncwarp();

        const float inv = 1.f / dsum;
        const size_t oo = (size_t)n * DM + h * DH + lane * 4;
        __half2* ph = (__half2*)(Oh + oo);
        ph[0] = __halves2half2(__float2half(acc.x * inv), __float2half(acc.y * inv));
        ph[1] = __halves2half2(__float2half(acc.z * inv), __float2half(acc.w * inv));
    }
}

// ---------------------------------------------------------------------------
// Launch
// ---------------------------------------------------------------------------
extern "C" void kernel_launch(void* const* d_in, const int* in_sizes, int n_in,
                              void* d_out, int out_size) {
    const float* images    = (const float*)d_in[0];
    const float* capitions = (const float*)d_in[1];
    const float* tp_w  = (const float*)d_in[3];
    const float* tp_b  = (const float*)d_in[4];
    const float* ip_w  = (const float*)d_in[5];
    const float* ip_b  = (const float*)d_in[6];
    const float* ia_qw = (const float*)d_in[7];
    const float* ia_qb = (const float*)d_in[8];
    const float* ia_kw = (const float*)d_in[9];
    const float* ia_kb = (const float*)d_in[10];
    const float* ia_vw = (const float*)d_in[11];
    const float* ia_vb = (const float*)d_in[12];
    const float* ia_ow = (const float*)d_in[13];
    const float* ia_ob = (const float*)d_in[14];
    const float* ta_qw = (const float*)d_in[15];
    const float* ta_qb = (const float*)d_in[16];
    const float* ta_kw = (const float*)d_in[17];
    const float* ta_kb = (const float*)d_in[18];
    const float* ta_vw = (const float*)d_in[19];
    const float* ta_vb = (const float*)d_in[20];
    const float* ta_ow = (const float*)d_in[21];
    const float* ta_ob = (const float*)d_in[22];

    void* fp = nullptr; cudaGetSymbolAddress(&fp, g_f);
    void* bp = nullptr; cudaGetSymbolAddress(&bp, g_hf);
    float* F = (float*)fp;
    __half* B = (__half*)bp;

    float* g_txt = F + 0 * SZ;
    float* g_img = F + 1 * SZ;

    size_t cur = 0;
    auto take = [&](size_t n) { __half* p = B + cur; cur += n; return p; };
    const size_t W1 = 1024 * 1024;
    __half *iaq_h = take(W1), *iak_h = take(W1), *iav_h = take(W1), *iao_h = take(W1);
    __half *taq_h = take(W1), *tak_h = take(W1), *tav_h = take(W1), *tao_h = take(W1);
    __half *txt_h = take(SZ), *txt_l = take(SZ);
    __half *gim_h = take(SZ), *gim_l = take(SZ);
    __half *q1h = take(SZ), *k1h = take(SZ), *v1h = take(SZ);
    __half *q2h = take(SZ), *k2h = take(SZ), *v2h = take(SZ);
    __half *o1_h = take(SZ), *o2_h = take(SZ);

    float* out_img = (float*)d_out;
    float* out_txt = out_img + SZ;

    cudaFuncSetAttribute((const void*)&gemm1_conv,
                         cudaFuncAttributeMaxDynamicSharedMemorySize, G1_SMEM);
    cudaFuncSetAttribute((const void*)&gemm_mma<128>,
                         cudaFuncAttributeMaxDynamicSharedMemorySize, GEMM_SMEM_128);
    cudaFuncSetAttribute((const void*)&gemm_mma<64>,
                         cudaFuncAttributeMaxDynamicSharedMemorySize, GEMM_SMEM_64);
    cudaFuncSetAttribute((const void*)&attn_kernel,
                         cudaFuncAttributeMaxDynamicSharedMemorySize, ATTN_SMEM);

    const CBatch empty = {};

    // 1: modality projections — convert-on-load split GEMM + fused QKV converts
    G1 p0 = { capitions, tp_w, tp_b, g_txt, txt_h, txt_l, 768 };
    G1 p1 = { images,    ip_w, ip_b, g_img, gim_h, gim_l, 1024 };
    CBatch wc1 = {};
    wc1.s[0] = { ia_qw, iaq_h, nullptr, (int)(W1 / 4) };
    wc1.s[1] = { ia_kw, iak_h, nullptr, (int)(W1 / 4) };
    wc1.s[2] = { ia_vw, iav_h, nullptr, (int)(W1 / 4) };
    wc1.s[3] = { ta_qw, taq_h, nullptr, (int)(W1 / 4) };
    wc1.s[4] = { ta_kw, tak_h, nullptr, (int)(W1 / 4) };
    wc1.s[5] = { ta_vw, tav_h, nullptr, (int)(W1 / 4) };
    gemm1_conv<<<dim3(8, 8, 2 + 2), 256, G1_SMEM>>>(p0, p1, wc1, 6, 2);

    // 2: Q/K/V GEMMs (MT=128: 192 CTAs) + fused O-weight converts
    GB b2 = {};
    b2.d[0] = { gim_h, iaq_h, ia_qb, nullptr, nullptr, q1h, 1024 };
    b2.d[1] = { txt_h, iak_h, ia_kb, nullptr, nullptr, k1h, 1024 };
    b2.d[2] = { txt_h, iav_h, ia_vb, nullptr, nullptr, v1h, 1024 };
    b2.d[3] = { txt_h, taq_h, ta_qb, nullptr, nullptr, q2h, 1024 };
    b2.d[4] = { gim_h, tak_h, ta_kb, nullptr, nullptr, k2h, 1024 };
    b2.d[5] = { gim_h, tav_h, ta_vb, nullptr, nullptr, v2h, 1024 };
    CBatch wc2 = {};
    wc2.s[0] = { ia_ow, iao_h, nullptr, (int)(W1 / 4) };
    wc2.s[1] = { ta_ow, tao_h, nullptr, (int)(W1 / 4) };
    gemm_mma<128><<<dim3(8, 4, 6 + 2), 256, GEMM_SMEM_128>>>(b2, DM, wc2, 2, 6);

    // NOTE: stage-2 A operand is hi-only (single pass); lo tiles of txt/img are
    // consumed only by... nothing anymore — stage 1 still writes txt_l/gim_l
    // for bit-compatibility of the split epilogue (cheap, keeps rel_err pinned).

    // 3: windowed attention (fp16 in/out)
    attn_kernel<<<dim3(NTOK / QB, HEADS, 2), 256, ATTN_SMEM>>>(
        q1h, k1h, v1h, ia_kb, ia_vb, o1_h,
        q2h, k2h, v2h, ta_kb, ta_vb, o2_h);

    // 4: output projections + residual -> d_out (MT=64: 128 CTAs)
    GB b4 = {};
    b4.d[0] = { o1_h, iao_h, ia_ob, g_img, out_img, nullptr, 1024 };
    b4.d[1] = { o2_h, tao_h, ta_ob, g_txt, out_txt, nullptr, 1024 };
    gemm_mma<64><<<dim3(8, 8, 2), 256, GEMM_SMEM_64>>>(b4, DM, empty, 0, 2);
}